// round 1
// baseline (speedup 1.0000x reference)
#include <cuda_runtime.h>
#include <math.h>

// Problem constants
#define B_ 4
#define T_ 2048
#define C_ 2048
#define NH_ 2048   // N*H
#define KH_ 512    // K*H
#define NHEADS 16
#define G_ 4
#define H_ 128
#define M_ (B_*T_)   // 8192

// Scratch (device globals — no allocation allowed)
__device__ float g_q[(size_t)M_ * NH_];
__device__ float g_k[(size_t)M_ * KH_];
__device__ float g_v[(size_t)M_ * KH_];
__device__ float g_enc[(size_t)M_ * NH_];

// ---------------------------------------------------------------------------
// Classic 128x128x16 register-tiled SGEMM: C[M,Nc] = A[M,Kc] * B[Kc,Nc]
// A, B, C row-major. M % 128 == 0, Nc % 128 == 0, Kc % 16 == 0 (all true here).
// 256 threads, 8x8 per-thread tile.
// ---------------------------------------------------------------------------
__global__ __launch_bounds__(256) void sgemm128(
    const float* __restrict__ A, const float* __restrict__ B,
    float* __restrict__ C, int M, int Nc, int Kc)
{
    const int BK = 16;
    __shared__ float As[BK][128];
    __shared__ float Bs[BK][128];

    int bx = blockIdx.x;            // N tile
    int by = blockIdx.y;            // M tile
    int tid = threadIdx.x;
    int tx = tid & 15;              // N dir (x8)
    int ty = tid >> 4;              // M dir (x8)

    float acc[8][8];
    #pragma unroll
    for (int i = 0; i < 8; i++)
        #pragma unroll
        for (int j = 0; j < 8; j++) acc[i][j] = 0.f;

    int arow  = tid >> 2;           // 0..63 (two rows: +0, +64)
    int acol4 = tid & 3;            // float4 index within 16-wide k
    int brow  = tid >> 5;           // 0..7 (two rows: +0, +8)
    int bcol4 = tid & 31;           // float4 index within 128-wide n

    const float* Aptr = A + (size_t)(by * 128) * Kc;
    const float* Bptr = B + bx * 128;

    for (int k0 = 0; k0 < Kc; k0 += BK) {
        #pragma unroll
        for (int r = 0; r < 2; ++r) {
            int row = arow + r * 64;
            float4 v = *(const float4*)(Aptr + (size_t)row * Kc + k0 + acol4 * 4);
            As[acol4 * 4 + 0][row] = v.x;
            As[acol4 * 4 + 1][row] = v.y;
            As[acol4 * 4 + 2][row] = v.z;
            As[acol4 * 4 + 3][row] = v.w;
        }
        #pragma unroll
        for (int r = 0; r < 2; ++r) {
            int row = brow + r * 8;
            float4 v = *(const float4*)(Bptr + (size_t)(k0 + row) * Nc + bcol4 * 4);
            *(float4*)&Bs[row][bcol4 * 4] = v;
        }
        __syncthreads();

        #pragma unroll
        for (int k = 0; k < BK; ++k) {
            float a[8], b[8];
            float4 a0 = *(const float4*)&As[k][ty * 8];
            float4 a1 = *(const float4*)&As[k][ty * 8 + 4];
            float4 b0 = *(const float4*)&Bs[k][tx * 8];
            float4 b1 = *(const float4*)&Bs[k][tx * 8 + 4];
            a[0]=a0.x; a[1]=a0.y; a[2]=a0.z; a[3]=a0.w;
            a[4]=a1.x; a[5]=a1.y; a[6]=a1.z; a[7]=a1.w;
            b[0]=b0.x; b[1]=b0.y; b[2]=b0.z; b[3]=b0.w;
            b[4]=b1.x; b[5]=b1.y; b[6]=b1.z; b[7]=b1.w;
            #pragma unroll
            for (int i = 0; i < 8; i++)
                #pragma unroll
                for (int j = 0; j < 8; j++)
                    acc[i][j] = fmaf(a[i], b[j], acc[i][j]);
        }
        __syncthreads();
    }

    float* Cptr = C + (size_t)(by * 128 + ty * 8) * Nc + bx * 128 + tx * 8;
    #pragma unroll
    for (int i = 0; i < 8; i++) {
        *(float4*)(Cptr + (size_t)i * Nc)     = make_float4(acc[i][0], acc[i][1], acc[i][2], acc[i][3]);
        *(float4*)(Cptr + (size_t)i * Nc + 4) = make_float4(acc[i][4], acc[i][5], acc[i][6], acc[i][7]);
    }
}

// ---------------------------------------------------------------------------
// Fused RMSNorm (over full row of `width`) + RoPE (per head of H_=128) + scale.
// One block (256 threads) per row (b*T + t). In-place.
// ---------------------------------------------------------------------------
__global__ __launch_bounds__(256) void rms_rope(float* __restrict__ buf,
                                                int width, int nheads,
                                                float outscale)
{
    int row = blockIdx.x;
    int t = row % T_;
    float* ptr = buf + (size_t)row * width;

    float ss = 0.f;
    for (int i = threadIdx.x; i < width; i += 256) {
        float v = ptr[i];
        ss += v * v;
    }
    #pragma unroll
    for (int o = 16; o; o >>= 1) ss += __shfl_xor_sync(0xffffffffu, ss, o);
    __shared__ float red[8];
    if ((threadIdx.x & 31) == 0) red[threadIdx.x >> 5] = ss;
    __syncthreads();
    float tot = red[0] + red[1] + red[2] + red[3] + red[4] + red[5] + red[6] + red[7];
    float rs = rsqrtf(tot / (float)width + 1e-6f) * outscale;

    // RoPE: pairs (h', h'+64) within each 128-wide head
    int npairs = nheads * 64;
    const double TWO_PI = 6.283185307179586476925286766559;
    for (int p = threadIdx.x; p < npairs; p += 256) {
        int head = p >> 6;
        int hp = p & 63;
        // inv timescale = 10000^(-hp/64), computed in f32 like the reference
        float inv = __expf(-(float)hp * (9.210340371976184f / 64.f));
        float theta = (float)t * inv;
        // accurate range reduction in double (cheap; immune to fast-math sin)
        double td = (double)theta * (1.0 / TWO_PI);
        double frac = td - floor(td);
        if (frac > 0.5) frac -= 1.0;
        float redang = (float)(frac * TWO_PI);
        float s, c;
        sincosf(redang, &s, &c);

        int base = head * H_;
        float x1 = ptr[base + hp] * rs;
        float x2 = ptr[base + hp + 64] * rs;
        ptr[base + hp]      = x1 * c - x2 * s;
        ptr[base + hp + 64] = x2 * c + x1 * s;
    }
}

// ---------------------------------------------------------------------------
// Flash-attention style kernel, fp32. 64 queries x 64 keys per tile, H=128.
// grid = (T/64, NHEADS, B). 256 threads.
//   S compute: 16x16 thread grid, 4x4 per thread, h as k-dim (Q,K transposed in smem).
//   Online softmax: 4 threads per query row.
//   PV: thread (row, c) owns h = c*4 + 16*i + j (conflict-free float4 V reads).
// ---------------------------------------------------------------------------
struct __align__(16) AttnSmem {
    float Qs[H_][64];     // [h][q]
    float Ks[H_][64];     // [h][s]
    float Vs[64][H_];     // [s][h]
    float Ss[64][65];     // padded scores / probs
};

__global__ __launch_bounds__(256) void attn_kernel(
    const float* __restrict__ q, const float* __restrict__ k,
    const float* __restrict__ v, float* __restrict__ enc)
{
    extern __shared__ char smem_raw[];
    AttnSmem& sm = *reinterpret_cast<AttnSmem*>(smem_raw);
    const int QT = 64, ST = 64;

    int b = blockIdx.z;
    int n = blockIdx.y;          // head index = kh*G + g
    int kh = n >> 2;             // G_ = 4
    int q0 = blockIdx.x * QT;
    int tid = threadIdx.x;

    const float* qbase = q + ((size_t)(b * T_ + q0)) * NH_ + n * H_;

    // Load Q tile transposed: Qs[h][q]
    for (int idx = tid; idx < QT * 32; idx += 256) {
        int r = idx >> 5;          // q row within tile
        int c4 = idx & 31;         // float4 index along h
        float4 val = *(const float4*)(qbase + (size_t)r * NH_ + c4 * 4);
        sm.Qs[c4 * 4 + 0][r] = val.x;
        sm.Qs[c4 * 4 + 1][r] = val.y;
        sm.Qs[c4 * 4 + 2][r] = val.z;
        sm.Qs[c4 * 4 + 3][r] = val.w;
    }

    float4 o4[8];
    #pragma unroll
    for (int i = 0; i < 8; i++) o4[i] = make_float4(0.f, 0.f, 0.f, 0.f);
    int orow = tid >> 2, oc = tid & 3;
    int ty = tid >> 4, tx = tid & 15;
    float mi = -1e30f, li = 0.f;
    __syncthreads();

    for (int s0 = 0; s0 < T_; s0 += ST) {
        const float* kbase = k + ((size_t)(b * T_ + s0)) * KH_ + kh * H_;
        const float* vbase = v + ((size_t)(b * T_ + s0)) * KH_ + kh * H_;
        for (int idx = tid; idx < ST * 32; idx += 256) {
            int r = idx >> 5;
            int c4 = idx & 31;
            float4 val = *(const float4*)(kbase + (size_t)r * KH_ + c4 * 4);
            sm.Ks[c4 * 4 + 0][r] = val.x;
            sm.Ks[c4 * 4 + 1][r] = val.y;
            sm.Ks[c4 * 4 + 2][r] = val.z;
            sm.Ks[c4 * 4 + 3][r] = val.w;
            float4 vv = *(const float4*)(vbase + (size_t)r * KH_ + c4 * 4);
            *(float4*)&sm.Vs[r][c4 * 4] = vv;
        }
        __syncthreads();

        // S = Q K^T for this tile
        {
            float acc[4][4];
            #pragma unroll
            for (int i = 0; i < 4; i++)
                #pragma unroll
                for (int j = 0; j < 4; j++) acc[i][j] = 0.f;

            #pragma unroll 4
            for (int h = 0; h < H_; ++h) {
                float4 a = *(const float4*)&sm.Qs[h][ty * 4];
                float4 bb = *(const float4*)&sm.Ks[h][tx * 4];
                float av[4] = {a.x, a.y, a.z, a.w};
                float bv[4] = {bb.x, bb.y, bb.z, bb.w};
                #pragma unroll
                for (int i = 0; i < 4; i++)
                    #pragma unroll
                    for (int j = 0; j < 4; j++)
                        acc[i][j] = fmaf(av[i], bv[j], acc[i][j]);
            }
            #pragma unroll
            for (int i = 0; i < 4; i++)
                #pragma unroll
                for (int j = 0; j < 4; j++)
                    sm.Ss[ty * 4 + i][tx * 4 + j] = acc[i][j];
        }
        __syncthreads();

        // Online softmax update (4 threads per row; they share a warp quad)
        float tmax = -1e30f;
        #pragma unroll
        for (int j = 0; j < 16; j++) tmax = fmaxf(tmax, sm.Ss[orow][oc * 16 + j]);
        tmax = fmaxf(tmax, __shfl_xor_sync(0xffffffffu, tmax, 1));
        tmax = fmaxf(tmax, __shfl_xor_sync(0xffffffffu, tmax, 2));
        float mnew = fmaxf(mi, tmax);
        float alpha = __expf(mi - mnew);
        float ps = 0.f;
        #pragma unroll
        for (int j = 0; j < 16; j++) {
            float pv = __expf(sm.Ss[orow][oc * 16 + j] - mnew);
            sm.Ss[orow][oc * 16 + j] = pv;
            ps += pv;
        }
        ps += __shfl_xor_sync(0xffffffffu, ps, 1);
        ps += __shfl_xor_sync(0xffffffffu, ps, 2);
        li = li * alpha + ps;
        mi = mnew;
        #pragma unroll
        for (int i = 0; i < 8; i++) {
            o4[i].x *= alpha; o4[i].y *= alpha;
            o4[i].z *= alpha; o4[i].w *= alpha;
        }
        __syncwarp();   // make quad's P writes visible before full-row read

        // O += P V : thread owns h = oc*4 + 16*i + {0..3}
        #pragma unroll 1
        for (int s = 0; s < ST; ++s) {
            float p = sm.Ss[orow][s];
            #pragma unroll
            for (int i = 0; i < 8; i++) {
                float4 vv = *(const float4*)&sm.Vs[s][oc * 4 + 16 * i];
                o4[i].x = fmaf(p, vv.x, o4[i].x);
                o4[i].y = fmaf(p, vv.y, o4[i].y);
                o4[i].z = fmaf(p, vv.z, o4[i].z);
                o4[i].w = fmaf(p, vv.w, o4[i].w);
            }
        }
        __syncthreads();
    }

    float invl = 1.f / li;
    float* obase = enc + ((size_t)(b * T_ + q0 + orow)) * NH_ + n * H_;
    #pragma unroll
    for (int i = 0; i < 8; i++) {
        *(float4*)(obase + oc * 4 + 16 * i) =
            make_float4(o4[i].x * invl, o4[i].y * invl, o4[i].z * invl, o4[i].w * invl);
    }
}

// ---------------------------------------------------------------------------
extern "C" void kernel_launch(void* const* d_in, const int* in_sizes, int n_in,
                              void* d_out, int out_size)
{
    const float* x    = (const float*)d_in[0];
    const float* Wq   = (const float*)d_in[1];
    const float* Wk   = (const float*)d_in[2];
    const float* Wv   = (const float*)d_in[3];
    const float* Wout = (const float*)d_in[4];
    float* out = (float*)d_out;

    float *qb, *kb, *vb, *eb;
    cudaGetSymbolAddress((void**)&qb, g_q);
    cudaGetSymbolAddress((void**)&kb, g_k);
    cudaGetSymbolAddress((void**)&vb, g_v);
    cudaGetSymbolAddress((void**)&eb, g_enc);

    // Opt in to >48KB dynamic smem for the attention kernel (idempotent).
    cudaFuncSetAttribute(attn_kernel, cudaFuncAttributeMaxDynamicSharedMemorySize,
                         (int)sizeof(AttnSmem));

    dim3 gBig(NH_ / 128, M_ / 128);   // 16 x 64
    dim3 gSmall(KH_ / 128, M_ / 128); // 4 x 64

    // QKV projections
    sgemm128<<<gBig, 256>>>(x, Wq, qb, M_, NH_, C_);
    sgemm128<<<gSmall, 256>>>(x, Wk, kb, M_, KH_, C_);
    sgemm128<<<gSmall, 256>>>(x, Wv, vb, M_, KH_, C_);

    // RMSNorm + RoPE (+ 1/sqrt(H) folded into q's scale; RoPE is linear)
    rms_rope<<<M_, 256>>>(qb, NH_, NHEADS, 0.08838834764831845f); // rsqrt(128)
    rms_rope<<<M_, 256>>>(kb, KH_, 4, 1.0f);

    // Attention
    dim3 gAttn(T_ / 64, NHEADS, B_);
    attn_kernel<<<gAttn, 256, sizeof(AttnSmem)>>>(qb, kb, vb, eb);

    // Output projection
    sgemm128<<<gBig, 256>>>(eb, Wout, out, M_, NH_, C_);
}

// round 3
// speedup vs baseline: 1.2328x; 1.2328x over previous
#include <cuda_runtime.h>
#include <cuda_bf16.h>
#include <cstdint>
#include <math.h>

// Problem constants
#define B_ 4
#define T_ 2048
#define C_ 2048
#define NH_ 2048   // N*H
#define KH_ 512    // K*H
#define NHEADS 16
#define H_ 128
#define M_ (B_*T_)   // 8192

typedef __nv_bfloat16 bf16;

// ---------------------------------------------------------------------------
// Scratch (device globals — no allocation allowed)
// ---------------------------------------------------------------------------
__device__ float g_q[(size_t)M_ * NH_];
__device__ float g_k[(size_t)M_ * KH_];
__device__ float g_v[(size_t)M_ * KH_];
__device__ float g_enc[(size_t)M_ * NH_];

__device__ bf16 g_x_hi[(size_t)M_ * C_],  g_x_lo[(size_t)M_ * C_];
__device__ bf16 g_e_hi[(size_t)M_ * NH_], g_e_lo[(size_t)M_ * NH_];
__device__ bf16 g_Wq_hi[(size_t)NH_ * C_], g_Wq_lo[(size_t)NH_ * C_];  // [NH][C] (transposed)
__device__ bf16 g_Wk_hi[(size_t)KH_ * C_], g_Wk_lo[(size_t)KH_ * C_];  // [KH][C]
__device__ bf16 g_Wv_hi[(size_t)KH_ * C_], g_Wv_lo[(size_t)KH_ * C_];
__device__ bf16 g_Wo_hi[(size_t)C_ * NH_], g_Wo_lo[(size_t)C_ * NH_];  // [C][NH]

// ---------------------------------------------------------------------------
// Elementwise split: f32 -> bf16 hi + bf16 lo (hi = rn(f), lo = rn(f - hi))
// ---------------------------------------------------------------------------
__global__ __launch_bounds__(256) void split_f32(
    const float* __restrict__ src, bf16* __restrict__ hi, bf16* __restrict__ lo,
    size_t n4)
{
    size_t i = (size_t)blockIdx.x * blockDim.x + threadIdx.x;
    if (i >= n4) return;
    float4 v = *(const float4*)(src + i * 4);
    bf16 h0 = __float2bfloat16(v.x), h1 = __float2bfloat16(v.y);
    bf16 h2 = __float2bfloat16(v.z), h3 = __float2bfloat16(v.w);
    bf16 l0 = __float2bfloat16(v.x - __bfloat162float(h0));
    bf16 l1 = __float2bfloat16(v.y - __bfloat162float(h1));
    bf16 l2 = __float2bfloat16(v.z - __bfloat162float(h2));
    bf16 l3 = __float2bfloat16(v.w - __bfloat162float(h3));
    __nv_bfloat162 hp0 = {h0, h1}, hp1 = {h2, h3};
    __nv_bfloat162 lp0 = {l0, l1}, lp1 = {l2, l3};
    *(uint2*)(hi + i * 4) = make_uint2(*(unsigned int*)&hp0, *(unsigned int*)&hp1);
    *(uint2*)(lo + i * 4) = make_uint2(*(unsigned int*)&lp0, *(unsigned int*)&lp1);
}

// ---------------------------------------------------------------------------
// Transpose + split: W[K][N] f32 -> Wt_hi/lo[N][K] bf16
// ---------------------------------------------------------------------------
__global__ __launch_bounds__(256) void tsplit(
    const float* __restrict__ W, bf16* __restrict__ hi, bf16* __restrict__ lo,
    int K, int N)
{
    __shared__ float t[32][33];
    int kb = blockIdx.y * 32, nb = blockIdx.x * 32;
    #pragma unroll
    for (int i = 0; i < 4; i++)
        t[threadIdx.y + 8 * i][threadIdx.x] =
            W[(size_t)(kb + threadIdx.y + 8 * i) * N + nb + threadIdx.x];
    __syncthreads();
    #pragma unroll
    for (int i = 0; i < 4; i++) {
        float f = t[threadIdx.x][threadIdx.y + 8 * i];
        bf16 h = __float2bfloat16(f);
        size_t idx = (size_t)(nb + threadIdx.y + 8 * i) * K + kb + threadIdx.x;
        hi[idx] = h;
        lo[idx] = __float2bfloat16(f - __bfloat162float(h));
    }
}

// ---------------------------------------------------------------------------
// Split-bf16 tensor-core GEMM: C[M,N](f32) = A[M,K] * Bt[N,K]^T
// A given as hi/lo bf16 [M][K]; B given transposed hi/lo bf16 [N][K].
// 128x128x32 tile, 3-stage cp.async pipeline, 8 warps (2x4), 64x32 warp tiles.
// ---------------------------------------------------------------------------
#define BM 128
#define BN 128
#define BK 32
#define GSTAGES 3
#define LDA 40                 // bf16 per smem row: 32 data + 8 pad (conflict-free)
#define SSZ (128 * LDA)        // bf16 per operand array per stage
#define STAGE_BYTES (4 * SSZ * 2)

__device__ __forceinline__ void cp16(void* dst, const void* src) {
    uint32_t d = (uint32_t)__cvta_generic_to_shared(dst);
    asm volatile("cp.async.cg.shared.global [%0], [%1], 16;\n" :: "r"(d), "l"(src));
}
__device__ __forceinline__ void mma16816(float* d, const uint32_t* a, const uint32_t* b) {
    asm volatile(
        "mma.sync.aligned.m16n8k16.row.col.f32.bf16.bf16.f32 "
        "{%0,%1,%2,%3},{%4,%5,%6,%7},{%8,%9},{%0,%1,%2,%3};\n"
        : "+f"(d[0]), "+f"(d[1]), "+f"(d[2]), "+f"(d[3])
        : "r"(a[0]), "r"(a[1]), "r"(a[2]), "r"(a[3]), "r"(b[0]), "r"(b[1]));
}

__global__ __launch_bounds__(256) void gemm_split(
    const bf16* __restrict__ Ah, const bf16* __restrict__ Al,
    const bf16* __restrict__ Bh, const bf16* __restrict__ Bl,
    float* __restrict__ Cc, int M, int N, int K)
{
    extern __shared__ bf16 sm[];
    int tid = threadIdx.x;
    int bx = blockIdx.x, by = blockIdx.y;
    int warp = tid >> 5, lane = tid & 31;
    int wm = (warp >> 2) * 64, wn = (warp & 3) * 32;
    int r = lane >> 2, c = lane & 3;

    const bf16* gAh = Ah + (size_t)(by * BM) * K;
    const bf16* gAl = Al + (size_t)(by * BM) * K;
    const bf16* gBh = Bh + (size_t)(bx * BN) * K;
    const bf16* gBl = Bl + (size_t)(bx * BN) * K;

    float acc[4][4][4];
    #pragma unroll
    for (int i = 0; i < 4; i++)
        #pragma unroll
        for (int j = 0; j < 4; j++)
            #pragma unroll
            for (int e = 0; e < 4; e++) acc[i][j][e] = 0.f;

    const int k_tiles = K / BK;

    auto issue = [&](int stage, int kt) {
        if (kt < k_tiles) {
            size_t k0 = (size_t)kt * BK;
            bf16* base = sm + stage * 4 * SSZ;
            #pragma unroll
            for (int p = 0; p < 2; p++) {
                int ci = tid + p * 256;          // 0..511
                int row = ci >> 2, c16 = ci & 3; // row, 16B-chunk within 64B row
                int so = row * LDA + c16 * 8;
                size_t go = (size_t)row * K + k0 + c16 * 8;
                cp16(base + so,           gAh + go);
                cp16(base + SSZ + so,     gAl + go);
                cp16(base + 2 * SSZ + so, gBh + go);
                cp16(base + 3 * SSZ + so, gBl + go);
            }
        }
        asm volatile("cp.async.commit_group;\n" ::);
    };

    #pragma unroll
    for (int s = 0; s < GSTAGES - 1; s++) issue(s, s);

    for (int kt = 0; kt < k_tiles; kt++) {
        asm volatile("cp.async.wait_group %0;\n" :: "n"(GSTAGES - 2));
        __syncthreads();
        issue((kt + GSTAGES - 1) % GSTAGES, kt + GSTAGES - 1);

        const uint32_t* wAh = (const uint32_t*)(sm + (kt % GSTAGES) * 4 * SSZ);
        const uint32_t* wAl = wAh + SSZ / 2;
        const uint32_t* wBh = wAh + SSZ;
        const uint32_t* wBl = wAh + 3 * (SSZ / 2);

        #pragma unroll
        for (int ks = 0; ks < 2; ks++) {
            int kw = ks * 8;   // word offset within row (20 words per row)
            uint32_t a_h[4][4], a_l[4][4], b_h[4][2], b_l[4][2];
            #pragma unroll
            for (int i = 0; i < 4; i++) {
                int r0 = (wm + i * 16 + r) * 20 + kw + c;
                int r1 = r0 + 8 * 20;
                a_h[i][0] = wAh[r0];     a_h[i][1] = wAh[r1];
                a_h[i][2] = wAh[r0 + 4]; a_h[i][3] = wAh[r1 + 4];
                a_l[i][0] = wAl[r0];     a_l[i][1] = wAl[r1];
                a_l[i][2] = wAl[r0 + 4]; a_l[i][3] = wAl[r1 + 4];
            }
            #pragma unroll
            for (int j = 0; j < 4; j++) {
                int n0 = (wn + j * 8 + r) * 20 + kw + c;
                b_h[j][0] = wBh[n0]; b_h[j][1] = wBh[n0 + 4];
                b_l[j][0] = wBl[n0]; b_l[j][1] = wBl[n0 + 4];
            }
            #pragma unroll
            for (int i = 0; i < 4; i++)
                #pragma unroll
                for (int j = 0; j < 4; j++) {
                    mma16816(acc[i][j], a_h[i], b_h[j]);
                    mma16816(acc[i][j], a_h[i], b_l[j]);
                    mma16816(acc[i][j], a_l[i], b_h[j]);
                }
        }
        __syncthreads();
    }

    #pragma unroll
    for (int i = 0; i < 4; i++)
        #pragma unroll
        for (int j = 0; j < 4; j++) {
            int row = by * BM + wm + i * 16 + r;
            int col = bx * BN + wn + j * 8 + 2 * c;
            *(float2*)(Cc + (size_t)row * N + col) =
                make_float2(acc[i][j][0], acc[i][j][1]);
            *(float2*)(Cc + (size_t)(row + 8) * N + col) =
                make_float2(acc[i][j][2], acc[i][j][3]);
        }
}

// ---------------------------------------------------------------------------
// Fused RMSNorm + RoPE + scale
// ---------------------------------------------------------------------------
__global__ __launch_bounds__(256) void rms_rope(float* __restrict__ buf,
                                                int width, int nheads,
                                                float outscale)
{
    int row = blockIdx.x;
    int t = row % T_;
    float* ptr = buf + (size_t)row * width;

    float ss = 0.f;
    for (int i = threadIdx.x; i < width; i += 256) {
        float v = ptr[i];
        ss += v * v;
    }
    #pragma unroll
    for (int o = 16; o; o >>= 1) ss += __shfl_xor_sync(0xffffffffu, ss, o);
    __shared__ float red[8];
    if ((threadIdx.x & 31) == 0) red[threadIdx.x >> 5] = ss;
    __syncthreads();
    float tot = red[0] + red[1] + red[2] + red[3] + red[4] + red[5] + red[6] + red[7];
    float rs = rsqrtf(tot / (float)width + 1e-6f) * outscale;

    int npairs = nheads * 64;
    const double TWO_PI = 6.283185307179586476925286766559;
    for (int p = threadIdx.x; p < npairs; p += 256) {
        int head = p >> 6;
        int hp = p & 63;
        float inv = __expf(-(float)hp * (9.210340371976184f / 64.f));
        float theta = (float)t * inv;
        double td = (double)theta * (1.0 / TWO_PI);
        double frac = td - floor(td);
        if (frac > 0.5) frac -= 1.0;
        float redang = (float)(frac * TWO_PI);
        float s, cc;
        sincosf(redang, &s, &cc);

        int base = head * H_;
        float x1 = ptr[base + hp] * rs;
        float x2 = ptr[base + hp + 64] * rs;
        ptr[base + hp]      = x1 * cc - x2 * s;
        ptr[base + hp + 64] = x2 * cc + x1 * s;
    }
}

// ---------------------------------------------------------------------------
// Flash-attention style kernel, fp32
// ---------------------------------------------------------------------------
struct __align__(16) AttnSmem {
    float Qs[H_][64];
    float Ks[H_][64];
    float Vs[64][H_];
    float Ss[64][65];
};

__global__ __launch_bounds__(256) void attn_kernel(
    const float* __restrict__ q, const float* __restrict__ k,
    const float* __restrict__ v, float* __restrict__ enc)
{
    extern __shared__ char smem_raw[];
    AttnSmem& sm = *reinterpret_cast<AttnSmem*>(smem_raw);
    const int QT = 64, ST = 64;

    int b = blockIdx.z;
    int n = blockIdx.y;
    int kh = n >> 2;
    int q0 = blockIdx.x * QT;
    int tid = threadIdx.x;

    const float* qbase = q + ((size_t)(b * T_ + q0)) * NH_ + n * H_;

    for (int idx = tid; idx < QT * 32; idx += 256) {
        int r = idx >> 5;
        int c4 = idx & 31;
        float4 val = *(const float4*)(qbase + (size_t)r * NH_ + c4 * 4);
        sm.Qs[c4 * 4 + 0][r] = val.x;
        sm.Qs[c4 * 4 + 1][r] = val.y;
        sm.Qs[c4 * 4 + 2][r] = val.z;
        sm.Qs[c4 * 4 + 3][r] = val.w;
    }

    float4 o4[8];
    #pragma unroll
    for (int i = 0; i < 8; i++) o4[i] = make_float4(0.f, 0.f, 0.f, 0.f);
    int orow = tid >> 2, oc = tid & 3;
    int ty = tid >> 4, tx = tid & 15;
    float mi = -1e30f, li = 0.f;
    __syncthreads();

    for (int s0 = 0; s0 < T_; s0 += ST) {
        const float* kbase = k + ((size_t)(b * T_ + s0)) * KH_ + kh * H_;
        const float* vbase = v + ((size_t)(b * T_ + s0)) * KH_ + kh * H_;
        for (int idx = tid; idx < ST * 32; idx += 256) {
            int r = idx >> 5;
            int c4 = idx & 31;
            float4 val = *(const float4*)(kbase + (size_t)r * KH_ + c4 * 4);
            sm.Ks[c4 * 4 + 0][r] = val.x;
            sm.Ks[c4 * 4 + 1][r] = val.y;
            sm.Ks[c4 * 4 + 2][r] = val.z;
            sm.Ks[c4 * 4 + 3][r] = val.w;
            float4 vv = *(const float4*)(vbase + (size_t)r * KH_ + c4 * 4);
            *(float4*)&sm.Vs[r][c4 * 4] = vv;
        }
        __syncthreads();

        {
            float accs[4][4];
            #pragma unroll
            for (int i = 0; i < 4; i++)
                #pragma unroll
                for (int j = 0; j < 4; j++) accs[i][j] = 0.f;

            #pragma unroll 4
            for (int h = 0; h < H_; ++h) {
                float4 a = *(const float4*)&sm.Qs[h][ty * 4];
                float4 bb = *(const float4*)&sm.Ks[h][tx * 4];
                float av[4] = {a.x, a.y, a.z, a.w};
                float bv[4] = {bb.x, bb.y, bb.z, bb.w};
                #pragma unroll
                for (int i = 0; i < 4; i++)
                    #pragma unroll
                    for (int j = 0; j < 4; j++)
                        accs[i][j] = fmaf(av[i], bv[j], accs[i][j]);
            }
            #pragma unroll
            for (int i = 0; i < 4; i++)
                #pragma unroll
                for (int j = 0; j < 4; j++)
                    sm.Ss[ty * 4 + i][tx * 4 + j] = accs[i][j];
        }
        __syncthreads();

        float tmax = -1e30f;
        #pragma unroll
        for (int j = 0; j < 16; j++) tmax = fmaxf(tmax, sm.Ss[orow][oc * 16 + j]);
        tmax = fmaxf(tmax, __shfl_xor_sync(0xffffffffu, tmax, 1));
        tmax = fmaxf(tmax, __shfl_xor_sync(0xffffffffu, tmax, 2));
        float mnew = fmaxf(mi, tmax);
        float alpha = __expf(mi - mnew);
        float ps = 0.f;
        #pragma unroll
        for (int j = 0; j < 16; j++) {
            float pv = __expf(sm.Ss[orow][oc * 16 + j] - mnew);
            sm.Ss[orow][oc * 16 + j] = pv;
            ps += pv;
        }
        ps += __shfl_xor_sync(0xffffffffu, ps, 1);
        ps += __shfl_xor_sync(0xffffffffu, ps, 2);
        li = li * alpha + ps;
        mi = mnew;
        #pragma unroll
        for (int i = 0; i < 8; i++) {
            o4[i].x *= alpha; o4[i].y *= alpha;
            o4[i].z *= alpha; o4[i].w *= alpha;
        }
        __syncwarp();

        #pragma unroll 1
        for (int s = 0; s < ST; ++s) {
            float p = sm.Ss[orow][s];
            #pragma unroll
            for (int i = 0; i < 8; i++) {
                float4 vv = *(const float4*)&sm.Vs[s][oc * 4 + 16 * i];
                o4[i].x = fmaf(p, vv.x, o4[i].x);
                o4[i].y = fmaf(p, vv.y, o4[i].y);
                o4[i].z = fmaf(p, vv.z, o4[i].z);
                o4[i].w = fmaf(p, vv.w, o4[i].w);
            }
        }
        __syncthreads();
    }

    float invl = 1.f / li;
    float* obase = enc + ((size_t)(b * T_ + q0 + orow)) * NH_ + n * H_;
    #pragma unroll
    for (int i = 0; i < 8; i++) {
        *(float4*)(obase + oc * 4 + 16 * i) =
            make_float4(o4[i].x * invl, o4[i].y * invl, o4[i].z * invl, o4[i].w * invl);
    }
}

// ---------------------------------------------------------------------------
extern "C" void kernel_launch(void* const* d_in, const int* in_sizes, int n_in,
                              void* d_out, int out_size)
{
    const float* x    = (const float*)d_in[0];
    const float* Wq   = (const float*)d_in[1];
    const float* Wk   = (const float*)d_in[2];
    const float* Wv   = (const float*)d_in[3];
    const float* Wout = (const float*)d_in[4];
    float* out = (float*)d_out;

    float *qb, *kb, *vb, *eb;
    cudaGetSymbolAddress((void**)&qb, g_q);
    cudaGetSymbolAddress((void**)&kb, g_k);
    cudaGetSymbolAddress((void**)&vb, g_v);
    cudaGetSymbolAddress((void**)&eb, g_enc);
    bf16 *xh, *xl, *eh, *el, *wqh, *wql, *wkh, *wkl, *wvh, *wvl, *woh, *wol;
    cudaGetSymbolAddress((void**)&xh, g_x_hi);  cudaGetSymbolAddress((void**)&xl, g_x_lo);
    cudaGetSymbolAddress((void**)&eh, g_e_hi);  cudaGetSymbolAddress((void**)&el, g_e_lo);
    cudaGetSymbolAddress((void**)&wqh, g_Wq_hi); cudaGetSymbolAddress((void**)&wql, g_Wq_lo);
    cudaGetSymbolAddress((void**)&wkh, g_Wk_hi); cudaGetSymbolAddress((void**)&wkl, g_Wk_lo);
    cudaGetSymbolAddress((void**)&wvh, g_Wv_hi); cudaGetSymbolAddress((void**)&wvl, g_Wv_lo);
    cudaGetSymbolAddress((void**)&woh, g_Wo_hi); cudaGetSymbolAddress((void**)&wol, g_Wo_lo);

    cudaFuncSetAttribute(attn_kernel, cudaFuncAttributeMaxDynamicSharedMemorySize,
                         (int)sizeof(AttnSmem));
    cudaFuncSetAttribute(gemm_split, cudaFuncAttributeMaxDynamicSharedMemorySize,
                         GSTAGES * STAGE_BYTES);

    // --- operand prep: split x, transpose+split weights ---
    split_f32<<<(int)((M_ * (size_t)C_ / 4 + 255) / 256), 256>>>(x, xh, xl, (size_t)M_ * C_ / 4);
    tsplit<<<dim3(NH_ / 32, C_ / 32), dim3(32, 8)>>>(Wq, wqh, wql, C_, NH_);
    tsplit<<<dim3(KH_ / 32, C_ / 32), dim3(32, 8)>>>(Wk, wkh, wkl, C_, KH_);
    tsplit<<<dim3(KH_ / 32, C_ / 32), dim3(32, 8)>>>(Wv, wvh, wvl, C_, KH_);
    tsplit<<<dim3(C_ / 32, NH_ / 32), dim3(32, 8)>>>(Wout, woh, wol, NH_, C_);

    // --- QKV projections (tensor-core, error-compensated bf16) ---
    gemm_split<<<dim3(NH_ / BN, M_ / BM), 256, GSTAGES * STAGE_BYTES>>>(
        xh, xl, wqh, wql, qb, M_, NH_, C_);
    gemm_split<<<dim3(KH_ / BN, M_ / BM), 256, GSTAGES * STAGE_BYTES>>>(
        xh, xl, wkh, wkl, kb, M_, KH_, C_);
    gemm_split<<<dim3(KH_ / BN, M_ / BM), 256, GSTAGES * STAGE_BYTES>>>(
        xh, xl, wvh, wvl, vb, M_, KH_, C_);

    // --- RMSNorm + RoPE (1/sqrt(H) folded into q) ---
    rms_rope<<<M_, 256>>>(qb, NH_, NHEADS, 0.08838834764831845f);
    rms_rope<<<M_, 256>>>(kb, KH_, 4, 1.0f);

    // --- Attention (fp32) ---
    dim3 gAttn(T_ / 64, NHEADS, B_);
    attn_kernel<<<gAttn, 256, sizeof(AttnSmem)>>>(qb, kb, vb, eb);

    // --- Output projection ---
    split_f32<<<(int)((M_ * (size_t)NH_ / 4 + 255) / 256), 256>>>(eb, eh, el, (size_t)M_ * NH_ / 4);
    gemm_split<<<dim3(C_ / BN, M_ / BM), 256, GSTAGES * STAGE_BYTES>>>(
        eh, el, woh, wol, out, M_, C_, NH_);
}

// round 4
// speedup vs baseline: 3.1100x; 2.5227x over previous
#include <cuda_runtime.h>
#include <cuda_bf16.h>
#include <cstdint>
#include <math.h>

#define B_ 4
#define T_ 2048
#define C_ 2048
#define NH_ 2048
#define KH_ 512
#define NHEADS 16
#define H_ 128
#define M_ (B_*T_)

typedef __nv_bfloat16 bf16;

// ---------------------------------------------------------------------------
// Device-global scratch
// ---------------------------------------------------------------------------
__device__ float g_q[(size_t)M_ * NH_];
__device__ float g_k[(size_t)M_ * KH_];
__device__ float g_v[(size_t)M_ * KH_];

__device__ bf16 g_x_hi[(size_t)M_ * C_],  g_x_lo[(size_t)M_ * C_];
__device__ bf16 g_e_hi[(size_t)M_ * NH_], g_e_lo[(size_t)M_ * NH_];
__device__ bf16 g_qh[(size_t)M_ * NH_],   g_ql[(size_t)M_ * NH_];
__device__ bf16 g_kh[(size_t)M_ * KH_],   g_kl[(size_t)M_ * KH_];
__device__ bf16 g_vth[(size_t)16 * 128 * T_], g_vtl[(size_t)16 * 128 * T_]; // [b*4+kh][h][t]
__device__ bf16 g_Wq_hi[(size_t)NH_ * C_], g_Wq_lo[(size_t)NH_ * C_];
__device__ bf16 g_Wk_hi[(size_t)KH_ * C_], g_Wk_lo[(size_t)KH_ * C_];
__device__ bf16 g_Wv_hi[(size_t)KH_ * C_], g_Wv_lo[(size_t)KH_ * C_];
__device__ bf16 g_Wo_hi[(size_t)C_ * NH_], g_Wo_lo[(size_t)C_ * NH_];

// ---------------------------------------------------------------------------
__global__ __launch_bounds__(256) void split_f32(
    const float* __restrict__ src, bf16* __restrict__ hi, bf16* __restrict__ lo,
    size_t n4)
{
    size_t i = (size_t)blockIdx.x * blockDim.x + threadIdx.x;
    if (i >= n4) return;
    float4 v = *(const float4*)(src + i * 4);
    bf16 h0 = __float2bfloat16(v.x), h1 = __float2bfloat16(v.y);
    bf16 h2 = __float2bfloat16(v.z), h3 = __float2bfloat16(v.w);
    bf16 l0 = __float2bfloat16(v.x - __bfloat162float(h0));
    bf16 l1 = __float2bfloat16(v.y - __bfloat162float(h1));
    bf16 l2 = __float2bfloat16(v.z - __bfloat162float(h2));
    bf16 l3 = __float2bfloat16(v.w - __bfloat162float(h3));
    __nv_bfloat162 hp0 = {h0, h1}, hp1 = {h2, h3};
    __nv_bfloat162 lp0 = {l0, l1}, lp1 = {l2, l3};
    *(uint2*)(hi + i * 4) = make_uint2(*(unsigned int*)&hp0, *(unsigned int*)&hp1);
    *(uint2*)(lo + i * 4) = make_uint2(*(unsigned int*)&lp0, *(unsigned int*)&lp1);
}

__global__ __launch_bounds__(256) void tsplit(
    const float* __restrict__ W, bf16* __restrict__ hi, bf16* __restrict__ lo,
    int K, int N)
{
    __shared__ float t[32][33];
    int kb = blockIdx.y * 32, nb = blockIdx.x * 32;
    #pragma unroll
    for (int i = 0; i < 4; i++)
        t[threadIdx.y + 8 * i][threadIdx.x] =
            W[(size_t)(kb + threadIdx.y + 8 * i) * N + nb + threadIdx.x];
    __syncthreads();
    #pragma unroll
    for (int i = 0; i < 4; i++) {
        float f = t[threadIdx.x][threadIdx.y + 8 * i];
        bf16 h = __float2bfloat16(f);
        size_t idx = (size_t)(nb + threadIdx.y + 8 * i) * K + kb + threadIdx.x;
        hi[idx] = h;
        lo[idx] = __float2bfloat16(f - __bfloat162float(h));
    }
}

// V transpose + split: g_v [b*T][512] -> vt[b*4+kh][h][t]
__global__ __launch_bounds__(256) void vtsplit(
    const float* __restrict__ v, bf16* __restrict__ hi, bf16* __restrict__ lo)
{
    __shared__ float t[32][33];
    int t0 = blockIdx.x * 32, h0 = blockIdx.y * 32;
    int bz = blockIdx.z;             // b*4 + kh
    int b = bz >> 2, kh = bz & 3;
    #pragma unroll
    for (int i = 0; i < 4; i++)
        t[threadIdx.y + 8 * i][threadIdx.x] =
            v[(size_t)(b * T_ + t0 + threadIdx.y + 8 * i) * KH_ + kh * 128 + h0 + threadIdx.x];
    __syncthreads();
    #pragma unroll
    for (int i = 0; i < 4; i++) {
        float f = t[threadIdx.x][threadIdx.y + 8 * i];
        bf16 h = __float2bfloat16(f);
        size_t idx = ((size_t)bz * 128 + h0 + threadIdx.y + 8 * i) * T_ + t0 + threadIdx.x;
        hi[idx] = h;
        lo[idx] = __float2bfloat16(f - __bfloat162float(h));
    }
}

// ---------------------------------------------------------------------------
// MMA / cp.async helpers
// ---------------------------------------------------------------------------
__device__ __forceinline__ void cp16(void* dst, const void* src) {
    uint32_t d = (uint32_t)__cvta_generic_to_shared(dst);
    asm volatile("cp.async.cg.shared.global [%0], [%1], 16;\n" :: "r"(d), "l"(src));
}
__device__ __forceinline__ void mma16816(float* d, const uint32_t* a, const uint32_t* b) {
    asm volatile(
        "mma.sync.aligned.m16n8k16.row.col.f32.bf16.bf16.f32 "
        "{%0,%1,%2,%3},{%4,%5,%6,%7},{%8,%9},{%0,%1,%2,%3};\n"
        : "+f"(d[0]), "+f"(d[1]), "+f"(d[2]), "+f"(d[3])
        : "r"(a[0]), "r"(a[1]), "r"(a[2]), "r"(a[3]), "r"(b[0]), "r"(b[1]));
}

// ---------------------------------------------------------------------------
// Split-bf16 GEMM (unchanged, passing at rel_err 2.5e-5)
// ---------------------------------------------------------------------------
#define BM 128
#define BN 128
#define BK 32
#define GSTAGES 3
#define LDA 40
#define SSZ (128 * LDA)
#define STAGE_BYTES (4 * SSZ * 2)

__global__ __launch_bounds__(256) void gemm_split(
    const bf16* __restrict__ Ah, const bf16* __restrict__ Al,
    const bf16* __restrict__ Bh, const bf16* __restrict__ Bl,
    float* __restrict__ Cc, int M, int N, int K)
{
    extern __shared__ bf16 sm[];
    int tid = threadIdx.x;
    int bx = blockIdx.x, by = blockIdx.y;
    int warp = tid >> 5, lane = tid & 31;
    int wm = (warp >> 2) * 64, wn = (warp & 3) * 32;
    int r = lane >> 2, c = lane & 3;

    const bf16* gAh = Ah + (size_t)(by * BM) * K;
    const bf16* gAl = Al + (size_t)(by * BM) * K;
    const bf16* gBh = Bh + (size_t)(bx * BN) * K;
    const bf16* gBl = Bl + (size_t)(bx * BN) * K;

    float acc[4][4][4];
    #pragma unroll
    for (int i = 0; i < 4; i++)
        #pragma unroll
        for (int j = 0; j < 4; j++)
            #pragma unroll
            for (int e = 0; e < 4; e++) acc[i][j][e] = 0.f;

    const int k_tiles = K / BK;

    auto issue = [&](int stage, int kt) {
        if (kt < k_tiles) {
            size_t k0 = (size_t)kt * BK;
            bf16* base = sm + stage * 4 * SSZ;
            #pragma unroll
            for (int p = 0; p < 2; p++) {
                int ci = tid + p * 256;
                int row = ci >> 2, c16 = ci & 3;
                int so = row * LDA + c16 * 8;
                size_t go = (size_t)row * K + k0 + c16 * 8;
                cp16(base + so,           gAh + go);
                cp16(base + SSZ + so,     gAl + go);
                cp16(base + 2 * SSZ + so, gBh + go);
                cp16(base + 3 * SSZ + so, gBl + go);
            }
        }
        asm volatile("cp.async.commit_group;\n" ::);
    };

    #pragma unroll
    for (int s = 0; s < GSTAGES - 1; s++) issue(s, s);

    for (int kt = 0; kt < k_tiles; kt++) {
        asm volatile("cp.async.wait_group %0;\n" :: "n"(GSTAGES - 2));
        __syncthreads();
        issue((kt + GSTAGES - 1) % GSTAGES, kt + GSTAGES - 1);

        const uint32_t* wAh = (const uint32_t*)(sm + (kt % GSTAGES) * 4 * SSZ);
        const uint32_t* wAl = wAh + SSZ / 2;
        const uint32_t* wBh = wAh + SSZ;
        const uint32_t* wBl = wAh + 3 * (SSZ / 2);

        #pragma unroll
        for (int ks = 0; ks < 2; ks++) {
            int kw = ks * 8;
            uint32_t a_h[4][4], a_l[4][4], b_h[4][2], b_l[4][2];
            #pragma unroll
            for (int i = 0; i < 4; i++) {
                int r0 = (wm + i * 16 + r) * 20 + kw + c;
                int r1 = r0 + 8 * 20;
                a_h[i][0] = wAh[r0];     a_h[i][1] = wAh[r1];
                a_h[i][2] = wAh[r0 + 4]; a_h[i][3] = wAh[r1 + 4];
                a_l[i][0] = wAl[r0];     a_l[i][1] = wAl[r1];
                a_l[i][2] = wAl[r0 + 4]; a_l[i][3] = wAl[r1 + 4];
            }
            #pragma unroll
            for (int j = 0; j < 4; j++) {
                int n0 = (wn + j * 8 + r) * 20 + kw + c;
                b_h[j][0] = wBh[n0]; b_h[j][1] = wBh[n0 + 4];
                b_l[j][0] = wBl[n0]; b_l[j][1] = wBl[n0 + 4];
            }
            #pragma unroll
            for (int i = 0; i < 4; i++)
                #pragma unroll
                for (int j = 0; j < 4; j++) {
                    mma16816(acc[i][j], a_h[i], b_h[j]);
                    mma16816(acc[i][j], a_h[i], b_l[j]);
                    mma16816(acc[i][j], a_l[i], b_h[j]);
                }
        }
        __syncthreads();
    }

    #pragma unroll
    for (int i = 0; i < 4; i++)
        #pragma unroll
        for (int j = 0; j < 4; j++) {
            int row = by * BM + wm + i * 16 + r;
            int col = bx * BN + wn + j * 8 + 2 * c;
            *(float2*)(Cc + (size_t)row * N + col) =
                make_float2(acc[i][j][0], acc[i][j][1]);
            *(float2*)(Cc + (size_t)(row + 8) * N + col) =
                make_float2(acc[i][j][2], acc[i][j][3]);
        }
}

// ---------------------------------------------------------------------------
// RMSNorm + RoPE + scale -> split bf16 output
// ---------------------------------------------------------------------------
__global__ __launch_bounds__(256) void rms_rope_split(
    const float* __restrict__ in, bf16* __restrict__ outh, bf16* __restrict__ outl,
    int width, int nheads, float outscale)
{
    int row = blockIdx.x;
    int t = row % T_;
    const float* ptr = in + (size_t)row * width;

    float ss = 0.f;
    for (int i = threadIdx.x; i < width; i += 256) {
        float v = ptr[i];
        ss += v * v;
    }
    #pragma unroll
    for (int o = 16; o; o >>= 1) ss += __shfl_xor_sync(0xffffffffu, ss, o);
    __shared__ float red[8];
    if ((threadIdx.x & 31) == 0) red[threadIdx.x >> 5] = ss;
    __syncthreads();
    float tot = red[0] + red[1] + red[2] + red[3] + red[4] + red[5] + red[6] + red[7];
    float rs = rsqrtf(tot / (float)width + 1e-6f) * outscale;

    int npairs = nheads * 64;
    const double TWO_PI = 6.283185307179586476925286766559;
    bf16* oh = outh + (size_t)row * width;
    bf16* ol = outl + (size_t)row * width;
    for (int p = threadIdx.x; p < npairs; p += 256) {
        int head = p >> 6;
        int hp = p & 63;
        float inv = __expf(-(float)hp * (9.210340371976184f / 64.f));
        float theta = (float)t * inv;
        double td = (double)theta * (1.0 / TWO_PI);
        double frac = td - floor(td);
        if (frac > 0.5) frac -= 1.0;
        float redang = (float)(frac * TWO_PI);
        float s, cc;
        sincosf(redang, &s, &cc);

        int base = head * H_;
        float x1 = ptr[base + hp] * rs;
        float x2 = ptr[base + hp + 64] * rs;
        float y1 = x1 * cc - x2 * s;
        float y2 = x2 * cc + x1 * s;
        bf16 h1 = __float2bfloat16(y1), h2 = __float2bfloat16(y2);
        oh[base + hp]      = h1;
        oh[base + hp + 64] = h2;
        ol[base + hp]      = __float2bfloat16(y1 - __bfloat162float(h1));
        ol[base + hp + 64] = __float2bfloat16(y2 - __bfloat162float(h2));
    }
}

// ---------------------------------------------------------------------------
// Flash attention with split-bf16 tensor-core MMAs.
// 64q x 64s tiles, H=128. 256 threads (8 warps). Double-buffered K/V cp.async.
// ---------------------------------------------------------------------------
// smem layout (bf16 units unless noted):
//  Qh 64x136 @0, Ql @8704
//  K stages: base 17408, per stage 17408 (Kh 8704 + Kl 8704)
//  V stages: base 52224, per stage 18432 (Vth 9216 + Vtl 9216), rows 128x72
//  Ss fp32 64x66 @byte 178176
//  Ph 64x72 @byte 195072, Pl follows
//  alphas(64 f32) @byte 213504, l(64 f32) @213760
#define ATTN_SMEM_BYTES 214016

__global__ __launch_bounds__(256) void attn_mma(
    const bf16* __restrict__ qh, const bf16* __restrict__ ql,
    const bf16* __restrict__ kh_, const bf16* __restrict__ kl_,
    const bf16* __restrict__ vth, const bf16* __restrict__ vtl,
    bf16* __restrict__ eh, bf16* __restrict__ el)
{
    extern __shared__ char smem[];
    bf16* sQh = (bf16*)smem;
    bf16* sQl = sQh + 8704;
    bf16* sK  = sQl + 8704;          // + stage*17408 ; kl = +8704
    bf16* sV  = sK + 2 * 17408;      // + stage*18432 ; vl = +9216
    float* sS = (float*)(smem + 178176);
    bf16* sPh = (bf16*)(smem + 195072);
    bf16* sPl = sPh + 4608;
    float* sAlpha = (float*)(smem + 213504);
    float* sL     = sAlpha + 64;

    int tid = threadIdx.x;
    int warp = tid >> 5, lane = tid & 31;
    int r = lane >> 2, c = lane & 3;

    int b  = blockIdx.z;
    int n  = blockIdx.y;
    int khd = n >> 2;                // kv head
    int q0 = blockIdx.x * 64;
    int bT = b * T_;

    // ---- prologue: Q tile loads (split, transposed-free [q][h]) ----
    #pragma unroll
    for (int p = 0; p < 8; p++) {
        int idx = p * 256 + tid;
        int arr = idx >> 10, rem = idx & 1023;
        int row = rem >> 4, ch = rem & 15;
        const bf16* src = (arr ? ql : qh) + (size_t)(bT + q0 + row) * NH_ + n * 128 + ch * 8;
        cp16((arr ? sQl : sQh) + row * 136 + ch * 8, src);
    }

    auto issue_kv = [&](int stage, int tile) {
        if (tile < T_ / 64) {
            int s0 = tile * 64;
            bf16* kb = sK + stage * 17408;
            bf16* vb = sV + stage * 18432;
            #pragma unroll
            for (int p = 0; p < 8; p++) {
                int idx = p * 256 + tid;
                int arr = idx >> 10, rem = idx & 1023;
                int row = rem >> 4, ch = rem & 15;
                const bf16* src = (arr ? kl_ : kh_) + (size_t)(bT + s0 + row) * KH_ + khd * 128 + ch * 8;
                cp16(kb + arr * 8704 + row * 136 + ch * 8, src);
            }
            #pragma unroll
            for (int p = 0; p < 8; p++) {
                int idx = p * 256 + tid;
                int arr = idx >> 10, rem = idx & 1023;
                int row = rem >> 3, ch = rem & 7;
                const bf16* src = (arr ? vtl : vth) + ((size_t)(b * 4 + khd) * 128 + row) * T_ + s0 + ch * 8;
                cp16(vb + arr * 9216 + row * 72 + ch * 8, src);
            }
        }
        asm volatile("cp.async.commit_group;\n" ::);
    };

    issue_kv(0, 0);

    // roles
    int wsr = (warp >> 1) * 16;      // S row strip (also PV q strip)
    int wsc = (warp & 1) * 32;       // S col strip
    int whh = (warp & 1) * 64;       // PV h strip
    int orow = tid >> 2, oc = tid & 3;
    float mi = -1e30f, li = 0.f;

    float oacc[8][4];
    #pragma unroll
    for (int j = 0; j < 8; j++)
        #pragma unroll
        for (int e = 0; e < 4; e++) oacc[j][e] = 0.f;

    const uint32_t* wQh = (const uint32_t*)sQh;
    const uint32_t* wQl = (const uint32_t*)sQl;

    for (int tIdx = 0; tIdx < T_ / 64; tIdx++) {
        asm volatile("cp.async.wait_group 0;\n" ::);
        __syncthreads();
        issue_kv((tIdx + 1) & 1, tIdx + 1);

        int stage = tIdx & 1;
        const uint32_t* wKh = (const uint32_t*)(sK + stage * 17408);
        const uint32_t* wKl = wKh + 8704 / 2;
        const uint32_t* wVh = (const uint32_t*)(sV + stage * 18432);
        const uint32_t* wVl = wVh + 9216 / 2;

        // ---- S = Q K^T (split MMA) ----
        {
            float sacc[4][4];
            #pragma unroll
            for (int j = 0; j < 4; j++)
                #pragma unroll
                for (int e = 0; e < 4; e++) sacc[j][e] = 0.f;

            #pragma unroll
            for (int kf = 0; kf < 8; kf++) {
                int kw = kf * 8;
                uint32_t ah[4], al[4];
                int r0 = (wsr + r) * 68 + kw + c;
                int r1 = r0 + 8 * 68;
                ah[0] = wQh[r0]; ah[1] = wQh[r1]; ah[2] = wQh[r0 + 4]; ah[3] = wQh[r1 + 4];
                al[0] = wQl[r0]; al[1] = wQl[r1]; al[2] = wQl[r0 + 4]; al[3] = wQl[r1 + 4];
                #pragma unroll
                for (int j = 0; j < 4; j++) {
                    int n0 = (wsc + j * 8 + r) * 68 + kw + c;
                    uint32_t bh[2] = {wKh[n0], wKh[n0 + 4]};
                    uint32_t bl[2] = {wKl[n0], wKl[n0 + 4]};
                    mma16816(sacc[j], ah, bh);
                    mma16816(sacc[j], ah, bl);
                    mma16816(sacc[j], al, bh);
                }
            }
            #pragma unroll
            for (int j = 0; j < 4; j++) {
                int row = wsr + r, col = wsc + j * 8 + 2 * c;
                *(float2*)&sS[row * 66 + col]       = make_float2(sacc[j][0], sacc[j][1]);
                *(float2*)&sS[(row + 8) * 66 + col] = make_float2(sacc[j][2], sacc[j][3]);
            }
        }
        __syncthreads();

        // ---- online softmax (4 threads per row) + P -> split bf16 ----
        {
            float tmax = -1e30f;
            #pragma unroll
            for (int j = 0; j < 16; j++)
                tmax = fmaxf(tmax, sS[orow * 66 + oc * 16 + j]);
            tmax = fmaxf(tmax, __shfl_xor_sync(0xffffffffu, tmax, 1));
            tmax = fmaxf(tmax, __shfl_xor_sync(0xffffffffu, tmax, 2));
            float mnew = fmaxf(mi, tmax);
            float alpha = __expf(mi - mnew);
            float ps = 0.f;
            #pragma unroll
            for (int j = 0; j < 16; j += 2) {
                float p0 = __expf(sS[orow * 66 + oc * 16 + j]     - mnew);
                float p1 = __expf(sS[orow * 66 + oc * 16 + j + 1] - mnew);
                ps += p0 + p1;
                bf16 h0 = __float2bfloat16(p0), h1 = __float2bfloat16(p1);
                __nv_bfloat162 hp = {h0, h1};
                __nv_bfloat162 lp = {__float2bfloat16(p0 - __bfloat162float(h0)),
                                     __float2bfloat16(p1 - __bfloat162float(h1))};
                *(__nv_bfloat162*)&sPh[orow * 72 + oc * 16 + j] = hp;
                *(__nv_bfloat162*)&sPl[orow * 72 + oc * 16 + j] = lp;
            }
            ps += __shfl_xor_sync(0xffffffffu, ps, 1);
            ps += __shfl_xor_sync(0xffffffffu, ps, 2);
            li = li * alpha + ps;
            mi = mnew;
            if (oc == 0) sAlpha[orow] = alpha;
        }
        __syncthreads();

        // ---- O = alpha*O + P V (split MMA) ----
        {
            float a0 = sAlpha[wsr + r], a1 = sAlpha[wsr + r + 8];
            #pragma unroll
            for (int j = 0; j < 8; j++) {
                oacc[j][0] *= a0; oacc[j][1] *= a0;
                oacc[j][2] *= a1; oacc[j][3] *= a1;
            }
            const uint32_t* wPh = (const uint32_t*)sPh;
            const uint32_t* wPl = (const uint32_t*)sPl;
            #pragma unroll
            for (int kf = 0; kf < 4; kf++) {
                int kc = kf * 8;
                uint32_t ah[4], al[4];
                int r0 = (wsr + r) * 36 + kc + c;
                int r1 = r0 + 8 * 36;
                ah[0] = wPh[r0]; ah[1] = wPh[r1]; ah[2] = wPh[r0 + 4]; ah[3] = wPh[r1 + 4];
                al[0] = wPl[r0]; al[1] = wPl[r1]; al[2] = wPl[r0 + 4]; al[3] = wPl[r1 + 4];
                #pragma unroll
                for (int j = 0; j < 8; j++) {
                    int n0 = (whh + j * 8 + r) * 36 + kc + c;
                    uint32_t bh[2] = {wVh[n0], wVh[n0 + 4]};
                    uint32_t bl[2] = {wVl[n0], wVl[n0 + 4]};
                    mma16816(oacc[j], ah, bh);
                    mma16816(oacc[j], ah, bl);
                    mma16816(oacc[j], al, bh);
                }
            }
        }
        // next-iteration top barrier protects Ss/P/alpha/KV reuse
    }

    if (oc == 0) sL[orow] = li;
    __syncthreads();

    float inv0 = 1.f / sL[wsr + r];
    float inv1 = 1.f / sL[wsr + r + 8];
    #pragma unroll
    for (int j = 0; j < 8; j++) {
        int col = n * 128 + whh + j * 8 + 2 * c;
        size_t i0 = (size_t)(bT + q0 + wsr + r) * NH_ + col;
        size_t i1 = (size_t)(bT + q0 + wsr + r + 8) * NH_ + col;
        float v0 = oacc[j][0] * inv0, v1 = oacc[j][1] * inv0;
        float v2 = oacc[j][2] * inv1, v3 = oacc[j][3] * inv1;
        bf16 h0 = __float2bfloat16(v0), h1 = __float2bfloat16(v1);
        bf16 h2 = __float2bfloat16(v2), h3 = __float2bfloat16(v3);
        __nv_bfloat162 hp0 = {h0, h1}, hp1 = {h2, h3};
        __nv_bfloat162 lp0 = {__float2bfloat16(v0 - __bfloat162float(h0)),
                              __float2bfloat16(v1 - __bfloat162float(h1))};
        __nv_bfloat162 lp1 = {__float2bfloat16(v2 - __bfloat162float(h2)),
                              __float2bfloat16(v3 - __bfloat162float(h3))};
        *(__nv_bfloat162*)&eh[i0] = hp0;
        *(__nv_bfloat162*)&el[i0] = lp0;
        *(__nv_bfloat162*)&eh[i1] = hp1;
        *(__nv_bfloat162*)&el[i1] = lp1;
    }
}

// ---------------------------------------------------------------------------
extern "C" void kernel_launch(void* const* d_in, const int* in_sizes, int n_in,
                              void* d_out, int out_size)
{
    const float* x    = (const float*)d_in[0];
    const float* Wq   = (const float*)d_in[1];
    const float* Wk   = (const float*)d_in[2];
    const float* Wv   = (const float*)d_in[3];
    const float* Wout = (const float*)d_in[4];
    float* out = (float*)d_out;

    float *qb, *kb, *vb;
    cudaGetSymbolAddress((void**)&qb, g_q);
    cudaGetSymbolAddress((void**)&kb, g_k);
    cudaGetSymbolAddress((void**)&vb, g_v);
    bf16 *xh, *xl, *eh, *el, *qsh, *qsl, *ksh, *ksl, *vth, *vtl;
    bf16 *wqh, *wql, *wkh, *wkl, *wvh, *wvl, *woh, *wol;
    cudaGetSymbolAddress((void**)&xh, g_x_hi);   cudaGetSymbolAddress((void**)&xl, g_x_lo);
    cudaGetSymbolAddress((void**)&eh, g_e_hi);   cudaGetSymbolAddress((void**)&el, g_e_lo);
    cudaGetSymbolAddress((void**)&qsh, g_qh);    cudaGetSymbolAddress((void**)&qsl, g_ql);
    cudaGetSymbolAddress((void**)&ksh, g_kh);    cudaGetSymbolAddress((void**)&ksl, g_kl);
    cudaGetSymbolAddress((void**)&vth, g_vth);   cudaGetSymbolAddress((void**)&vtl, g_vtl);
    cudaGetSymbolAddress((void**)&wqh, g_Wq_hi); cudaGetSymbolAddress((void**)&wql, g_Wq_lo);
    cudaGetSymbolAddress((void**)&wkh, g_Wk_hi); cudaGetSymbolAddress((void**)&wkl, g_Wk_lo);
    cudaGetSymbolAddress((void**)&wvh, g_Wv_hi); cudaGetSymbolAddress((void**)&wvl, g_Wv_lo);
    cudaGetSymbolAddress((void**)&woh, g_Wo_hi); cudaGetSymbolAddress((void**)&wol, g_Wo_lo);

    cudaFuncSetAttribute(gemm_split, cudaFuncAttributeMaxDynamicSharedMemorySize,
                         GSTAGES * STAGE_BYTES);
    cudaFuncSetAttribute(attn_mma, cudaFuncAttributeMaxDynamicSharedMemorySize,
                         ATTN_SMEM_BYTES);

    // operand prep
    split_f32<<<(int)((M_ * (size_t)C_ / 4 + 255) / 256), 256>>>(x, xh, xl, (size_t)M_ * C_ / 4);
    tsplit<<<dim3(NH_ / 32, C_ / 32), dim3(32, 8)>>>(Wq, wqh, wql, C_, NH_);
    tsplit<<<dim3(KH_ / 32, C_ / 32), dim3(32, 8)>>>(Wk, wkh, wkl, C_, KH_);
    tsplit<<<dim3(KH_ / 32, C_ / 32), dim3(32, 8)>>>(Wv, wvh, wvl, C_, KH_);
    tsplit<<<dim3(C_ / 32, NH_ / 32), dim3(32, 8)>>>(Wout, woh, wol, NH_, C_);

    // QKV projections
    gemm_split<<<dim3(NH_ / BN, M_ / BM), 256, GSTAGES * STAGE_BYTES>>>(
        xh, xl, wqh, wql, qb, M_, NH_, C_);
    gemm_split<<<dim3(KH_ / BN, M_ / BM), 256, GSTAGES * STAGE_BYTES>>>(
        xh, xl, wkh, wkl, kb, M_, KH_, C_);
    gemm_split<<<dim3(KH_ / BN, M_ / BM), 256, GSTAGES * STAGE_BYTES>>>(
        xh, xl, wvh, wvl, vb, M_, KH_, C_);

    // norm + rope -> split bf16 ; V transpose+split
    rms_rope_split<<<M_, 256>>>(qb, qsh, qsl, NH_, NHEADS, 0.08838834764831845f);
    rms_rope_split<<<M_, 256>>>(kb, ksh, ksl, KH_, 4, 1.0f);
    vtsplit<<<dim3(T_ / 32, 4, 16), dim3(32, 8)>>>(vb, vth, vtl);

    // attention (tensor-core)
    dim3 gAttn(T_ / 64, NHEADS, B_);
    attn_mma<<<gAttn, 256, ATTN_SMEM_BYTES>>>(qsh, qsl, ksh, ksl, vth, vtl, eh, el);

    // output projection
    gemm_split<<<dim3(C_ / BN, M_ / BM), 256, GSTAGES * STAGE_BYTES>>>(
        eh, el, woh, wol, out, M_, C_, NH_);
}

// round 6
// speedup vs baseline: 4.5240x; 1.4547x over previous
#include <cuda_runtime.h>
#include <cuda_bf16.h>
#include <cstdint>
#include <math.h>

#define B_ 4
#define T_ 2048
#define C_ 2048
#define NH_ 2048
#define KH_ 512
#define QKV_ 3072      // NH_ + KH_ + KH_
#define NHEADS 16
#define H_ 128
#define M_ (B_*T_)

typedef __nv_bfloat16 bf16;

#if defined(__CUDA_ARCH_FEAT_SM103_ALL) || defined(__CUDA_ARCH_FEAT_SM100_ALL)
#define HAS_TCGEN05 1
#else
#define HAS_TCGEN05 0
#endif

// ---------------------------------------------------------------------------
// Device-global scratch
// ---------------------------------------------------------------------------
__device__ float g_qkv[(size_t)M_ * QKV_];

__device__ bf16 g_x_hi[(size_t)M_ * C_],  g_x_lo[(size_t)M_ * C_];
__device__ bf16 g_e_hi[(size_t)M_ * NH_], g_e_lo[(size_t)M_ * NH_];
__device__ bf16 g_qh[(size_t)M_ * NH_],   g_ql[(size_t)M_ * NH_];
__device__ bf16 g_kh[(size_t)M_ * KH_],   g_kl[(size_t)M_ * KH_];
__device__ bf16 g_vth[(size_t)16 * 128 * T_], g_vtl[(size_t)16 * 128 * T_];
__device__ bf16 g_Wc_hi[(size_t)QKV_ * C_], g_Wc_lo[(size_t)QKV_ * C_];  // [Wq;Wk;Wv] transposed
__device__ bf16 g_Wo_hi[(size_t)C_ * NH_],  g_Wo_lo[(size_t)C_ * NH_];

// ---------------------------------------------------------------------------
// PTX helpers
// ---------------------------------------------------------------------------
__device__ __forceinline__ void cp16(void* dst, const void* src) {
    uint32_t d = (uint32_t)__cvta_generic_to_shared(dst);
    asm volatile("cp.async.cg.shared.global [%0], [%1], 16;\n" :: "r"(d), "l"(src));
}
__device__ __forceinline__ void mma16816(float* d, const uint32_t* a, const uint32_t* b) {
    asm volatile(
        "mma.sync.aligned.m16n8k16.row.col.f32.bf16.bf16.f32 "
        "{%0,%1,%2,%3},{%4,%5,%6,%7},{%8,%9},{%0,%1,%2,%3};\n"
        : "+f"(d[0]), "+f"(d[1]), "+f"(d[2]), "+f"(d[3])
        : "r"(a[0]), "r"(a[1]), "r"(a[2]), "r"(a[3]), "r"(b[0]), "r"(b[1]));
}

#if HAS_TCGEN05
#define MBAR_INIT(addr, cnt) \
    asm volatile("mbarrier.init.shared.b64 [%0], %1;" :: "r"(addr), "r"(cnt) : "memory")
#define MBAR_WAIT(addr, parity) do {                                        \
    asm volatile(                                                            \
        "{\n\t.reg .pred P1;\n\t"                                            \
        "WAIT_LOOP_%=:\n\t"                                                  \
        "mbarrier.try_wait.parity.acquire.cta.shared::cta.b64 P1, [%0], %1, 0x989680;\n\t" \
        "@P1 bra.uni WAIT_DONE_%=;\n\t"                                      \
        "bra.uni WAIT_LOOP_%=;\n\t"                                          \
        "WAIT_DONE_%=:\n\t}"                                                 \
        :: "r"(addr), "r"(parity) : "memory");                               \
} while (0)
#define TC_ALLOC(smem_addr, n) \
    asm volatile("tcgen05.alloc.cta_group::1.sync.aligned.shared::cta.b32 [%0], %1;" \
                 :: "r"(smem_addr), "r"(n) : "memory")
#define TC_DEALLOC(tmem, n) \
    asm volatile("tcgen05.dealloc.cta_group::1.sync.aligned.b32 %0, %1;" :: "r"(tmem), "r"(n))
#define TC_RELINQ() \
    asm volatile("tcgen05.relinquish_alloc_permit.cta_group::1.sync.aligned;")
#define TC_COMMIT(mbar) \
    asm volatile("tcgen05.commit.cta_group::1.mbarrier::arrive::one.shared::cluster.b64 [%0];" \
                 :: "r"(mbar) : "memory")
#define TC_FENCE_AFTER()  asm volatile("tcgen05.fence::after_thread_sync;" ::: "memory")
#define TC_LD_X32(r, addr) \
    asm volatile( \
        "tcgen05.ld.sync.aligned.32x32b.x32.b32 " \
        "{%0, %1, %2, %3, %4, %5, %6, %7, %8, %9, %10, %11, %12, %13, %14, %15, " \
        " %16, %17, %18, %19, %20, %21, %22, %23, %24, %25, %26, %27, %28, %29, %30, %31}, [%32];" \
        : "=r"((r)[0]),  "=r"((r)[1]),  "=r"((r)[2]),  "=r"((r)[3]), \
          "=r"((r)[4]),  "=r"((r)[5]),  "=r"((r)[6]),  "=r"((r)[7]), \
          "=r"((r)[8]),  "=r"((r)[9]),  "=r"((r)[10]), "=r"((r)[11]), \
          "=r"((r)[12]), "=r"((r)[13]), "=r"((r)[14]), "=r"((r)[15]), \
          "=r"((r)[16]), "=r"((r)[17]), "=r"((r)[18]), "=r"((r)[19]), \
          "=r"((r)[20]), "=r"((r)[21]), "=r"((r)[22]), "=r"((r)[23]), \
          "=r"((r)[24]), "=r"((r)[25]), "=r"((r)[26]), "=r"((r)[27]), \
          "=r"((r)[28]), "=r"((r)[29]), "=r"((r)[30]), "=r"((r)[31]) \
        : "r"(addr))
#define TC_WAIT_LD() asm volatile("tcgen05.wait::ld.sync.aligned;" ::: "memory")

__device__ __forceinline__ void tc_mma_ss_f16(
    uint32_t d_tmem, uint64_t a_desc, uint64_t b_desc, uint32_t idesc, uint32_t en)
{
    asm volatile(
        "{\n\t.reg .pred p;\n\t"
        "setp.ne.u32 p, %4, 0;\n\t"
        "tcgen05.mma.cta_group::1.kind::f16 [%0], %1, %2, %3, {%5, %5, %5, %5}, p;\n\t"
        "}"
        :: "r"(d_tmem), "l"(a_desc), "l"(b_desc), "r"(idesc), "r"(en), "r"(0u)
        : "memory");
}
__device__ __forceinline__ uint64_t make_desc_sw128(uint32_t smem_addr) {
    return ((uint64_t)2 << 61) | ((uint64_t)1 << 46) | ((uint64_t)64 << 32)
         | ((uint64_t)1 << 16) | ((uint64_t)(smem_addr >> 4) & 0x3FFF);
}
#endif

// ---------------------------------------------------------------------------
// Dual-path GEMM: C[M,N](f32) = A[M,K] * Bt[N,K]^T, split bf16 operands.
// Tile 128x128. tcgen05 path when the compile pass has sm_103a/sm_100a
// features; otherwise mma.sync fallback (identical math, known-good).
// ---------------------------------------------------------------------------
#define GBM 128
#define GBN 128
// tcgen05 path constants
#define TBK 64
#define ST_OP 16384                 // 128x64 bf16
#define TSTAGE (4 * ST_OP)          // Ah,Al,Bh,Bl
// fallback constants
#define FBK 32
#define FLDA 40
#define FSSZ (128 * FLDA)
#define FSTAGE_BYTES (4 * FSSZ * 2)
// unified dynamic smem: max(1024 + 2*65536, 3*40960) = 132096
#define GEMM_SMEM 132096
#define GEMM_IDESC 0x8200490u       // f32 acc, bf16 a/b, M=128, N=128

__global__ __launch_bounds__(256) void gemm_dual(
    const bf16* __restrict__ Ah, const bf16* __restrict__ Al,
    const bf16* __restrict__ Bh, const bf16* __restrict__ Bl,
    float* __restrict__ Cc, int M, int N, int K)
{
#if HAS_TCGEN05
    // ------------------------- tcgen05 path -------------------------
    extern __shared__ __align__(1024) char smem[];
    uint32_t sbase = (uint32_t)__cvta_generic_to_shared(smem);
    int tid = threadIdx.x, warp = tid >> 5, lane = tid & 31;
    int bx = blockIdx.x, by = blockIdx.y;
    const int ktiles = K / TBK;

    if (tid == 0) {
        MBAR_INIT(sbase + 16, 1);
        MBAR_INIT(sbase + 24, 1);
    }
    if (warp == 0) TC_ALLOC(sbase, 128);
    __syncthreads();
    uint32_t tmem;
    asm volatile("ld.shared.b32 %0, [%1];" : "=r"(tmem) : "r"(sbase));

    char* stage0 = smem + 1024;

    auto issue = [&](int kt) {
        if (kt < ktiles) {
            char* st = stage0 + (kt & 1) * TSTAGE;
            size_t k0 = (size_t)kt * TBK;
            const bf16* gsrc[4] = {
                Ah + (size_t)(by * GBM) * K + k0,
                Al + (size_t)(by * GBM) * K + k0,
                Bh + (size_t)(bx * GBN) * K + k0,
                Bl + (size_t)(bx * GBN) * K + k0 };
            #pragma unroll
            for (int a = 0; a < 4; a++) {
                char* base = st + a * ST_OP;
                #pragma unroll
                for (int it = 0; it < 4; it++) {
                    int idx = tid + it * 256;
                    int row = idx >> 3, ch = idx & 7;
                    uint32_t off = (uint32_t)((row >> 3) * 1024 + (row & 7) * 128 + ch * 16);
                    off ^= ((off >> 3) & 0x70);
                    cp16(base + off, gsrc[a] + (size_t)row * K + ch * 8);
                }
            }
        }
        asm volatile("cp.async.commit_group;\n" ::);
    };

    issue(0);

    for (int kt = 0; kt < ktiles; kt++) {
        if (kt >= 1) {
            uint32_t mb = sbase + 16 + ((kt - 1) & 1) * 8;
            MBAR_WAIT(mb, ((kt - 1) >> 1) & 1);
        }
        issue(kt + 1);
        asm volatile("cp.async.wait_group 1;\n" ::);
        __syncthreads();

        if (tid == 0) {
            asm volatile("fence.proxy.async.shared::cta;" ::: "memory");
            char* st = stage0 + (kt & 1) * TSTAGE;
            uint32_t a0 = (uint32_t)__cvta_generic_to_shared(st);
            uint64_t dAh = make_desc_sw128(a0);
            uint64_t dAl = make_desc_sw128(a0 + ST_OP);
            uint64_t dBh = make_desc_sw128(a0 + 2 * ST_OP);
            uint64_t dBl = make_desc_sw128(a0 + 3 * ST_OP);
            #pragma unroll
            for (int ks = 0; ks < 4; ks++) {
                tc_mma_ss_f16(tmem, dAh + ks * 2, dBh + ks * 2, GEMM_IDESC,
                              (kt > 0 || ks > 0) ? 1u : 0u);
                tc_mma_ss_f16(tmem, dAh + ks * 2, dBl + ks * 2, GEMM_IDESC, 1u);
                tc_mma_ss_f16(tmem, dAl + ks * 2, dBh + ks * 2, GEMM_IDESC, 1u);
            }
            TC_COMMIT(sbase + 16 + (kt & 1) * 8);
        }
    }

    {
        uint32_t mb = sbase + 16 + ((ktiles - 1) & 1) * 8;
        MBAR_WAIT(mb, ((ktiles - 1) >> 1) & 1);
    }
    TC_FENCE_AFTER();

    // epilogue: warp w -> rows (w&3)*32+lane, cols (w>>2)*64 .. +63
    int sp = warp & 3, chf = warp >> 2;
    #pragma unroll
    for (int cc = 0; cc < 2; cc++) {
        uint32_t dr[32];
        TC_LD_X32(dr, tmem + chf * 64 + cc * 32);
        TC_WAIT_LD();
        int row = by * GBM + sp * 32 + lane;
        int col = bx * GBN + chf * 64 + cc * 32;
        float* o = Cc + (size_t)row * N + col;
        #pragma unroll
        for (int q = 0; q < 8; q++)
            *(float4*)(o + q * 4) = make_float4(
                __uint_as_float(dr[4 * q]),     __uint_as_float(dr[4 * q + 1]),
                __uint_as_float(dr[4 * q + 2]), __uint_as_float(dr[4 * q + 3]));
    }
    __syncthreads();
    if (warp == 0) {
        TC_RELINQ();
        TC_DEALLOC(tmem, 128);
    }
#else
    // ------------------------- mma.sync fallback -------------------------
    extern __shared__ bf16 sm[];
    int tid = threadIdx.x;
    int bx = blockIdx.x, by = blockIdx.y;
    int warp = tid >> 5, lane = tid & 31;
    int wm = (warp >> 2) * 64, wn = (warp & 3) * 32;
    int r = lane >> 2, c = lane & 3;

    const bf16* gAh = Ah + (size_t)(by * GBM) * K;
    const bf16* gAl = Al + (size_t)(by * GBM) * K;
    const bf16* gBh = Bh + (size_t)(bx * GBN) * K;
    const bf16* gBl = Bl + (size_t)(bx * GBN) * K;

    float acc[4][4][4];
    #pragma unroll
    for (int i = 0; i < 4; i++)
        #pragma unroll
        for (int j = 0; j < 4; j++)
            #pragma unroll
            for (int e = 0; e < 4; e++) acc[i][j][e] = 0.f;

    const int k_tiles = K / FBK;

    auto issue = [&](int stage, int kt) {
        if (kt < k_tiles) {
            size_t k0 = (size_t)kt * FBK;
            bf16* base = sm + stage * 4 * FSSZ;
            #pragma unroll
            for (int p = 0; p < 2; p++) {
                int ci = tid + p * 256;
                int row = ci >> 2, c16 = ci & 3;
                int so = row * FLDA + c16 * 8;
                size_t go = (size_t)row * K + k0 + c16 * 8;
                cp16(base + so,            gAh + go);
                cp16(base + FSSZ + so,     gAl + go);
                cp16(base + 2 * FSSZ + so, gBh + go);
                cp16(base + 3 * FSSZ + so, gBl + go);
            }
        }
        asm volatile("cp.async.commit_group;\n" ::);
    };

    #pragma unroll
    for (int s = 0; s < 2; s++) issue(s, s);

    for (int kt = 0; kt < k_tiles; kt++) {
        asm volatile("cp.async.wait_group 1;\n" ::);
        __syncthreads();
        issue((kt + 2) % 3, kt + 2);

        const uint32_t* wAh = (const uint32_t*)(sm + (kt % 3) * 4 * FSSZ);
        const uint32_t* wAl = wAh + FSSZ / 2;
        const uint32_t* wBh = wAh + FSSZ;
        const uint32_t* wBl = wAh + 3 * (FSSZ / 2);

        #pragma unroll
        for (int ks = 0; ks < 2; ks++) {
            int kw = ks * 8;
            uint32_t a_h[4][4], a_l[4][4], b_h[4][2], b_l[4][2];
            #pragma unroll
            for (int i = 0; i < 4; i++) {
                int r0 = (wm + i * 16 + r) * 20 + kw + c;
                int r1 = r0 + 8 * 20;
                a_h[i][0] = wAh[r0];     a_h[i][1] = wAh[r1];
                a_h[i][2] = wAh[r0 + 4]; a_h[i][3] = wAh[r1 + 4];
                a_l[i][0] = wAl[r0];     a_l[i][1] = wAl[r1];
                a_l[i][2] = wAl[r0 + 4]; a_l[i][3] = wAl[r1 + 4];
            }
            #pragma unroll
            for (int j = 0; j < 4; j++) {
                int n0 = (wn + j * 8 + r) * 20 + kw + c;
                b_h[j][0] = wBh[n0]; b_h[j][1] = wBh[n0 + 4];
                b_l[j][0] = wBl[n0]; b_l[j][1] = wBl[n0 + 4];
            }
            #pragma unroll
            for (int i = 0; i < 4; i++)
                #pragma unroll
                for (int j = 0; j < 4; j++) {
                    mma16816(acc[i][j], a_h[i], b_h[j]);
                    mma16816(acc[i][j], a_h[i], b_l[j]);
                    mma16816(acc[i][j], a_l[i], b_h[j]);
                }
        }
        __syncthreads();
    }

    #pragma unroll
    for (int i = 0; i < 4; i++)
        #pragma unroll
        for (int j = 0; j < 4; j++) {
            int row = by * GBM + wm + i * 16 + r;
            int col = bx * GBN + wn + j * 8 + 2 * c;
            *(float2*)(Cc + (size_t)row * N + col) =
                make_float2(acc[i][j][0], acc[i][j][1]);
            *(float2*)(Cc + (size_t)(row + 8) * N + col) =
                make_float2(acc[i][j][2], acc[i][j][3]);
        }
#endif
}

// ---------------------------------------------------------------------------
// Prep kernels
// ---------------------------------------------------------------------------
__global__ __launch_bounds__(256) void split_f32(
    const float* __restrict__ src, bf16* __restrict__ hi, bf16* __restrict__ lo,
    size_t n4)
{
    size_t i = (size_t)blockIdx.x * blockDim.x + threadIdx.x;
    if (i >= n4) return;
    float4 v = *(const float4*)(src + i * 4);
    bf16 h0 = __float2bfloat16(v.x), h1 = __float2bfloat16(v.y);
    bf16 h2 = __float2bfloat16(v.z), h3 = __float2bfloat16(v.w);
    bf16 l0 = __float2bfloat16(v.x - __bfloat162float(h0));
    bf16 l1 = __float2bfloat16(v.y - __bfloat162float(h1));
    bf16 l2 = __float2bfloat16(v.z - __bfloat162float(h2));
    bf16 l3 = __float2bfloat16(v.w - __bfloat162float(h3));
    __nv_bfloat162 hp0 = {h0, h1}, hp1 = {h2, h3};
    __nv_bfloat162 lp0 = {l0, l1}, lp1 = {l2, l3};
    *(uint2*)(hi + i * 4) = make_uint2(*(unsigned int*)&hp0, *(unsigned int*)&hp1);
    *(uint2*)(lo + i * 4) = make_uint2(*(unsigned int*)&lp0, *(unsigned int*)&lp1);
}

__global__ __launch_bounds__(256) void tsplit(
    const float* __restrict__ W, bf16* __restrict__ hi, bf16* __restrict__ lo,
    int K, int N)
{
    __shared__ float t[32][33];
    int kb = blockIdx.y * 32, nb = blockIdx.x * 32;
    #pragma unroll
    for (int i = 0; i < 4; i++)
        t[threadIdx.y + 8 * i][threadIdx.x] =
            W[(size_t)(kb + threadIdx.y + 8 * i) * N + nb + threadIdx.x];
    __syncthreads();
    #pragma unroll
    for (int i = 0; i < 4; i++) {
        float f = t[threadIdx.x][threadIdx.y + 8 * i];
        bf16 h = __float2bfloat16(f);
        size_t idx = (size_t)(nb + threadIdx.y + 8 * i) * K + kb + threadIdx.x;
        hi[idx] = h;
        lo[idx] = __float2bfloat16(f - __bfloat162float(h));
    }
}

// V transpose+split: v at qkv[:, 2560 + kh*128 + h] -> vt[b*4+kh][h][t]
__global__ __launch_bounds__(256) void vtsplit(
    const float* __restrict__ qkv, bf16* __restrict__ hi, bf16* __restrict__ lo)
{
    __shared__ float t[32][33];
    int t0 = blockIdx.x * 32, h0 = blockIdx.y * 32;
    int bz = blockIdx.z;
    int b = bz >> 2, kh = bz & 3;
    #pragma unroll
    for (int i = 0; i < 4; i++)
        t[threadIdx.y + 8 * i][threadIdx.x] =
            qkv[(size_t)(b * T_ + t0 + threadIdx.y + 8 * i) * QKV_ + 2560 + kh * 128 + h0 + threadIdx.x];
    __syncthreads();
    #pragma unroll
    for (int i = 0; i < 4; i++) {
        float f = t[threadIdx.x][threadIdx.y + 8 * i];
        bf16 h = __float2bfloat16(f);
        size_t idx = ((size_t)bz * 128 + h0 + threadIdx.y + 8 * i) * T_ + t0 + threadIdx.x;
        hi[idx] = h;
        lo[idx] = __float2bfloat16(f - __bfloat162float(h));
    }
}

// ---------------------------------------------------------------------------
// RMSNorm + RoPE + scale -> split bf16, reading strided from fused qkv
// ---------------------------------------------------------------------------
__global__ __launch_bounds__(256) void rms_rope_split(
    const float* __restrict__ in, int inoff,
    bf16* __restrict__ outh, bf16* __restrict__ outl,
    int width, int nheads, float outscale)
{
    int row = blockIdx.x;
    int t = row % T_;
    const float* ptr = in + (size_t)row * QKV_ + inoff;

    float ss = 0.f;
    for (int i = threadIdx.x; i < width; i += 256) {
        float v = ptr[i];
        ss += v * v;
    }
    #pragma unroll
    for (int o = 16; o; o >>= 1) ss += __shfl_xor_sync(0xffffffffu, ss, o);
    __shared__ float red[8];
    if ((threadIdx.x & 31) == 0) red[threadIdx.x >> 5] = ss;
    __syncthreads();
    float tot = red[0] + red[1] + red[2] + red[3] + red[4] + red[5] + red[6] + red[7];
    float rs = rsqrtf(tot / (float)width + 1e-6f) * outscale;

    int npairs = nheads * 64;
    const double TWO_PI = 6.283185307179586476925286766559;
    bf16* oh = outh + (size_t)row * width;
    bf16* ol = outl + (size_t)row * width;
    for (int p = threadIdx.x; p < npairs; p += 256) {
        int head = p >> 6;
        int hp = p & 63;
        float inv = __expf(-(float)hp * (9.210340371976184f / 64.f));
        float theta = (float)t * inv;
        double td = (double)theta * (1.0 / TWO_PI);
        double frac = td - floor(td);
        if (frac > 0.5) frac -= 1.0;
        float redang = (float)(frac * TWO_PI);
        float s, cc;
        sincosf(redang, &s, &cc);

        int base = head * H_;
        float x1 = ptr[base + hp] * rs;
        float x2 = ptr[base + hp + 64] * rs;
        float y1 = x1 * cc - x2 * s;
        float y2 = x2 * cc + x1 * s;
        bf16 h1 = __float2bfloat16(y1), h2 = __float2bfloat16(y2);
        oh[base + hp]      = h1;
        oh[base + hp + 64] = h2;
        ol[base + hp]      = __float2bfloat16(y1 - __bfloat162float(h1));
        ol[base + hp + 64] = __float2bfloat16(y2 - __bfloat162float(h2));
    }
}

// ---------------------------------------------------------------------------
// Flash attention with split-bf16 mma.sync (unchanged from R4, passing)
// ---------------------------------------------------------------------------
#define ATTN_SMEM_BYTES 214016

__global__ __launch_bounds__(256) void attn_mma(
    const bf16* __restrict__ qh, const bf16* __restrict__ ql,
    const bf16* __restrict__ kh_, const bf16* __restrict__ kl_,
    const bf16* __restrict__ vth, const bf16* __restrict__ vtl,
    bf16* __restrict__ eh, bf16* __restrict__ el)
{
    extern __shared__ char smem[];
    bf16* sQh = (bf16*)smem;
    bf16* sQl = sQh + 8704;
    bf16* sK  = sQl + 8704;
    bf16* sV  = sK + 2 * 17408;
    float* sS = (float*)(smem + 178176);
    bf16* sPh = (bf16*)(smem + 195072);
    bf16* sPl = sPh + 4608;
    float* sAlpha = (float*)(smem + 213504);
    float* sL     = sAlpha + 64;

    int tid = threadIdx.x;
    int warp = tid >> 5, lane = tid & 31;
    int r = lane >> 2, c = lane & 3;

    int b  = blockIdx.z;
    int n  = blockIdx.y;
    int khd = n >> 2;
    int q0 = blockIdx.x * 64;
    int bT = b * T_;

    #pragma unroll
    for (int p = 0; p < 8; p++) {
        int idx = p * 256 + tid;
        int arr = idx >> 10, rem = idx & 1023;
        int row = rem >> 4, ch = rem & 15;
        const bf16* src = (arr ? ql : qh) + (size_t)(bT + q0 + row) * NH_ + n * 128 + ch * 8;
        cp16((arr ? sQl : sQh) + row * 136 + ch * 8, src);
    }

    auto issue_kv = [&](int stage, int tile) {
        if (tile < T_ / 64) {
            int s0 = tile * 64;
            bf16* kb = sK + stage * 17408;
            bf16* vb = sV + stage * 18432;
            #pragma unroll
            for (int p = 0; p < 8; p++) {
                int idx = p * 256 + tid;
                int arr = idx >> 10, rem = idx & 1023;
                int row = rem >> 4, ch = rem & 15;
                const bf16* src = (arr ? kl_ : kh_) + (size_t)(bT + s0 + row) * KH_ + khd * 128 + ch * 8;
                cp16(kb + arr * 8704 + row * 136 + ch * 8, src);
            }
            #pragma unroll
            for (int p = 0; p < 8; p++) {
                int idx = p * 256 + tid;
                int arr = idx >> 10, rem = idx & 1023;
                int row = rem >> 3, ch = rem & 7;
                const bf16* src = (arr ? vtl : vth) + ((size_t)(b * 4 + khd) * 128 + row) * T_ + s0 + ch * 8;
                cp16(vb + arr * 9216 + row * 72 + ch * 8, src);
            }
        }
        asm volatile("cp.async.commit_group;\n" ::);
    };

    issue_kv(0, 0);

    int wsr = (warp >> 1) * 16;
    int wsc = (warp & 1) * 32;
    int whh = (warp & 1) * 64;
    int orow = tid >> 2, oc = tid & 3;
    float mi = -1e30f, li = 0.f;

    float oacc[8][4];
    #pragma unroll
    for (int j = 0; j < 8; j++)
        #pragma unroll
        for (int e = 0; e < 4; e++) oacc[j][e] = 0.f;

    const uint32_t* wQh = (const uint32_t*)sQh;
    const uint32_t* wQl = (const uint32_t*)sQl;

    for (int tIdx = 0; tIdx < T_ / 64; tIdx++) {
        asm volatile("cp.async.wait_group 0;\n" ::);
        __syncthreads();
        issue_kv((tIdx + 1) & 1, tIdx + 1);

        int stage = tIdx & 1;
        const uint32_t* wKh = (const uint32_t*)(sK + stage * 17408);
        const uint32_t* wKl = wKh + 8704 / 2;
        const uint32_t* wVh = (const uint32_t*)(sV + stage * 18432);
        const uint32_t* wVl = wVh + 9216 / 2;

        {
            float sacc[4][4];
            #pragma unroll
            for (int j = 0; j < 4; j++)
                #pragma unroll
                for (int e = 0; e < 4; e++) sacc[j][e] = 0.f;

            #pragma unroll
            for (int kf = 0; kf < 8; kf++) {
                int kw = kf * 8;
                uint32_t ah[4], al[4];
                int r0 = (wsr + r) * 68 + kw + c;
                int r1 = r0 + 8 * 68;
                ah[0] = wQh[r0]; ah[1] = wQh[r1]; ah[2] = wQh[r0 + 4]; ah[3] = wQh[r1 + 4];
                al[0] = wQl[r0]; al[1] = wQl[r1]; al[2] = wQl[r0 + 4]; al[3] = wQl[r1 + 4];
                #pragma unroll
                for (int j = 0; j < 4; j++) {
                    int n0 = (wsc + j * 8 + r) * 68 + kw + c;
                    uint32_t bh[2] = {wKh[n0], wKh[n0 + 4]};
                    uint32_t bl[2] = {wKl[n0], wKl[n0 + 4]};
                    mma16816(sacc[j], ah, bh);
                    mma16816(sacc[j], ah, bl);
                    mma16816(sacc[j], al, bh);
                }
            }
            #pragma unroll
            for (int j = 0; j < 4; j++) {
                int row = wsr + r, col = wsc + j * 8 + 2 * c;
                *(float2*)&sS[row * 66 + col]       = make_float2(sacc[j][0], sacc[j][1]);
                *(float2*)&sS[(row + 8) * 66 + col] = make_float2(sacc[j][2], sacc[j][3]);
            }
        }
        __syncthreads();

        {
            float tmax = -1e30f;
            #pragma unroll
            for (int j = 0; j < 16; j++)
                tmax = fmaxf(tmax, sS[orow * 66 + oc * 16 + j]);
            tmax = fmaxf(tmax, __shfl_xor_sync(0xffffffffu, tmax, 1));
            tmax = fmaxf(tmax, __shfl_xor_sync(0xffffffffu, tmax, 2));
            float mnew = fmaxf(mi, tmax);
            float alpha = __expf(mi - mnew);
            float ps = 0.f;
            #pragma unroll
            for (int j = 0; j < 16; j += 2) {
                float p0 = __expf(sS[orow * 66 + oc * 16 + j]     - mnew);
                float p1 = __expf(sS[orow * 66 + oc * 16 + j + 1] - mnew);
                ps += p0 + p1;
                bf16 h0 = __float2bfloat16(p0), h1 = __float2bfloat16(p1);
                __nv_bfloat162 hp = {h0, h1};
                __nv_bfloat162 lp = {__float2bfloat16(p0 - __bfloat162float(h0)),
                                     __float2bfloat16(p1 - __bfloat162float(h1))};
                *(__nv_bfloat162*)&sPh[orow * 72 + oc * 16 + j] = hp;
                *(__nv_bfloat162*)&sPl[orow * 72 + oc * 16 + j] = lp;
            }
            ps += __shfl_xor_sync(0xffffffffu, ps, 1);
            ps += __shfl_xor_sync(0xffffffffu, ps, 2);
            li = li * alpha + ps;
            mi = mnew;
            if (oc == 0) sAlpha[orow] = alpha;
        }
        __syncthreads();

        {
            float a0 = sAlpha[wsr + r], a1 = sAlpha[wsr + r + 8];
            #pragma unroll
            for (int j = 0; j < 8; j++) {
                oacc[j][0] *= a0; oacc[j][1] *= a0;
                oacc[j][2] *= a1; oacc[j][3] *= a1;
            }
            const uint32_t* wPh = (const uint32_t*)sPh;
            const uint32_t* wPl = (const uint32_t*)sPl;
            #pragma unroll
            for (int kf = 0; kf < 4; kf++) {
                int kc = kf * 8;
                uint32_t ah[4], al[4];
                int r0 = (wsr + r) * 36 + kc + c;
                int r1 = r0 + 8 * 36;
                ah[0] = wPh[r0]; ah[1] = wPh[r1]; ah[2] = wPh[r0 + 4]; ah[3] = wPh[r1 + 4];
                al[0] = wPl[r0]; al[1] = wPl[r1]; al[2] = wPl[r0 + 4]; al[3] = wPl[r1 + 4];
                #pragma unroll
                for (int j = 0; j < 8; j++) {
                    int n0 = (whh + j * 8 + r) * 36 + kc + c;
                    uint32_t bh[2] = {wVh[n0], wVh[n0 + 4]};
                    uint32_t bl[2] = {wVl[n0], wVl[n0 + 4]};
                    mma16816(oacc[j], ah, bh);
                    mma16816(oacc[j], ah, bl);
                    mma16816(oacc[j], al, bh);
                }
            }
        }
    }

    if (oc == 0) sL[orow] = li;
    __syncthreads();

    float inv0 = 1.f / sL[wsr + r];
    float inv1 = 1.f / sL[wsr + r + 8];
    #pragma unroll
    for (int j = 0; j < 8; j++) {
        int col = n * 128 + whh + j * 8 + 2 * c;
        size_t i0 = (size_t)(bT + q0 + wsr + r) * NH_ + col;
        size_t i1 = (size_t)(bT + q0 + wsr + r + 8) * NH_ + col;
        float v0 = oacc[j][0] * inv0, v1 = oacc[j][1] * inv0;
        float v2 = oacc[j][2] * inv1, v3 = oacc[j][3] * inv1;
        bf16 h0 = __float2bfloat16(v0), h1 = __float2bfloat16(v1);
        bf16 h2 = __float2bfloat16(v2), h3 = __float2bfloat16(v3);
        __nv_bfloat162 hp0 = {h0, h1}, hp1 = {h2, h3};
        __nv_bfloat162 lp0 = {__float2bfloat16(v0 - __bfloat162float(h0)),
                              __float2bfloat16(v1 - __bfloat162float(h1))};
        __nv_bfloat162 lp1 = {__float2bfloat16(v2 - __bfloat162float(h2)),
                              __float2bfloat16(v3 - __bfloat162float(h3))};
        *(__nv_bfloat162*)&eh[i0] = hp0;
        *(__nv_bfloat162*)&el[i0] = lp0;
        *(__nv_bfloat162*)&eh[i1] = hp1;
        *(__nv_bfloat162*)&el[i1] = lp1;
    }
}

// ---------------------------------------------------------------------------
extern "C" void kernel_launch(void* const* d_in, const int* in_sizes, int n_in,
                              void* d_out, int out_size)
{
    const float* x    = (const float*)d_in[0];
    const float* Wq   = (const float*)d_in[1];
    const float* Wk   = (const float*)d_in[2];
    const float* Wv   = (const float*)d_in[3];
    const float* Wout = (const float*)d_in[4];
    float* out = (float*)d_out;

    float* qkv;
    cudaGetSymbolAddress((void**)&qkv, g_qkv);
    bf16 *xh, *xl, *eh, *el, *qsh, *qsl, *ksh, *ksl, *vth, *vtl;
    bf16 *wch, *wcl, *woh, *wol;
    cudaGetSymbolAddress((void**)&xh, g_x_hi);   cudaGetSymbolAddress((void**)&xl, g_x_lo);
    cudaGetSymbolAddress((void**)&eh, g_e_hi);   cudaGetSymbolAddress((void**)&el, g_e_lo);
    cudaGetSymbolAddress((void**)&qsh, g_qh);    cudaGetSymbolAddress((void**)&qsl, g_ql);
    cudaGetSymbolAddress((void**)&ksh, g_kh);    cudaGetSymbolAddress((void**)&ksl, g_kl);
    cudaGetSymbolAddress((void**)&vth, g_vth);   cudaGetSymbolAddress((void**)&vtl, g_vtl);
    cudaGetSymbolAddress((void**)&wch, g_Wc_hi); cudaGetSymbolAddress((void**)&wcl, g_Wc_lo);
    cudaGetSymbolAddress((void**)&woh, g_Wo_hi); cudaGetSymbolAddress((void**)&wol, g_Wo_lo);

    cudaFuncSetAttribute(gemm_dual, cudaFuncAttributeMaxDynamicSharedMemorySize,
                         GEMM_SMEM);
    cudaFuncSetAttribute(attn_mma, cudaFuncAttributeMaxDynamicSharedMemorySize,
                         ATTN_SMEM_BYTES);

    // operand prep: x split; weights transposed+split into fused buffer
    split_f32<<<(int)((M_ * (size_t)C_ / 4 + 255) / 256), 256>>>(x, xh, xl, (size_t)M_ * C_ / 4);
    tsplit<<<dim3(NH_ / 32, C_ / 32), dim3(32, 8)>>>(Wq, wch, wcl, C_, NH_);
    tsplit<<<dim3(KH_ / 32, C_ / 32), dim3(32, 8)>>>(
        Wk, wch + (size_t)NH_ * C_, wcl + (size_t)NH_ * C_, C_, KH_);
    tsplit<<<dim3(KH_ / 32, C_ / 32), dim3(32, 8)>>>(
        Wv, wch + (size_t)(NH_ + KH_) * C_, wcl + (size_t)(NH_ + KH_) * C_, C_, KH_);
    tsplit<<<dim3(C_ / 32, NH_ / 32), dim3(32, 8)>>>(Wout, woh, wol, NH_, C_);

    // fused QKV projection
    gemm_dual<<<dim3(QKV_ / GBN, M_ / GBM), 256, GEMM_SMEM>>>(
        xh, xl, wch, wcl, qkv, M_, QKV_, C_);

    // norm + rope -> split bf16 ; V transpose+split
    rms_rope_split<<<M_, 256>>>(qkv, 0,    qsh, qsl, NH_, NHEADS, 0.08838834764831845f);
    rms_rope_split<<<M_, 256>>>(qkv, 2048, ksh, ksl, KH_, 4, 1.0f);
    vtsplit<<<dim3(T_ / 32, 4, 16), dim3(32, 8)>>>(qkv, vth, vtl);

    // attention
    dim3 gAttn(T_ / 64, NHEADS, B_);
    attn_mma<<<gAttn, 256, ATTN_SMEM_BYTES>>>(qsh, qsl, ksh, ksl, vth, vtl, eh, el);

    // output projection
    gemm_dual<<<dim3(C_ / GBN, M_ / GBM), 256, GEMM_SMEM>>>(
        eh, el, woh, wol, out, M_, C_, NH_);
}

// round 7
// speedup vs baseline: 10.0254x; 2.2160x over previous
#include <cuda_runtime.h>
#include <cuda_bf16.h>
#include <cstdint>
#include <math.h>

#define B_ 4
#define T_ 2048
#define C_ 2048
#define NH_ 2048
#define KH_ 512
#define QKV_ 3072      // NH_ + KH_ + KH_
#define NHEADS 16
#define H_ 128
#define M_ (B_*T_)

typedef __nv_bfloat16 bf16;

#if defined(__CUDA_ARCH_FEAT_SM103_ALL) || defined(__CUDA_ARCH_FEAT_SM100_ALL)
#define HAS_TCGEN05 1
#else
#define HAS_TCGEN05 0
#endif

// ---------------------------------------------------------------------------
// Device-global scratch
// ---------------------------------------------------------------------------
__device__ float g_qkv[(size_t)M_ * QKV_];

__device__ bf16 g_x_hi[(size_t)M_ * C_],  g_x_lo[(size_t)M_ * C_];
__device__ bf16 g_e_hi[(size_t)M_ * NH_], g_e_lo[(size_t)M_ * NH_];
__device__ bf16 g_qh[(size_t)M_ * NH_],   g_ql[(size_t)M_ * NH_];
__device__ bf16 g_kh[(size_t)M_ * KH_],   g_kl[(size_t)M_ * KH_];
__device__ bf16 g_vth[(size_t)16 * 128 * T_], g_vtl[(size_t)16 * 128 * T_];
__device__ bf16 g_Wc_hi[(size_t)QKV_ * C_], g_Wc_lo[(size_t)QKV_ * C_];
__device__ bf16 g_Wo_hi[(size_t)C_ * NH_],  g_Wo_lo[(size_t)C_ * NH_];

// ---------------------------------------------------------------------------
// PTX helpers
// ---------------------------------------------------------------------------
__device__ __forceinline__ void cp16(void* dst, const void* src) {
    uint32_t d = (uint32_t)__cvta_generic_to_shared(dst);
    asm volatile("cp.async.cg.shared.global [%0], [%1], 16;\n" :: "r"(d), "l"(src));
}
__device__ __forceinline__ void mma16816(float* d, const uint32_t* a, const uint32_t* b) {
    asm volatile(
        "mma.sync.aligned.m16n8k16.row.col.f32.bf16.bf16.f32 "
        "{%0,%1,%2,%3},{%4,%5,%6,%7},{%8,%9},{%0,%1,%2,%3};\n"
        : "+f"(d[0]), "+f"(d[1]), "+f"(d[2]), "+f"(d[3])
        : "r"(a[0]), "r"(a[1]), "r"(a[2]), "r"(a[3]), "r"(b[0]), "r"(b[1]));
}

#if HAS_TCGEN05
#define MBAR_INIT(addr, cnt) \
    asm volatile("mbarrier.init.shared.b64 [%0], %1;" :: "r"(addr), "r"(cnt) : "memory")
#define MBAR_WAIT(addr, parity) do {                                        \
    asm volatile(                                                            \
        "{\n\t.reg .pred P1;\n\t"                                            \
        "WAIT_LOOP_%=:\n\t"                                                  \
        "mbarrier.try_wait.parity.acquire.cta.shared::cta.b64 P1, [%0], %1, 0x989680;\n\t" \
        "@P1 bra.uni WAIT_DONE_%=;\n\t"                                      \
        "bra.uni WAIT_LOOP_%=;\n\t"                                          \
        "WAIT_DONE_%=:\n\t}"                                                 \
        :: "r"(addr), "r"(parity) : "memory");                               \
} while (0)
#define TC_ALLOC(smem_addr, n) \
    asm volatile("tcgen05.alloc.cta_group::1.sync.aligned.shared::cta.b32 [%0], %1;" \
                 :: "r"(smem_addr), "r"(n) : "memory")
#define TC_DEALLOC(tmem, n) \
    asm volatile("tcgen05.dealloc.cta_group::1.sync.aligned.b32 %0, %1;" :: "r"(tmem), "r"(n))
#define TC_RELINQ() \
    asm volatile("tcgen05.relinquish_alloc_permit.cta_group::1.sync.aligned;")
#define TC_COMMIT(mbar) \
    asm volatile("tcgen05.commit.cta_group::1.mbarrier::arrive::one.shared::cluster.b64 [%0];" \
                 :: "r"(mbar) : "memory")
#define TC_FENCE_AFTER()  asm volatile("tcgen05.fence::after_thread_sync;" ::: "memory")
#define TC_FENCE_BEFORE() asm volatile("tcgen05.fence::before_thread_sync;" ::: "memory")
#define TC_WAIT_LD() asm volatile("tcgen05.wait::ld.sync.aligned;" ::: "memory")
#define TC_WAIT_ST() asm volatile("tcgen05.wait::st.sync.aligned;" ::: "memory")

#define TC_LD_X32(r, addr) \
    asm volatile( \
        "tcgen05.ld.sync.aligned.32x32b.x32.b32 " \
        "{%0, %1, %2, %3, %4, %5, %6, %7, %8, %9, %10, %11, %12, %13, %14, %15, " \
        " %16, %17, %18, %19, %20, %21, %22, %23, %24, %25, %26, %27, %28, %29, %30, %31}, [%32];" \
        : "=r"((r)[0]),  "=r"((r)[1]),  "=r"((r)[2]),  "=r"((r)[3]), \
          "=r"((r)[4]),  "=r"((r)[5]),  "=r"((r)[6]),  "=r"((r)[7]), \
          "=r"((r)[8]),  "=r"((r)[9]),  "=r"((r)[10]), "=r"((r)[11]), \
          "=r"((r)[12]), "=r"((r)[13]), "=r"((r)[14]), "=r"((r)[15]), \
          "=r"((r)[16]), "=r"((r)[17]), "=r"((r)[18]), "=r"((r)[19]), \
          "=r"((r)[20]), "=r"((r)[21]), "=r"((r)[22]), "=r"((r)[23]), \
          "=r"((r)[24]), "=r"((r)[25]), "=r"((r)[26]), "=r"((r)[27]), \
          "=r"((r)[28]), "=r"((r)[29]), "=r"((r)[30]), "=r"((r)[31]) \
        : "r"(addr))

#define TC_ST_X32(addr, r) \
    asm volatile( \
        "tcgen05.st.sync.aligned.32x32b.x32.b32 [%0], " \
        "{%1, %2, %3, %4, %5, %6, %7, %8, %9, %10, %11, %12, %13, %14, %15, %16, " \
        " %17, %18, %19, %20, %21, %22, %23, %24, %25, %26, %27, %28, %29, %30, %31, %32};" \
        :: "r"(addr), \
           "r"((r)[0]),  "r"((r)[1]),  "r"((r)[2]),  "r"((r)[3]), \
           "r"((r)[4]),  "r"((r)[5]),  "r"((r)[6]),  "r"((r)[7]), \
           "r"((r)[8]),  "r"((r)[9]),  "r"((r)[10]), "r"((r)[11]), \
           "r"((r)[12]), "r"((r)[13]), "r"((r)[14]), "r"((r)[15]), \
           "r"((r)[16]), "r"((r)[17]), "r"((r)[18]), "r"((r)[19]), \
           "r"((r)[20]), "r"((r)[21]), "r"((r)[22]), "r"((r)[23]), \
           "r"((r)[24]), "r"((r)[25]), "r"((r)[26]), "r"((r)[27]), \
           "r"((r)[28]), "r"((r)[29]), "r"((r)[30]), "r"((r)[31]) \
        : "memory")

#define TC_ST_X16(addr, r) \
    asm volatile( \
        "tcgen05.st.sync.aligned.32x32b.x16.b32 [%0], " \
        "{%1, %2, %3, %4, %5, %6, %7, %8, %9, %10, %11, %12, %13, %14, %15, %16};" \
        :: "r"(addr), \
           "r"((r)[0]),  "r"((r)[1]),  "r"((r)[2]),  "r"((r)[3]), \
           "r"((r)[4]),  "r"((r)[5]),  "r"((r)[6]),  "r"((r)[7]), \
           "r"((r)[8]),  "r"((r)[9]),  "r"((r)[10]), "r"((r)[11]), \
           "r"((r)[12]), "r"((r)[13]), "r"((r)[14]), "r"((r)[15]) \
        : "memory")

__device__ __forceinline__ void tc_mma_ss_f16(
    uint32_t d_tmem, uint64_t a_desc, uint64_t b_desc, uint32_t idesc, uint32_t en)
{
    asm volatile(
        "{\n\t.reg .pred p;\n\t"
        "setp.ne.u32 p, %4, 0;\n\t"
        "tcgen05.mma.cta_group::1.kind::f16 [%0], %1, %2, %3, {%5, %5, %5, %5}, p;\n\t"
        "}"
        :: "r"(d_tmem), "l"(a_desc), "l"(b_desc), "r"(idesc), "r"(en), "r"(0u)
        : "memory");
}
__device__ __forceinline__ void tc_mma_ts_f16(
    uint32_t d_tmem, uint32_t a_tmem, uint64_t b_desc, uint32_t idesc, uint32_t en)
{
    asm volatile(
        "{\n\t.reg .pred p;\n\t"
        "setp.ne.u32 p, %4, 0;\n\t"
        "tcgen05.mma.cta_group::1.kind::f16 [%0], [%1], %2, %3, {%5, %5, %5, %5}, p;\n\t"
        "}"
        :: "r"(d_tmem), "r"(a_tmem), "l"(b_desc), "r"(idesc), "r"(en), "r"(0u)
        : "memory");
}
__device__ __forceinline__ uint64_t make_desc_sw128(uint32_t smem_addr) {
    return ((uint64_t)2 << 61) | ((uint64_t)1 << 46) | ((uint64_t)64 << 32)
         | ((uint64_t)1 << 16) | ((uint64_t)(smem_addr >> 4) & 0x3FFF);
}
#endif

// ---------------------------------------------------------------------------
// Dual-path GEMM (unchanged from R6, passing): C = A * Bt^T, split bf16
// ---------------------------------------------------------------------------
#define GBM 128
#define GBN 128
#define TBK 64
#define ST_OP 16384
#define TSTAGE (4 * ST_OP)
#define FBK 32
#define FLDA 40
#define FSSZ (128 * FLDA)
#define GEMM_SMEM 132096
#define GEMM_IDESC 0x8200490u

__global__ __launch_bounds__(256) void gemm_dual(
    const bf16* __restrict__ Ah, const bf16* __restrict__ Al,
    const bf16* __restrict__ Bh, const bf16* __restrict__ Bl,
    float* __restrict__ Cc, int M, int N, int K)
{
#if HAS_TCGEN05
    extern __shared__ __align__(1024) char smem[];
    uint32_t sbase = (uint32_t)__cvta_generic_to_shared(smem);
    int tid = threadIdx.x, warp = tid >> 5, lane = tid & 31;
    int bx = blockIdx.x, by = blockIdx.y;
    const int ktiles = K / TBK;

    if (tid == 0) {
        MBAR_INIT(sbase + 16, 1);
        MBAR_INIT(sbase + 24, 1);
    }
    if (warp == 0) TC_ALLOC(sbase, 128);
    __syncthreads();
    uint32_t tmem;
    asm volatile("ld.shared.b32 %0, [%1];" : "=r"(tmem) : "r"(sbase));

    char* stage0 = smem + 1024;

    auto issue = [&](int kt) {
        if (kt < ktiles) {
            char* st = stage0 + (kt & 1) * TSTAGE;
            size_t k0 = (size_t)kt * TBK;
            const bf16* gsrc[4] = {
                Ah + (size_t)(by * GBM) * K + k0,
                Al + (size_t)(by * GBM) * K + k0,
                Bh + (size_t)(bx * GBN) * K + k0,
                Bl + (size_t)(bx * GBN) * K + k0 };
            #pragma unroll
            for (int a = 0; a < 4; a++) {
                char* base = st + a * ST_OP;
                #pragma unroll
                for (int it = 0; it < 4; it++) {
                    int idx = tid + it * 256;
                    int row = idx >> 3, ch = idx & 7;
                    uint32_t off = (uint32_t)((row >> 3) * 1024 + (row & 7) * 128 + ch * 16);
                    off ^= ((off >> 3) & 0x70);
                    cp16(base + off, gsrc[a] + (size_t)row * K + ch * 8);
                }
            }
        }
        asm volatile("cp.async.commit_group;\n" ::);
    };

    issue(0);

    for (int kt = 0; kt < ktiles; kt++) {
        if (kt >= 1) {
            uint32_t mb = sbase + 16 + ((kt - 1) & 1) * 8;
            MBAR_WAIT(mb, ((kt - 1) >> 1) & 1);
        }
        issue(kt + 1);
        asm volatile("cp.async.wait_group 1;\n" ::);
        __syncthreads();

        if (tid == 0) {
            asm volatile("fence.proxy.async.shared::cta;" ::: "memory");
            char* st = stage0 + (kt & 1) * TSTAGE;
            uint32_t a0 = (uint32_t)__cvta_generic_to_shared(st);
            uint64_t dAh = make_desc_sw128(a0);
            uint64_t dAl = make_desc_sw128(a0 + ST_OP);
            uint64_t dBh = make_desc_sw128(a0 + 2 * ST_OP);
            uint64_t dBl = make_desc_sw128(a0 + 3 * ST_OP);
            #pragma unroll
            for (int ks = 0; ks < 4; ks++) {
                tc_mma_ss_f16(tmem, dAh + ks * 2, dBh + ks * 2, GEMM_IDESC,
                              (kt > 0 || ks > 0) ? 1u : 0u);
                tc_mma_ss_f16(tmem, dAh + ks * 2, dBl + ks * 2, GEMM_IDESC, 1u);
                tc_mma_ss_f16(tmem, dAl + ks * 2, dBh + ks * 2, GEMM_IDESC, 1u);
            }
            TC_COMMIT(sbase + 16 + (kt & 1) * 8);
        }
    }

    {
        uint32_t mb = sbase + 16 + ((ktiles - 1) & 1) * 8;
        MBAR_WAIT(mb, ((ktiles - 1) >> 1) & 1);
    }
    TC_FENCE_AFTER();

    int sp = warp & 3, chf = warp >> 2;
    #pragma unroll
    for (int cc = 0; cc < 2; cc++) {
        uint32_t dr[32];
        TC_LD_X32(dr, tmem + chf * 64 + cc * 32);
        TC_WAIT_LD();
        int row = by * GBM + sp * 32 + lane;
        int col = bx * GBN + chf * 64 + cc * 32;
        float* o = Cc + (size_t)row * N + col;
        #pragma unroll
        for (int q = 0; q < 8; q++)
            *(float4*)(o + q * 4) = make_float4(
                __uint_as_float(dr[4 * q]),     __uint_as_float(dr[4 * q + 1]),
                __uint_as_float(dr[4 * q + 2]), __uint_as_float(dr[4 * q + 3]));
    }
    __syncthreads();
    if (warp == 0) {
        TC_RELINQ();
        TC_DEALLOC(tmem, 128);
    }
#else
    // mma.sync fallback (PTX pass only; runtime uses sm_103a cubin)
    extern __shared__ bf16 sm[];
    int tid = threadIdx.x;
    int bx = blockIdx.x, by = blockIdx.y;
    int warp = tid >> 5, lane = tid & 31;
    int wm = (warp >> 2) * 64, wn = (warp & 3) * 32;
    int r = lane >> 2, c = lane & 3;

    const bf16* gAh = Ah + (size_t)(by * GBM) * K;
    const bf16* gAl = Al + (size_t)(by * GBM) * K;
    const bf16* gBh = Bh + (size_t)(bx * GBN) * K;
    const bf16* gBl = Bl + (size_t)(bx * GBN) * K;

    float acc[4][4][4];
    #pragma unroll
    for (int i = 0; i < 4; i++)
        #pragma unroll
        for (int j = 0; j < 4; j++)
            #pragma unroll
            for (int e = 0; e < 4; e++) acc[i][j][e] = 0.f;

    const int k_tiles = K / FBK;

    auto issue = [&](int stage, int kt) {
        if (kt < k_tiles) {
            size_t k0 = (size_t)kt * FBK;
            bf16* base = sm + stage * 4 * FSSZ;
            #pragma unroll
            for (int p = 0; p < 2; p++) {
                int ci = tid + p * 256;
                int row = ci >> 2, c16 = ci & 3;
                int so = row * FLDA + c16 * 8;
                size_t go = (size_t)row * K + k0 + c16 * 8;
                cp16(base + so,            gAh + go);
                cp16(base + FSSZ + so,     gAl + go);
                cp16(base + 2 * FSSZ + so, gBh + go);
                cp16(base + 3 * FSSZ + so, gBl + go);
            }
        }
        asm volatile("cp.async.commit_group;\n" ::);
    };

    #pragma unroll
    for (int s = 0; s < 2; s++) issue(s, s);

    for (int kt = 0; kt < k_tiles; kt++) {
        asm volatile("cp.async.wait_group 1;\n" ::);
        __syncthreads();
        issue((kt + 2) % 3, kt + 2);

        const uint32_t* wAh = (const uint32_t*)(sm + (kt % 3) * 4 * FSSZ);
        const uint32_t* wAl = wAh + FSSZ / 2;
        const uint32_t* wBh = wAh + FSSZ;
        const uint32_t* wBl = wAh + 3 * (FSSZ / 2);

        #pragma unroll
        for (int ks = 0; ks < 2; ks++) {
            int kw = ks * 8;
            uint32_t a_h[4][4], a_l[4][4], b_h[4][2], b_l[4][2];
            #pragma unroll
            for (int i = 0; i < 4; i++) {
                int r0 = (wm + i * 16 + r) * 20 + kw + c;
                int r1 = r0 + 8 * 20;
                a_h[i][0] = wAh[r0];     a_h[i][1] = wAh[r1];
                a_h[i][2] = wAh[r0 + 4]; a_h[i][3] = wAh[r1 + 4];
                a_l[i][0] = wAl[r0];     a_l[i][1] = wAl[r1];
                a_l[i][2] = wAl[r0 + 4]; a_l[i][3] = wAl[r1 + 4];
            }
            #pragma unroll
            for (int j = 0; j < 4; j++) {
                int n0 = (wn + j * 8 + r) * 20 + kw + c;
                b_h[j][0] = wBh[n0]; b_h[j][1] = wBh[n0 + 4];
                b_l[j][0] = wBl[n0]; b_l[j][1] = wBl[n0 + 4];
            }
            #pragma unroll
            for (int i = 0; i < 4; i++)
                #pragma unroll
                for (int j = 0; j < 4; j++) {
                    mma16816(acc[i][j], a_h[i], b_h[j]);
                    mma16816(acc[i][j], a_h[i], b_l[j]);
                    mma16816(acc[i][j], a_l[i], b_h[j]);
                }
        }
        __syncthreads();
    }

    #pragma unroll
    for (int i = 0; i < 4; i++)
        #pragma unroll
        for (int j = 0; j < 4; j++) {
            int row = by * GBM + wm + i * 16 + r;
            int col = bx * GBN + wn + j * 8 + 2 * c;
            *(float2*)(Cc + (size_t)row * N + col) =
                make_float2(acc[i][j][0], acc[i][j][1]);
            *(float2*)(Cc + (size_t)(row + 8) * N + col) =
                make_float2(acc[i][j][2], acc[i][j][3]);
        }
#endif
}

// ---------------------------------------------------------------------------
// tcgen05 flash attention, fixed-max softmax, O resident in TMEM.
// Tiles: 128 q x 64 s, H=128. grid (T/128, 16, 4), 256 threads.
// TMEM cols: O@0(128), Qh@128(64), Ql@192(64), S0@256(64), S1@320(64),
//            Ph@384(32), Pl@416(32)
// smem: [0:8) tmem ptr, [8:16) mbar; stages @1024: Kh,Kl(64x128),Vh,Vl(128x64)
// ---------------------------------------------------------------------------
#define AK_B 16384
#define ASTAGE (4 * AK_B)
#define ATTN_TC_SMEM (1024 + 2 * ASTAGE)
#define IDESC_S  0x8100490u    // M=128, N=64
#define IDESC_PV 0x8200490u    // M=128, N=128

__global__ __launch_bounds__(256) void attn_tc(
    const bf16* __restrict__ qh, const bf16* __restrict__ ql,
    const bf16* __restrict__ kh_, const bf16* __restrict__ kl_,
    const bf16* __restrict__ vth, const bf16* __restrict__ vtl,
    bf16* __restrict__ eh, bf16* __restrict__ el)
{
#if HAS_TCGEN05
    extern __shared__ __align__(1024) char smem[];
    __shared__ float sL[2][128];
    uint32_t sbase = (uint32_t)__cvta_generic_to_shared(smem);
    int tid = threadIdx.x, warp = tid >> 5, lane = tid & 31;
    int b = blockIdx.z, n = blockIdx.y, khd = n >> 2;
    int q0 = blockIdx.x * 128, bT = b * T_;
    const int NT = T_ / 64;   // 32

    if (tid == 0) MBAR_INIT(sbase + 8, 1);
    if (warp == 0) TC_ALLOC(sbase, 512);
    __syncthreads();
    uint32_t tmem;
    asm volatile("ld.shared.b32 %0, [%1];" : "=r"(tmem) : "r"(sbase));

    auto issue_kv = [&](int tile) {
        if (tile < NT) {
            int s0 = tile * 64;
            char* st = smem + 1024 + (tile & 1) * ASTAGE;
            // K hi/lo: 64 rows x 128 cols, blocked 2 atom-cols
            #pragma unroll
            for (int a = 0; a < 2; a++) {
                const bf16* g = (a ? kl_ : kh_);
                char* base = st + a * AK_B;
                #pragma unroll
                for (int it = 0; it < 4; it++) {
                    int idx = tid + it * 256;
                    int s = idx >> 4, ch = idx & 15;
                    uint32_t off = (uint32_t)((s >> 3) * 1024 + (ch >> 3) * 8192
                                            + (s & 7) * 128 + (ch & 7) * 16);
                    off ^= ((off >> 3) & 0x70);
                    cp16(base + off, g + (size_t)(bT + s0 + s) * KH_ + khd * 128 + ch * 8);
                }
            }
            // V^T hi/lo: 128 rows(h) x 64 cols(t)
            #pragma unroll
            for (int a = 0; a < 2; a++) {
                const bf16* g = (a ? vtl : vth);
                char* base = st + 2 * AK_B + a * AK_B;
                #pragma unroll
                for (int it = 0; it < 4; it++) {
                    int idx = tid + it * 256;
                    int h = idx >> 3, tch = idx & 7;
                    uint32_t off = (uint32_t)((h >> 3) * 1024 + (h & 7) * 128 + tch * 16);
                    off ^= ((off >> 3) & 0x70);
                    cp16(base + off,
                         g + ((size_t)(b * 4 + khd) * 128 + h) * T_ + s0 + tch * 8);
                }
            }
        }
        asm volatile("cp.async.commit_group;\n" ::);
    };

    issue_kv(0);

    // Q -> TMEM (warps 0-3, row = tid)
    if (tid < 128) {
        uint32_t woff = (uint32_t)(tid >> 5) << 21;
        uint32_t qr[32];
        const uint4* srcA = (const uint4*)(qh + (size_t)(bT + q0 + tid) * NH_ + n * 128);
        const uint4* srcB = (const uint4*)(ql + (size_t)(bT + q0 + tid) * NH_ + n * 128);
        #pragma unroll
        for (int i = 0; i < 8; i++) {
            uint4 v = srcA[i];
            qr[4*i] = v.x; qr[4*i+1] = v.y; qr[4*i+2] = v.z; qr[4*i+3] = v.w;
        }
        TC_ST_X32(tmem + 128 + woff, qr);
        #pragma unroll
        for (int i = 0; i < 8; i++) {
            uint4 v = srcA[i + 8];
            qr[4*i] = v.x; qr[4*i+1] = v.y; qr[4*i+2] = v.z; qr[4*i+3] = v.w;
        }
        TC_ST_X32(tmem + 160 + woff, qr);
        #pragma unroll
        for (int i = 0; i < 8; i++) {
            uint4 v = srcB[i];
            qr[4*i] = v.x; qr[4*i+1] = v.y; qr[4*i+2] = v.z; qr[4*i+3] = v.w;
        }
        TC_ST_X32(tmem + 192 + woff, qr);
        #pragma unroll
        for (int i = 0; i < 8; i++) {
            uint4 v = srcB[i + 8];
            qr[4*i] = v.x; qr[4*i+1] = v.y; qr[4*i+2] = v.z; qr[4*i+3] = v.w;
        }
        TC_ST_X32(tmem + 224 + woff, qr);
        TC_WAIT_ST();
    }
    TC_FENCE_BEFORE();
    asm volatile("cp.async.wait_group 0;\n" ::);
    __syncthreads();

    // descriptor K-step offsets within K tile (K=16 bf16 per step)
    // steps 0-3: atom col 0; steps 4-7: atom col 1 (+8192B = 512 units)
    if (tid == 0) {
        TC_FENCE_AFTER();
        asm volatile("fence.proxy.async.shared::cta;" ::: "memory");
        uint32_t kb = sbase + 1024;   // stage 0
        uint64_t dKh = make_desc_sw128(kb);
        uint64_t dKl = make_desc_sw128(kb + AK_B);
        #pragma unroll
        for (int ks = 0; ks < 8; ks++) {
            uint64_t koff = (ks < 4) ? (uint64_t)(ks * 2) : (uint64_t)(512 + (ks - 4) * 2);
            uint32_t aH = tmem + 128 + ks * 8, aL = tmem + 192 + ks * 8;
            tc_mma_ts_f16(tmem + 256, aH, dKh + koff, IDESC_S, ks > 0 ? 1u : 0u);
            tc_mma_ts_f16(tmem + 256, aH, dKl + koff, IDESC_S, 1u);
            tc_mma_ts_f16(tmem + 256, aL, dKh + koff, IDESC_S, 1u);
        }
        TC_COMMIT(sbase + 8);
    }

    int chalf = warp >> 2;            // 0: s-cols 0-31, 1: s-cols 32-63
    int row = (warp & 3) * 32 + lane;
    uint32_t woff = (uint32_t)(warp & 3) << 21;
    float li = 0.f;

    for (int t = 0; t < NT; t++) {
        MBAR_WAIT(sbase + 8, (uint32_t)(t & 1));
        TC_FENCE_AFTER();
        issue_kv(t + 1);

        // softmax on S(t)
        uint32_t sr[32];
        TC_LD_X32(sr, tmem + ((t & 1) ? 320 : 256) + chalf * 32);
        TC_WAIT_LD();
        float pv[32];
        float lsum = 0.f;
        #pragma unroll
        for (int i = 0; i < 32; i++) {
            pv[i] = __expf(__uint_as_float(sr[i]));
            lsum += pv[i];
        }
        li += lsum;
        uint32_t ph[16], pl[16];
        #pragma unroll
        for (int j = 0; j < 16; j++) {
            float p0 = pv[2*j], p1 = pv[2*j+1];
            bf16 h0 = __float2bfloat16(p0), h1 = __float2bfloat16(p1);
            __nv_bfloat162 hp = {h0, h1};
            __nv_bfloat162 lp = {__float2bfloat16(p0 - __bfloat162float(h0)),
                                 __float2bfloat16(p1 - __bfloat162float(h1))};
            ph[j] = *(uint32_t*)&hp;
            pl[j] = *(uint32_t*)&lp;
        }
        TC_ST_X16(tmem + 384 + chalf * 16 + woff, ph);
        TC_ST_X16(tmem + 416 + chalf * 16 + woff, pl);
        TC_WAIT_ST();
        TC_FENCE_BEFORE();

        asm volatile("cp.async.wait_group 0;\n" ::);
        __syncthreads();

        if (tid == 0) {
            TC_FENCE_AFTER();
            asm volatile("fence.proxy.async.shared::cta;" ::: "memory");
            // PV(t): A = P in TMEM, B = V^T stage t&1
            uint32_t vb = sbase + 1024 + (uint32_t)(t & 1) * ASTAGE + 2 * AK_B;
            uint64_t dVh = make_desc_sw128(vb);
            uint64_t dVl = make_desc_sw128(vb + AK_B);
            #pragma unroll
            for (int ks = 0; ks < 4; ks++) {
                uint32_t aH = tmem + 384 + ks * 8, aL = tmem + 416 + ks * 8;
                tc_mma_ts_f16(tmem, aH, dVh + ks * 2, IDESC_PV,
                              (t > 0 || ks > 0) ? 1u : 0u);
                tc_mma_ts_f16(tmem, aH, dVl + ks * 2, IDESC_PV, 1u);
                tc_mma_ts_f16(tmem, aL, dVh + ks * 2, IDESC_PV, 1u);
            }
            // S(t+1)
            if (t + 1 < NT) {
                uint32_t kb = sbase + 1024 + (uint32_t)((t + 1) & 1) * ASTAGE;
                uint64_t dKh = make_desc_sw128(kb);
                uint64_t dKl = make_desc_sw128(kb + AK_B);
                uint32_t sdst = tmem + (((t + 1) & 1) ? 320 : 256);
                #pragma unroll
                for (int ks = 0; ks < 8; ks++) {
                    uint64_t koff = (ks < 4) ? (uint64_t)(ks * 2)
                                             : (uint64_t)(512 + (ks - 4) * 2);
                    uint32_t aH = tmem + 128 + ks * 8, aL = tmem + 192 + ks * 8;
                    tc_mma_ts_f16(sdst, aH, dKh + koff, IDESC_S, ks > 0 ? 1u : 0u);
                    tc_mma_ts_f16(sdst, aH, dKl + koff, IDESC_S, 1u);
                    tc_mma_ts_f16(sdst, aL, dKh + koff, IDESC_S, 1u);
                }
            }
            TC_COMMIT(sbase + 8);
        }
    }

    // combine li halves
    sL[chalf][row] = li;
    __syncthreads();
    float inv = 1.f / (sL[0][row] + sL[1][row]);

    // wait last commit (PV(NT-1)); wait index NT -> parity NT&1
    MBAR_WAIT(sbase + 8, (uint32_t)(NT & 1));
    TC_FENCE_AFTER();

    // O readout: warp covers rows (warp&3)*32+lane, cols chalf*64 .. +63
    uint32_t o0[32], o1[32];
    TC_LD_X32(o0, tmem + chalf * 64);
    TC_LD_X32(o1, tmem + chalf * 64 + 32);
    TC_WAIT_LD();

    size_t obase = (size_t)(bT + q0 + row) * NH_ + n * 128 + chalf * 64;
    #pragma unroll
    for (int j = 0; j < 16; j++) {
        float v0 = __uint_as_float(j < 8 ? o0[4*(j&7)]   : o1[4*(j&7)])   * inv;
        float v1 = __uint_as_float(j < 8 ? o0[4*(j&7)+1] : o1[4*(j&7)+1]) * inv;
        float v2 = __uint_as_float(j < 8 ? o0[4*(j&7)+2] : o1[4*(j&7)+2]) * inv;
        float v3 = __uint_as_float(j < 8 ? o0[4*(j&7)+3] : o1[4*(j&7)+3]) * inv;
        bf16 h0 = __float2bfloat16(v0), h1 = __float2bfloat16(v1);
        bf16 h2 = __float2bfloat16(v2), h3 = __float2bfloat16(v3);
        __nv_bfloat162 hp0 = {h0, h1}, hp1 = {h2, h3};
        __nv_bfloat162 lp0 = {__float2bfloat16(v0 - __bfloat162float(h0)),
                              __float2bfloat16(v1 - __bfloat162float(h1))};
        __nv_bfloat162 lp1 = {__float2bfloat16(v2 - __bfloat162float(h2)),
                              __float2bfloat16(v3 - __bfloat162float(h3))};
        int colo = (j & 7) * 4 + (j < 8 ? 0 : 32);
        *(uint2*)(eh + obase + colo) = make_uint2(*(uint32_t*)&hp0, *(uint32_t*)&hp1);
        *(uint2*)(el + obase + colo) = make_uint2(*(uint32_t*)&lp0, *(uint32_t*)&lp1);
    }

    __syncthreads();
    if (warp == 0) {
        TC_RELINQ();
        TC_DEALLOC(tmem, 512);
    }
#endif
}

// ---------------------------------------------------------------------------
// Prep kernels (unchanged)
// ---------------------------------------------------------------------------
__global__ __launch_bounds__(256) void split_f32(
    const float* __restrict__ src, bf16* __restrict__ hi, bf16* __restrict__ lo,
    size_t n4)
{
    size_t i = (size_t)blockIdx.x * blockDim.x + threadIdx.x;
    if (i >= n4) return;
    float4 v = *(const float4*)(src + i * 4);
    bf16 h0 = __float2bfloat16(v.x), h1 = __float2bfloat16(v.y);
    bf16 h2 = __float2bfloat16(v.z), h3 = __float2bfloat16(v.w);
    bf16 l0 = __float2bfloat16(v.x - __bfloat162float(h0));
    bf16 l1 = __float2bfloat16(v.y - __bfloat162float(h1));
    bf16 l2 = __float2bfloat16(v.z - __bfloat162float(h2));
    bf16 l3 = __float2bfloat16(v.w - __bfloat162float(h3));
    __nv_bfloat162 hp0 = {h0, h1}, hp1 = {h2, h3};
    __nv_bfloat162 lp0 = {l0, l1}, lp1 = {l2, l3};
    *(uint2*)(hi + i * 4) = make_uint2(*(unsigned int*)&hp0, *(unsigned int*)&hp1);
    *(uint2*)(lo + i * 4) = make_uint2(*(unsigned int*)&lp0, *(unsigned int*)&lp1);
}

__global__ __launch_bounds__(256) void tsplit(
    const float* __restrict__ W, bf16* __restrict__ hi, bf16* __restrict__ lo,
    int K, int N)
{
    __shared__ float t[32][33];
    int kb = blockIdx.y * 32, nb = blockIdx.x * 32;
    #pragma unroll
    for (int i = 0; i < 4; i++)
        t[threadIdx.y + 8 * i][threadIdx.x] =
            W[(size_t)(kb + threadIdx.y + 8 * i) * N + nb + threadIdx.x];
    __syncthreads();
    #pragma unroll
    for (int i = 0; i < 4; i++) {
        float f = t[threadIdx.x][threadIdx.y + 8 * i];
        bf16 h = __float2bfloat16(f);
        size_t idx = (size_t)(nb + threadIdx.y + 8 * i) * K + kb + threadIdx.x;
        hi[idx] = h;
        lo[idx] = __float2bfloat16(f - __bfloat162float(h));
    }
}

__global__ __launch_bounds__(256) void vtsplit(
    const float* __restrict__ qkv, bf16* __restrict__ hi, bf16* __restrict__ lo)
{
    __shared__ float t[32][33];
    int t0 = blockIdx.x * 32, h0 = blockIdx.y * 32;
    int bz = blockIdx.z;
    int b = bz >> 2, kh = bz & 3;
    #pragma unroll
    for (int i = 0; i < 4; i++)
        t[threadIdx.y + 8 * i][threadIdx.x] =
            qkv[(size_t)(b * T_ + t0 + threadIdx.y + 8 * i) * QKV_ + 2560 + kh * 128 + h0 + threadIdx.x];
    __syncthreads();
    #pragma unroll
    for (int i = 0; i < 4; i++) {
        float f = t[threadIdx.x][threadIdx.y + 8 * i];
        bf16 h = __float2bfloat16(f);
        size_t idx = ((size_t)bz * 128 + h0 + threadIdx.y + 8 * i) * T_ + t0 + threadIdx.x;
        hi[idx] = h;
        lo[idx] = __float2bfloat16(f - __bfloat162float(h));
    }
}

__global__ __launch_bounds__(256) void rms_rope_split(
    const float* __restrict__ in, int inoff,
    bf16* __restrict__ outh, bf16* __restrict__ outl,
    int width, int nheads, float outscale)
{
    int row = blockIdx.x;
    int t = row % T_;
    const float* ptr = in + (size_t)row * QKV_ + inoff;

    float ss = 0.f;
    for (int i = threadIdx.x; i < width; i += 256) {
        float v = ptr[i];
        ss += v * v;
    }
    #pragma unroll
    for (int o = 16; o; o >>= 1) ss += __shfl_xor_sync(0xffffffffu, ss, o);
    __shared__ float red[8];
    if ((threadIdx.x & 31) == 0) red[threadIdx.x >> 5] = ss;
    __syncthreads();
    float tot = red[0] + red[1] + red[2] + red[3] + red[4] + red[5] + red[6] + red[7];
    float rs = rsqrtf(tot / (float)width + 1e-6f) * outscale;

    int npairs = nheads * 64;
    const double TWO_PI = 6.283185307179586476925286766559;
    bf16* oh = outh + (size_t)row * width;
    bf16* ol = outl + (size_t)row * width;
    for (int p = threadIdx.x; p < npairs; p += 256) {
        int head = p >> 6;
        int hp = p & 63;
        float inv = __expf(-(float)hp * (9.210340371976184f / 64.f));
        float theta = (float)t * inv;
        double td = (double)theta * (1.0 / TWO_PI);
        double frac = td - floor(td);
        if (frac > 0.5) frac -= 1.0;
        float redang = (float)(frac * TWO_PI);
        float s, cc;
        sincosf(redang, &s, &cc);

        int base = head * H_;
        float x1 = ptr[base + hp] * rs;
        float x2 = ptr[base + hp + 64] * rs;
        float y1 = x1 * cc - x2 * s;
        float y2 = x2 * cc + x1 * s;
        bf16 h1 = __float2bfloat16(y1), h2 = __float2bfloat16(y2);
        oh[base + hp]      = h1;
        oh[base + hp + 64] = h2;
        ol[base + hp]      = __float2bfloat16(y1 - __bfloat162float(h1));
        ol[base + hp + 64] = __float2bfloat16(y2 - __bfloat162float(h2));
    }
}

// ---------------------------------------------------------------------------
extern "C" void kernel_launch(void* const* d_in, const int* in_sizes, int n_in,
                              void* d_out, int out_size)
{
    const float* x    = (const float*)d_in[0];
    const float* Wq   = (const float*)d_in[1];
    const float* Wk   = (const float*)d_in[2];
    const float* Wv   = (const float*)d_in[3];
    const float* Wout = (const float*)d_in[4];
    float* out = (float*)d_out;

    float* qkv;
    cudaGetSymbolAddress((void**)&qkv, g_qkv);
    bf16 *xh, *xl, *eh, *el, *qsh, *qsl, *ksh, *ksl, *vth, *vtl;
    bf16 *wch, *wcl, *woh, *wol;
    cudaGetSymbolAddress((void**)&xh, g_x_hi);   cudaGetSymbolAddress((void**)&xl, g_x_lo);
    cudaGetSymbolAddress((void**)&eh, g_e_hi);   cudaGetSymbolAddress((void**)&el, g_e_lo);
    cudaGetSymbolAddress((void**)&qsh, g_qh);    cudaGetSymbolAddress((void**)&qsl, g_ql);
    cudaGetSymbolAddress((void**)&ksh, g_kh);    cudaGetSymbolAddress((void**)&ksl, g_kl);
    cudaGetSymbolAddress((void**)&vth, g_vth);   cudaGetSymbolAddress((void**)&vtl, g_vtl);
    cudaGetSymbolAddress((void**)&wch, g_Wc_hi); cudaGetSymbolAddress((void**)&wcl, g_Wc_lo);
    cudaGetSymbolAddress((void**)&woh, g_Wo_hi); cudaGetSymbolAddress((void**)&wol, g_Wo_lo);

    cudaFuncSetAttribute(gemm_dual, cudaFuncAttributeMaxDynamicSharedMemorySize,
                         GEMM_SMEM);
    cudaFuncSetAttribute(attn_tc, cudaFuncAttributeMaxDynamicSharedMemorySize,
                         ATTN_TC_SMEM);

    // operand prep
    split_f32<<<(int)((M_ * (size_t)C_ / 4 + 255) / 256), 256>>>(x, xh, xl, (size_t)M_ * C_ / 4);
    tsplit<<<dim3(NH_ / 32, C_ / 32), dim3(32, 8)>>>(Wq, wch, wcl, C_, NH_);
    tsplit<<<dim3(KH_ / 32, C_ / 32), dim3(32, 8)>>>(
        Wk, wch + (size_t)NH_ * C_, wcl + (size_t)NH_ * C_, C_, KH_);
    tsplit<<<dim3(KH_ / 32, C_ / 32), dim3(32, 8)>>>(
        Wv, wch + (size_t)(NH_ + KH_) * C_, wcl + (size_t)(NH_ + KH_) * C_, C_, KH_);
    tsplit<<<dim3(C_ / 32, NH_ / 32), dim3(32, 8)>>>(Wout, woh, wol, NH_, C_);

    // fused QKV projection (tcgen05)
    gemm_dual<<<dim3(QKV_ / GBN, M_ / GBM), 256, GEMM_SMEM>>>(
        xh, xl, wch, wcl, qkv, M_, QKV_, C_);

    // norm + rope -> split bf16 ; V transpose+split
    rms_rope_split<<<M_, 256>>>(qkv, 0,    qsh, qsl, NH_, NHEADS, 0.08838834764831845f);
    rms_rope_split<<<M_, 256>>>(qkv, 2048, ksh, ksl, KH_, 4, 1.0f);
    vtsplit<<<dim3(T_ / 32, 4, 16), dim3(32, 8)>>>(qkv, vth, vtl);

    // attention (tcgen05, TMEM-resident)
    dim3 gAttn(T_ / 128, NHEADS, B_);
    attn_tc<<<gAttn, 256, ATTN_TC_SMEM>>>(qsh, qsl, ksh, ksl, vth, vtl, eh, el);

    // output projection (tcgen05)
    gemm_dual<<<dim3(C_ / GBN, M_ / GBM), 256, GEMM_SMEM>>>(
        eh, el, woh, wol, out, M_, C_, NH_);
}

// round 8
// speedup vs baseline: 10.0748x; 1.0049x over previous
#include <cuda_runtime.h>
#include <cuda_bf16.h>
#include <cstdint>
#include <math.h>

#define B_ 4
#define T_ 2048
#define C_ 2048
#define NH_ 2048
#define KH_ 512
#define QKV_ 3072      // NH_ + KH_ + KH_
#define NHEADS 16
#define H_ 128
#define M_ (B_*T_)

typedef __nv_bfloat16 bf16;

#if defined(__CUDA_ARCH_FEAT_SM103_ALL) || defined(__CUDA_ARCH_FEAT_SM100_ALL)
#define HAS_TCGEN05 1
#else
#define HAS_TCGEN05 0
#endif

// ---------------------------------------------------------------------------
// Device-global scratch
// ---------------------------------------------------------------------------
__device__ float g_qkv[(size_t)M_ * QKV_];

__device__ bf16 g_x_hi[(size_t)M_ * C_],  g_x_lo[(size_t)M_ * C_];
__device__ bf16 g_e_hi[(size_t)M_ * NH_], g_e_lo[(size_t)M_ * NH_];
__device__ bf16 g_qh[(size_t)M_ * NH_],   g_ql[(size_t)M_ * NH_];
__device__ bf16 g_kh[(size_t)M_ * KH_],   g_kl[(size_t)M_ * KH_];
__device__ bf16 g_vth[(size_t)16 * 128 * T_], g_vtl[(size_t)16 * 128 * T_];
__device__ bf16 g_Wc_hi[(size_t)QKV_ * C_], g_Wc_lo[(size_t)QKV_ * C_];
__device__ bf16 g_Wo_hi[(size_t)C_ * NH_],  g_Wo_lo[(size_t)C_ * NH_];

// ---------------------------------------------------------------------------
// PTX helpers
// ---------------------------------------------------------------------------
__device__ __forceinline__ void cp16(void* dst, const void* src) {
    uint32_t d = (uint32_t)__cvta_generic_to_shared(dst);
    asm volatile("cp.async.cg.shared.global [%0], [%1], 16;\n" :: "r"(d), "l"(src));
}
__device__ __forceinline__ void mma16816(float* d, const uint32_t* a, const uint32_t* b) {
    asm volatile(
        "mma.sync.aligned.m16n8k16.row.col.f32.bf16.bf16.f32 "
        "{%0,%1,%2,%3},{%4,%5,%6,%7},{%8,%9},{%0,%1,%2,%3};\n"
        : "+f"(d[0]), "+f"(d[1]), "+f"(d[2]), "+f"(d[3])
        : "r"(a[0]), "r"(a[1]), "r"(a[2]), "r"(a[3]), "r"(b[0]), "r"(b[1]));
}

#if HAS_TCGEN05
#define MBAR_INIT(addr, cnt) \
    asm volatile("mbarrier.init.shared.b64 [%0], %1;" :: "r"(addr), "r"(cnt) : "memory")
#define MBAR_WAIT(addr, parity) do {                                        \
    asm volatile(                                                            \
        "{\n\t.reg .pred P1;\n\t"                                            \
        "WAIT_LOOP_%=:\n\t"                                                  \
        "mbarrier.try_wait.parity.acquire.cta.shared::cta.b64 P1, [%0], %1, 0x989680;\n\t" \
        "@P1 bra.uni WAIT_DONE_%=;\n\t"                                      \
        "bra.uni WAIT_LOOP_%=;\n\t"                                          \
        "WAIT_DONE_%=:\n\t}"                                                 \
        :: "r"(addr), "r"(parity) : "memory");                               \
} while (0)
#define TC_ALLOC(smem_addr, n) \
    asm volatile("tcgen05.alloc.cta_group::1.sync.aligned.shared::cta.b32 [%0], %1;" \
                 :: "r"(smem_addr), "r"(n) : "memory")
#define TC_DEALLOC(tmem, n) \
    asm volatile("tcgen05.dealloc.cta_group::1.sync.aligned.b32 %0, %1;" :: "r"(tmem), "r"(n))
#define TC_RELINQ() \
    asm volatile("tcgen05.relinquish_alloc_permit.cta_group::1.sync.aligned;")
#define TC_COMMIT(mbar) \
    asm volatile("tcgen05.commit.cta_group::1.mbarrier::arrive::one.shared::cluster.b64 [%0];" \
                 :: "r"(mbar) : "memory")
#define TC_FENCE_AFTER()  asm volatile("tcgen05.fence::after_thread_sync;" ::: "memory")
#define TC_FENCE_BEFORE() asm volatile("tcgen05.fence::before_thread_sync;" ::: "memory")
#define TC_WAIT_LD() asm volatile("tcgen05.wait::ld.sync.aligned;" ::: "memory")
#define TC_WAIT_ST() asm volatile("tcgen05.wait::st.sync.aligned;" ::: "memory")

#define TC_LD_X32(r, addr) \
    asm volatile( \
        "tcgen05.ld.sync.aligned.32x32b.x32.b32 " \
        "{%0, %1, %2, %3, %4, %5, %6, %7, %8, %9, %10, %11, %12, %13, %14, %15, " \
        " %16, %17, %18, %19, %20, %21, %22, %23, %24, %25, %26, %27, %28, %29, %30, %31}, [%32];" \
        : "=r"((r)[0]),  "=r"((r)[1]),  "=r"((r)[2]),  "=r"((r)[3]), \
          "=r"((r)[4]),  "=r"((r)[5]),  "=r"((r)[6]),  "=r"((r)[7]), \
          "=r"((r)[8]),  "=r"((r)[9]),  "=r"((r)[10]), "=r"((r)[11]), \
          "=r"((r)[12]), "=r"((r)[13]), "=r"((r)[14]), "=r"((r)[15]), \
          "=r"((r)[16]), "=r"((r)[17]), "=r"((r)[18]), "=r"((r)[19]), \
          "=r"((r)[20]), "=r"((r)[21]), "=r"((r)[22]), "=r"((r)[23]), \
          "=r"((r)[24]), "=r"((r)[25]), "=r"((r)[26]), "=r"((r)[27]), \
          "=r"((r)[28]), "=r"((r)[29]), "=r"((r)[30]), "=r"((r)[31]) \
        : "r"(addr))

#define TC_ST_X32(addr, r) \
    asm volatile( \
        "tcgen05.st.sync.aligned.32x32b.x32.b32 [%0], " \
        "{%1, %2, %3, %4, %5, %6, %7, %8, %9, %10, %11, %12, %13, %14, %15, %16, " \
        " %17, %18, %19, %20, %21, %22, %23, %24, %25, %26, %27, %28, %29, %30, %31, %32};" \
        :: "r"(addr), \
           "r"((r)[0]),  "r"((r)[1]),  "r"((r)[2]),  "r"((r)[3]), \
           "r"((r)[4]),  "r"((r)[5]),  "r"((r)[6]),  "r"((r)[7]), \
           "r"((r)[8]),  "r"((r)[9]),  "r"((r)[10]), "r"((r)[11]), \
           "r"((r)[12]), "r"((r)[13]), "r"((r)[14]), "r"((r)[15]), \
           "r"((r)[16]), "r"((r)[17]), "r"((r)[18]), "r"((r)[19]), \
           "r"((r)[20]), "r"((r)[21]), "r"((r)[22]), "r"((r)[23]), \
           "r"((r)[24]), "r"((r)[25]), "r"((r)[26]), "r"((r)[27]), \
           "r"((r)[28]), "r"((r)[29]), "r"((r)[30]), "r"((r)[31]) \
        : "memory")

#define TC_ST_X16(addr, r) \
    asm volatile( \
        "tcgen05.st.sync.aligned.32x32b.x16.b32 [%0], " \
        "{%1, %2, %3, %4, %5, %6, %7, %8, %9, %10, %11, %12, %13, %14, %15, %16};" \
        :: "r"(addr), \
           "r"((r)[0]),  "r"((r)[1]),  "r"((r)[2]),  "r"((r)[3]), \
           "r"((r)[4]),  "r"((r)[5]),  "r"((r)[6]),  "r"((r)[7]), \
           "r"((r)[8]),  "r"((r)[9]),  "r"((r)[10]), "r"((r)[11]), \
           "r"((r)[12]), "r"((r)[13]), "r"((r)[14]), "r"((r)[15]) \
        : "memory")

__device__ __forceinline__ void tc_mma_ss_f16(
    uint32_t d_tmem, uint64_t a_desc, uint64_t b_desc, uint32_t idesc, uint32_t en)
{
    asm volatile(
        "{\n\t.reg .pred p;\n\t"
        "setp.ne.u32 p, %4, 0;\n\t"
        "tcgen05.mma.cta_group::1.kind::f16 [%0], %1, %2, %3, {%5, %5, %5, %5}, p;\n\t"
        "}"
        :: "r"(d_tmem), "l"(a_desc), "l"(b_desc), "r"(idesc), "r"(en), "r"(0u)
        : "memory");
}
__device__ __forceinline__ void tc_mma_ts_f16(
    uint32_t d_tmem, uint32_t a_tmem, uint64_t b_desc, uint32_t idesc, uint32_t en)
{
    asm volatile(
        "{\n\t.reg .pred p;\n\t"
        "setp.ne.u32 p, %4, 0;\n\t"
        "tcgen05.mma.cta_group::1.kind::f16 [%0], [%1], %2, %3, {%5, %5, %5, %5}, p;\n\t"
        "}"
        :: "r"(d_tmem), "r"(a_tmem), "l"(b_desc), "r"(idesc), "r"(en), "r"(0u)
        : "memory");
}
__device__ __forceinline__ uint64_t make_desc_sw128(uint32_t smem_addr) {
    return ((uint64_t)2 << 61) | ((uint64_t)1 << 46) | ((uint64_t)64 << 32)
         | ((uint64_t)1 << 16) | ((uint64_t)(smem_addr >> 4) & 0x3FFF);
}
#endif

// ---------------------------------------------------------------------------
// Dual-path GEMM (unchanged from R6, passing): C = A * Bt^T, split bf16
// ---------------------------------------------------------------------------
#define GBM 128
#define GBN 128
#define TBK 64
#define ST_OP 16384
#define TSTAGE (4 * ST_OP)
#define FBK 32
#define FLDA 40
#define FSSZ (128 * FLDA)
#define GEMM_SMEM 132096
#define GEMM_IDESC 0x8200490u

__global__ __launch_bounds__(256) void gemm_dual(
    const bf16* __restrict__ Ah, const bf16* __restrict__ Al,
    const bf16* __restrict__ Bh, const bf16* __restrict__ Bl,
    float* __restrict__ Cc, int M, int N, int K)
{
#if HAS_TCGEN05
    extern __shared__ __align__(1024) char smem[];
    uint32_t sbase = (uint32_t)__cvta_generic_to_shared(smem);
    int tid = threadIdx.x, warp = tid >> 5, lane = tid & 31;
    int bx = blockIdx.x, by = blockIdx.y;
    const int ktiles = K / TBK;

    if (tid == 0) {
        MBAR_INIT(sbase + 16, 1);
        MBAR_INIT(sbase + 24, 1);
    }
    if (warp == 0) TC_ALLOC(sbase, 128);
    __syncthreads();
    uint32_t tmem;
    asm volatile("ld.shared.b32 %0, [%1];" : "=r"(tmem) : "r"(sbase));

    char* stage0 = smem + 1024;

    auto issue = [&](int kt) {
        if (kt < ktiles) {
            char* st = stage0 + (kt & 1) * TSTAGE;
            size_t k0 = (size_t)kt * TBK;
            const bf16* gsrc[4] = {
                Ah + (size_t)(by * GBM) * K + k0,
                Al + (size_t)(by * GBM) * K + k0,
                Bh + (size_t)(bx * GBN) * K + k0,
                Bl + (size_t)(bx * GBN) * K + k0 };
            #pragma unroll
            for (int a = 0; a < 4; a++) {
                char* base = st + a * ST_OP;
                #pragma unroll
                for (int it = 0; it < 4; it++) {
                    int idx = tid + it * 256;
                    int row = idx >> 3, ch = idx & 7;
                    uint32_t off = (uint32_t)((row >> 3) * 1024 + (row & 7) * 128 + ch * 16);
                    off ^= ((off >> 3) & 0x70);
                    cp16(base + off, gsrc[a] + (size_t)row * K + ch * 8);
                }
            }
        }
        asm volatile("cp.async.commit_group;\n" ::);
    };

    issue(0);

    for (int kt = 0; kt < ktiles; kt++) {
        if (kt >= 1) {
            uint32_t mb = sbase + 16 + ((kt - 1) & 1) * 8;
            MBAR_WAIT(mb, ((kt - 1) >> 1) & 1);
        }
        issue(kt + 1);
        asm volatile("cp.async.wait_group 1;\n" ::);
        __syncthreads();

        if (tid == 0) {
            asm volatile("fence.proxy.async.shared::cta;" ::: "memory");
            char* st = stage0 + (kt & 1) * TSTAGE;
            uint32_t a0 = (uint32_t)__cvta_generic_to_shared(st);
            uint64_t dAh = make_desc_sw128(a0);
            uint64_t dAl = make_desc_sw128(a0 + ST_OP);
            uint64_t dBh = make_desc_sw128(a0 + 2 * ST_OP);
            uint64_t dBl = make_desc_sw128(a0 + 3 * ST_OP);
            #pragma unroll
            for (int ks = 0; ks < 4; ks++) {
                tc_mma_ss_f16(tmem, dAh + ks * 2, dBh + ks * 2, GEMM_IDESC,
                              (kt > 0 || ks > 0) ? 1u : 0u);
                tc_mma_ss_f16(tmem, dAh + ks * 2, dBl + ks * 2, GEMM_IDESC, 1u);
                tc_mma_ss_f16(tmem, dAl + ks * 2, dBh + ks * 2, GEMM_IDESC, 1u);
            }
            TC_COMMIT(sbase + 16 + (kt & 1) * 8);
        }
    }

    {
        uint32_t mb = sbase + 16 + ((ktiles - 1) & 1) * 8;
        MBAR_WAIT(mb, ((ktiles - 1) >> 1) & 1);
    }
    TC_FENCE_AFTER();

    int sp = warp & 3, chf = warp >> 2;
    #pragma unroll
    for (int cc = 0; cc < 2; cc++) {
        uint32_t dr[32];
        TC_LD_X32(dr, tmem + chf * 64 + cc * 32);
        TC_WAIT_LD();
        int row = by * GBM + sp * 32 + lane;
        int col = bx * GBN + chf * 64 + cc * 32;
        float* o = Cc + (size_t)row * N + col;
        #pragma unroll
        for (int q = 0; q < 8; q++)
            *(float4*)(o + q * 4) = make_float4(
                __uint_as_float(dr[4 * q]),     __uint_as_float(dr[4 * q + 1]),
                __uint_as_float(dr[4 * q + 2]), __uint_as_float(dr[4 * q + 3]));
    }
    __syncthreads();
    if (warp == 0) {
        TC_RELINQ();
        TC_DEALLOC(tmem, 128);
    }
#else
    // mma.sync fallback (PTX pass only; runtime uses sm_103a cubin)
    extern __shared__ bf16 sm[];
    int tid = threadIdx.x;
    int bx = blockIdx.x, by = blockIdx.y;
    int warp = tid >> 5, lane = tid & 31;
    int wm = (warp >> 2) * 64, wn = (warp & 3) * 32;
    int r = lane >> 2, c = lane & 3;

    const bf16* gAh = Ah + (size_t)(by * GBM) * K;
    const bf16* gAl = Al + (size_t)(by * GBM) * K;
    const bf16* gBh = Bh + (size_t)(bx * GBN) * K;
    const bf16* gBl = Bl + (size_t)(bx * GBN) * K;

    float acc[4][4][4];
    #pragma unroll
    for (int i = 0; i < 4; i++)
        #pragma unroll
        for (int j = 0; j < 4; j++)
            #pragma unroll
            for (int e = 0; e < 4; e++) acc[i][j][e] = 0.f;

    const int k_tiles = K / FBK;

    auto issue = [&](int stage, int kt) {
        if (kt < k_tiles) {
            size_t k0 = (size_t)kt * FBK;
            bf16* base = sm + stage * 4 * FSSZ;
            #pragma unroll
            for (int p = 0; p < 2; p++) {
                int ci = tid + p * 256;
                int row = ci >> 2, c16 = ci & 3;
                int so = row * FLDA + c16 * 8;
                size_t go = (size_t)row * K + k0 + c16 * 8;
                cp16(base + so,            gAh + go);
                cp16(base + FSSZ + so,     gAl + go);
                cp16(base + 2 * FSSZ + so, gBh + go);
                cp16(base + 3 * FSSZ + so, gBl + go);
            }
        }
        asm volatile("cp.async.commit_group;\n" ::);
    };

    #pragma unroll
    for (int s = 0; s < 2; s++) issue(s, s);

    for (int kt = 0; kt < k_tiles; kt++) {
        asm volatile("cp.async.wait_group 1;\n" ::);
        __syncthreads();
        issue((kt + 2) % 3, kt + 2);

        const uint32_t* wAh = (const uint32_t*)(sm + (kt % 3) * 4 * FSSZ);
        const uint32_t* wAl = wAh + FSSZ / 2;
        const uint32_t* wBh = wAh + FSSZ;
        const uint32_t* wBl = wAh + 3 * (FSSZ / 2);

        #pragma unroll
        for (int ks = 0; ks < 2; ks++) {
            int kw = ks * 8;
            uint32_t a_h[4][4], a_l[4][4], b_h[4][2], b_l[4][2];
            #pragma unroll
            for (int i = 0; i < 4; i++) {
                int r0 = (wm + i * 16 + r) * 20 + kw + c;
                int r1 = r0 + 8 * 20;
                a_h[i][0] = wAh[r0];     a_h[i][1] = wAh[r1];
                a_h[i][2] = wAh[r0 + 4]; a_h[i][3] = wAh[r1 + 4];
                a_l[i][0] = wAl[r0];     a_l[i][1] = wAl[r1];
                a_l[i][2] = wAl[r0 + 4]; a_l[i][3] = wAl[r1 + 4];
            }
            #pragma unroll
            for (int j = 0; j < 4; j++) {
                int n0 = (wn + j * 8 + r) * 20 + kw + c;
                b_h[j][0] = wBh[n0]; b_h[j][1] = wBh[n0 + 4];
                b_l[j][0] = wBl[n0]; b_l[j][1] = wBl[n0 + 4];
            }
            #pragma unroll
            for (int i = 0; i < 4; i++)
                #pragma unroll
                for (int j = 0; j < 4; j++) {
                    mma16816(acc[i][j], a_h[i], b_h[j]);
                    mma16816(acc[i][j], a_h[i], b_l[j]);
                    mma16816(acc[i][j], a_l[i], b_h[j]);
                }
        }
        __syncthreads();
    }

    #pragma unroll
    for (int i = 0; i < 4; i++)
        #pragma unroll
        for (int j = 0; j < 4; j++) {
            int row = by * GBM + wm + i * 16 + r;
            int col = bx * GBN + wn + j * 8 + 2 * c;
            *(float2*)(Cc + (size_t)row * N + col) =
                make_float2(acc[i][j][0], acc[i][j][1]);
            *(float2*)(Cc + (size_t)(row + 8) * N + col) =
                make_float2(acc[i][j][2], acc[i][j][3]);
        }
#endif
}

// ---------------------------------------------------------------------------
// tcgen05 flash attention, fixed-max softmax, O resident in TMEM.
// Tiles: 128 q x 64 s, H=128. grid (T/128, 16, 4), 256 threads.
// TMEM cols: O@0(128), Qh@128(64), Ql@192(64), S0@256(64), S1@320(64),
//            Ph@384(32), Pl@416(32)
// smem: [0:8) tmem ptr, [8:16) mbar; stages @1024: Kh,Kl(64x128),Vh,Vl(128x64)
// ---------------------------------------------------------------------------
#define AK_B 16384
#define ASTAGE (4 * AK_B)
#define ATTN_TC_SMEM (1024 + 2 * ASTAGE)
#define IDESC_S  0x8100490u    // M=128, N=64
#define IDESC_PV 0x8200490u    // M=128, N=128

__global__ __launch_bounds__(256) void attn_tc(
    const bf16* __restrict__ qh, const bf16* __restrict__ ql,
    const bf16* __restrict__ kh_, const bf16* __restrict__ kl_,
    const bf16* __restrict__ vth, const bf16* __restrict__ vtl,
    bf16* __restrict__ eh, bf16* __restrict__ el)
{
#if HAS_TCGEN05
    extern __shared__ __align__(1024) char smem[];
    __shared__ float sL[2][128];
    uint32_t sbase = (uint32_t)__cvta_generic_to_shared(smem);
    int tid = threadIdx.x, warp = tid >> 5, lane = tid & 31;
    int b = blockIdx.z, n = blockIdx.y, khd = n >> 2;
    int q0 = blockIdx.x * 128, bT = b * T_;
    const int NT = T_ / 64;   // 32

    if (tid == 0) MBAR_INIT(sbase + 8, 1);
    if (warp == 0) TC_ALLOC(sbase, 512);
    __syncthreads();
    uint32_t tmem;
    asm volatile("ld.shared.b32 %0, [%1];" : "=r"(tmem) : "r"(sbase));

    auto issue_kv = [&](int tile) {
        if (tile < NT) {
            int s0 = tile * 64;
            char* st = smem + 1024 + (tile & 1) * ASTAGE;
            // K hi/lo: 64 rows x 128 cols, blocked 2 atom-cols
            #pragma unroll
            for (int a = 0; a < 2; a++) {
                const bf16* g = (a ? kl_ : kh_);
                char* base = st + a * AK_B;
                #pragma unroll
                for (int it = 0; it < 4; it++) {
                    int idx = tid + it * 256;
                    int s = idx >> 4, ch = idx & 15;
                    uint32_t off = (uint32_t)((s >> 3) * 1024 + (ch >> 3) * 8192
                                            + (s & 7) * 128 + (ch & 7) * 16);
                    off ^= ((off >> 3) & 0x70);
                    cp16(base + off, g + (size_t)(bT + s0 + s) * KH_ + khd * 128 + ch * 8);
                }
            }
            // V^T hi/lo: 128 rows(h) x 64 cols(t)
            #pragma unroll
            for (int a = 0; a < 2; a++) {
                const bf16* g = (a ? vtl : vth);
                char* base = st + 2 * AK_B + a * AK_B;
                #pragma unroll
                for (int it = 0; it < 4; it++) {
                    int idx = tid + it * 256;
                    int h = idx >> 3, tch = idx & 7;
                    uint32_t off = (uint32_t)((h >> 3) * 1024 + (h & 7) * 128 + tch * 16);
                    off ^= ((off >> 3) & 0x70);
                    cp16(base + off,
                         g + ((size_t)(b * 4 + khd) * 128 + h) * T_ + s0 + tch * 8);
                }
            }
        }
        asm volatile("cp.async.commit_group;\n" ::);
    };

    issue_kv(0);

    // Q -> TMEM (warps 0-3, row = tid)
    if (tid < 128) {
        uint32_t woff = (uint32_t)(tid >> 5) << 21;
        uint32_t qr[32];
        const uint4* srcA = (const uint4*)(qh + (size_t)(bT + q0 + tid) * NH_ + n * 128);
        const uint4* srcB = (const uint4*)(ql + (size_t)(bT + q0 + tid) * NH_ + n * 128);
        #pragma unroll
        for (int i = 0; i < 8; i++) {
            uint4 v = srcA[i];
            qr[4*i] = v.x; qr[4*i+1] = v.y; qr[4*i+2] = v.z; qr[4*i+3] = v.w;
        }
        TC_ST_X32(tmem + 128 + woff, qr);
        #pragma unroll
        for (int i = 0; i < 8; i++) {
            uint4 v = srcA[i + 8];
            qr[4*i] = v.x; qr[4*i+1] = v.y; qr[4*i+2] = v.z; qr[4*i+3] = v.w;
        }
        TC_ST_X32(tmem + 160 + woff, qr);
        #pragma unroll
        for (int i = 0; i < 8; i++) {
            uint4 v = srcB[i];
            qr[4*i] = v.x; qr[4*i+1] = v.y; qr[4*i+2] = v.z; qr[4*i+3] = v.w;
        }
        TC_ST_X32(tmem + 192 + woff, qr);
        #pragma unroll
        for (int i = 0; i < 8; i++) {
            uint4 v = srcB[i + 8];
            qr[4*i] = v.x; qr[4*i+1] = v.y; qr[4*i+2] = v.z; qr[4*i+3] = v.w;
        }
        TC_ST_X32(tmem + 224 + woff, qr);
        TC_WAIT_ST();
    }
    TC_FENCE_BEFORE();
    asm volatile("cp.async.wait_group 0;\n" ::);
    __syncthreads();

    // descriptor K-step offsets within K tile (K=16 bf16 per step)
    // steps 0-3: atom col 0; steps 4-7: atom col 1 (+8192B = 512 units)
    if (tid == 0) {
        TC_FENCE_AFTER();
        asm volatile("fence.proxy.async.shared::cta;" ::: "memory");
        uint32_t kb = sbase + 1024;   // stage 0
        uint64_t dKh = make_desc_sw128(kb);
        uint64_t dKl = make_desc_sw128(kb + AK_B);
        #pragma unroll
        for (int ks = 0; ks < 8; ks++) {
            uint64_t koff = (ks < 4) ? (uint64_t)(ks * 2) : (uint64_t)(512 + (ks - 4) * 2);
            uint32_t aH = tmem + 128 + ks * 8, aL = tmem + 192 + ks * 8;
            tc_mma_ts_f16(tmem + 256, aH, dKh + koff, IDESC_S, ks > 0 ? 1u : 0u);
            tc_mma_ts_f16(tmem + 256, aH, dKl + koff, IDESC_S, 1u);
            tc_mma_ts_f16(tmem + 256, aL, dKh + koff, IDESC_S, 1u);
        }
        TC_COMMIT(sbase + 8);
    }

    int chalf = warp >> 2;            // 0: s-cols 0-31, 1: s-cols 32-63
    int row = (warp & 3) * 32 + lane;
    uint32_t woff = (uint32_t)(warp & 3) << 21;
    float li = 0.f;

    for (int t = 0; t < NT; t++) {
        MBAR_WAIT(sbase + 8, (uint32_t)(t & 1));
        TC_FENCE_AFTER();
        issue_kv(t + 1);

        // softmax on S(t)
        uint32_t sr[32];
        TC_LD_X32(sr, tmem + ((t & 1) ? 320 : 256) + chalf * 32);
        TC_WAIT_LD();
        float pv[32];
        float lsum = 0.f;
        #pragma unroll
        for (int i = 0; i < 32; i++) {
            pv[i] = __expf(__uint_as_float(sr[i]));
            lsum += pv[i];
        }
        li += lsum;
        uint32_t ph[16], pl[16];
        #pragma unroll
        for (int j = 0; j < 16; j++) {
            float p0 = pv[2*j], p1 = pv[2*j+1];
            bf16 h0 = __float2bfloat16(p0), h1 = __float2bfloat16(p1);
            __nv_bfloat162 hp = {h0, h1};
            __nv_bfloat162 lp = {__float2bfloat16(p0 - __bfloat162float(h0)),
                                 __float2bfloat16(p1 - __bfloat162float(h1))};
            ph[j] = *(uint32_t*)&hp;
            pl[j] = *(uint32_t*)&lp;
        }
        TC_ST_X16(tmem + 384 + chalf * 16 + woff, ph);
        TC_ST_X16(tmem + 416 + chalf * 16 + woff, pl);
        TC_WAIT_ST();
        TC_FENCE_BEFORE();

        asm volatile("cp.async.wait_group 0;\n" ::);
        __syncthreads();

        if (tid == 0) {
            TC_FENCE_AFTER();
            asm volatile("fence.proxy.async.shared::cta;" ::: "memory");
            // PV(t): A = P in TMEM, B = V^T stage t&1
            uint32_t vb = sbase + 1024 + (uint32_t)(t & 1) * ASTAGE + 2 * AK_B;
            uint64_t dVh = make_desc_sw128(vb);
            uint64_t dVl = make_desc_sw128(vb + AK_B);
            #pragma unroll
            for (int ks = 0; ks < 4; ks++) {
                uint32_t aH = tmem + 384 + ks * 8, aL = tmem + 416 + ks * 8;
                tc_mma_ts_f16(tmem, aH, dVh + ks * 2, IDESC_PV,
                              (t > 0 || ks > 0) ? 1u : 0u);
                tc_mma_ts_f16(tmem, aH, dVl + ks * 2, IDESC_PV, 1u);
                tc_mma_ts_f16(tmem, aL, dVh + ks * 2, IDESC_PV, 1u);
            }
            // S(t+1)
            if (t + 1 < NT) {
                uint32_t kb = sbase + 1024 + (uint32_t)((t + 1) & 1) * ASTAGE;
                uint64_t dKh = make_desc_sw128(kb);
                uint64_t dKl = make_desc_sw128(kb + AK_B);
                uint32_t sdst = tmem + (((t + 1) & 1) ? 320 : 256);
                #pragma unroll
                for (int ks = 0; ks < 8; ks++) {
                    uint64_t koff = (ks < 4) ? (uint64_t)(ks * 2)
                                             : (uint64_t)(512 + (ks - 4) * 2);
                    uint32_t aH = tmem + 128 + ks * 8, aL = tmem + 192 + ks * 8;
                    tc_mma_ts_f16(sdst, aH, dKh + koff, IDESC_S, ks > 0 ? 1u : 0u);
                    tc_mma_ts_f16(sdst, aH, dKl + koff, IDESC_S, 1u);
                    tc_mma_ts_f16(sdst, aL, dKh + koff, IDESC_S, 1u);
                }
            }
            TC_COMMIT(sbase + 8);
        }
    }

    // combine li halves
    sL[chalf][row] = li;
    __syncthreads();
    float inv = 1.f / (sL[0][row] + sL[1][row]);

    // wait last commit (PV(NT-1)); wait index NT -> parity NT&1
    MBAR_WAIT(sbase + 8, (uint32_t)(NT & 1));
    TC_FENCE_AFTER();

    // O readout: warp covers rows (warp&3)*32+lane, cols chalf*64 .. +63
    uint32_t o0[32], o1[32];
    TC_LD_X32(o0, tmem + chalf * 64);
    TC_LD_X32(o1, tmem + chalf * 64 + 32);
    TC_WAIT_LD();

    size_t obase = (size_t)(bT + q0 + row) * NH_ + n * 128 + chalf * 64;
    #pragma unroll
    for (int j = 0; j < 16; j++) {
        float v0 = __uint_as_float(j < 8 ? o0[4*(j&7)]   : o1[4*(j&7)])   * inv;
        float v1 = __uint_as_float(j < 8 ? o0[4*(j&7)+1] : o1[4*(j&7)+1]) * inv;
        float v2 = __uint_as_float(j < 8 ? o0[4*(j&7)+2] : o1[4*(j&7)+2]) * inv;
        float v3 = __uint_as_float(j < 8 ? o0[4*(j&7)+3] : o1[4*(j&7)+3]) * inv;
        bf16 h0 = __float2bfloat16(v0), h1 = __float2bfloat16(v1);
        bf16 h2 = __float2bfloat16(v2), h3 = __float2bfloat16(v3);
        __nv_bfloat162 hp0 = {h0, h1}, hp1 = {h2, h3};
        __nv_bfloat162 lp0 = {__float2bfloat16(v0 - __bfloat162float(h0)),
                              __float2bfloat16(v1 - __bfloat162float(h1))};
        __nv_bfloat162 lp1 = {__float2bfloat16(v2 - __bfloat162float(h2)),
                              __float2bfloat16(v3 - __bfloat162float(h3))};
        int colo = (j & 7) * 4 + (j < 8 ? 0 : 32);
        *(uint2*)(eh + obase + colo) = make_uint2(*(uint32_t*)&hp0, *(uint32_t*)&hp1);
        *(uint2*)(el + obase + colo) = make_uint2(*(uint32_t*)&lp0, *(uint32_t*)&lp1);
    }

    __syncthreads();
    if (warp == 0) {
        TC_RELINQ();
        TC_DEALLOC(tmem, 512);
    }
#endif
}

// ---------------------------------------------------------------------------
// Prep kernels (unchanged)
// ---------------------------------------------------------------------------
__global__ __launch_bounds__(256) void split_f32(
    const float* __restrict__ src, bf16* __restrict__ hi, bf16* __restrict__ lo,
    size_t n4)
{
    size_t i = (size_t)blockIdx.x * blockDim.x + threadIdx.x;
    if (i >= n4) return;
    float4 v = *(const float4*)(src + i * 4);
    bf16 h0 = __float2bfloat16(v.x), h1 = __float2bfloat16(v.y);
    bf16 h2 = __float2bfloat16(v.z), h3 = __float2bfloat16(v.w);
    bf16 l0 = __float2bfloat16(v.x - __bfloat162float(h0));
    bf16 l1 = __float2bfloat16(v.y - __bfloat162float(h1));
    bf16 l2 = __float2bfloat16(v.z - __bfloat162float(h2));
    bf16 l3 = __float2bfloat16(v.w - __bfloat162float(h3));
    __nv_bfloat162 hp0 = {h0, h1}, hp1 = {h2, h3};
    __nv_bfloat162 lp0 = {l0, l1}, lp1 = {l2, l3};
    *(uint2*)(hi + i * 4) = make_uint2(*(unsigned int*)&hp0, *(unsigned int*)&hp1);
    *(uint2*)(lo + i * 4) = make_uint2(*(unsigned int*)&lp0, *(unsigned int*)&lp1);
}

__global__ __launch_bounds__(256) void tsplit(
    const float* __restrict__ W, bf16* __restrict__ hi, bf16* __restrict__ lo,
    int K, int N)
{
    __shared__ float t[32][33];
    int kb = blockIdx.y * 32, nb = blockIdx.x * 32;
    #pragma unroll
    for (int i = 0; i < 4; i++)
        t[threadIdx.y + 8 * i][threadIdx.x] =
            W[(size_t)(kb + threadIdx.y + 8 * i) * N + nb + threadIdx.x];
    __syncthreads();
    #pragma unroll
    for (int i = 0; i < 4; i++) {
        float f = t[threadIdx.x][threadIdx.y + 8 * i];
        bf16 h = __float2bfloat16(f);
        size_t idx = (size_t)(nb + threadIdx.y + 8 * i) * K + kb + threadIdx.x;
        hi[idx] = h;
        lo[idx] = __float2bfloat16(f - __bfloat162float(h));
    }
}

__global__ __launch_bounds__(256) void vtsplit(
    const float* __restrict__ qkv, bf16* __restrict__ hi, bf16* __restrict__ lo)
{
    __shared__ float t[32][33];
    int t0 = blockIdx.x * 32, h0 = blockIdx.y * 32;
    int bz = blockIdx.z;
    int b = bz >> 2, kh = bz & 3;
    #pragma unroll
    for (int i = 0; i < 4; i++)
        t[threadIdx.y + 8 * i][threadIdx.x] =
            qkv[(size_t)(b * T_ + t0 + threadIdx.y + 8 * i) * QKV_ + 2560 + kh * 128 + h0 + threadIdx.x];
    __syncthreads();
    #pragma unroll
    for (int i = 0; i < 4; i++) {
        float f = t[threadIdx.x][threadIdx.y + 8 * i];
        bf16 h = __float2bfloat16(f);
        size_t idx = ((size_t)bz * 128 + h0 + threadIdx.y + 8 * i) * T_ + t0 + threadIdx.x;
        hi[idx] = h;
        lo[idx] = __float2bfloat16(f - __bfloat162float(h));
    }
}

__global__ __launch_bounds__(256) void rms_rope_split(
    const float* __restrict__ in, int inoff,
    bf16* __restrict__ outh, bf16* __restrict__ outl,
    int width, int nheads, float outscale)
{
    int row = blockIdx.x;
    int t = row % T_;
    const float* ptr = in + (size_t)row * QKV_ + inoff;

    float ss = 0.f;
    for (int i = threadIdx.x; i < width; i += 256) {
        float v = ptr[i];
        ss += v * v;
    }
    #pragma unroll
    for (int o = 16; o; o >>= 1) ss += __shfl_xor_sync(0xffffffffu, ss, o);
    __shared__ float red[8];
    if ((threadIdx.x & 31) == 0) red[threadIdx.x >> 5] = ss;
    __syncthreads();
    float tot = red[0] + red[1] + red[2] + red[3] + red[4] + red[5] + red[6] + red[7];
    float rs = rsqrtf(tot / (float)width + 1e-6f) * outscale;

    int npairs = nheads * 64;
    const double TWO_PI = 6.283185307179586476925286766559;
    bf16* oh = outh + (size_t)row * width;
    bf16* ol = outl + (size_t)row * width;
    for (int p = threadIdx.x; p < npairs; p += 256) {
        int head = p >> 6;
        int hp = p & 63;
        float inv = __expf(-(float)hp * (9.210340371976184f / 64.f));
        float theta = (float)t * inv;
        double td = (double)theta * (1.0 / TWO_PI);
        double frac = td - floor(td);
        if (frac > 0.5) frac -= 1.0;
        float redang = (float)(frac * TWO_PI);
        float s, cc;
        sincosf(redang, &s, &cc);

        int base = head * H_;
        float x1 = ptr[base + hp] * rs;
        float x2 = ptr[base + hp + 64] * rs;
        float y1 = x1 * cc - x2 * s;
        float y2 = x2 * cc + x1 * s;
        bf16 h1 = __float2bfloat16(y1), h2 = __float2bfloat16(y2);
        oh[base + hp]      = h1;
        oh[base + hp + 64] = h2;
        ol[base + hp]      = __float2bfloat16(y1 - __bfloat162float(h1));
        ol[base + hp + 64] = __float2bfloat16(y2 - __bfloat162float(h2));
    }
}

// ---------------------------------------------------------------------------
extern "C" void kernel_launch(void* const* d_in, const int* in_sizes, int n_in,
                              void* d_out, int out_size)
{
    const float* x    = (const float*)d_in[0];
    const float* Wq   = (const float*)d_in[1];
    const float* Wk   = (const float*)d_in[2];
    const float* Wv   = (const float*)d_in[3];
    const float* Wout = (const float*)d_in[4];
    float* out = (float*)d_out;

    float* qkv;
    cudaGetSymbolAddress((void**)&qkv, g_qkv);
    bf16 *xh, *xl, *eh, *el, *qsh, *qsl, *ksh, *ksl, *vth, *vtl;
    bf16 *wch, *wcl, *woh, *wol;
    cudaGetSymbolAddress((void**)&xh, g_x_hi);   cudaGetSymbolAddress((void**)&xl, g_x_lo);
    cudaGetSymbolAddress((void**)&eh, g_e_hi);   cudaGetSymbolAddress((void**)&el, g_e_lo);
    cudaGetSymbolAddress((void**)&qsh, g_qh);    cudaGetSymbolAddress((void**)&qsl, g_ql);
    cudaGetSymbolAddress((void**)&ksh, g_kh);    cudaGetSymbolAddress((void**)&ksl, g_kl);
    cudaGetSymbolAddress((void**)&vth, g_vth);   cudaGetSymbolAddress((void**)&vtl, g_vtl);
    cudaGetSymbolAddress((void**)&wch, g_Wc_hi); cudaGetSymbolAddress((void**)&wcl, g_Wc_lo);
    cudaGetSymbolAddress((void**)&woh, g_Wo_hi); cudaGetSymbolAddress((void**)&wol, g_Wo_lo);

    cudaFuncSetAttribute(gemm_dual, cudaFuncAttributeMaxDynamicSharedMemorySize,
                         GEMM_SMEM);
    cudaFuncSetAttribute(attn_tc, cudaFuncAttributeMaxDynamicSharedMemorySize,
                         ATTN_TC_SMEM);

    // operand prep
    split_f32<<<(int)((M_ * (size_t)C_ / 4 + 255) / 256), 256>>>(x, xh, xl, (size_t)M_ * C_ / 4);
    tsplit<<<dim3(NH_ / 32, C_ / 32), dim3(32, 8)>>>(Wq, wch, wcl, C_, NH_);
    tsplit<<<dim3(KH_ / 32, C_ / 32), dim3(32, 8)>>>(
        Wk, wch + (size_t)NH_ * C_, wcl + (size_t)NH_ * C_, C_, KH_);
    tsplit<<<dim3(KH_ / 32, C_ / 32), dim3(32, 8)>>>(
        Wv, wch + (size_t)(NH_ + KH_) * C_, wcl + (size_t)(NH_ + KH_) * C_, C_, KH_);
    tsplit<<<dim3(C_ / 32, NH_ / 32), dim3(32, 8)>>>(Wout, woh, wol, NH_, C_);

    // fused QKV projection (tcgen05)
    gemm_dual<<<dim3(QKV_ / GBN, M_ / GBM), 256, GEMM_SMEM>>>(
        xh, xl, wch, wcl, qkv, M_, QKV_, C_);

    // norm + rope -> split bf16 ; V transpose+split
    rms_rope_split<<<M_, 256>>>(qkv, 0,    qsh, qsl, NH_, NHEADS, 0.08838834764831845f);
    rms_rope_split<<<M_, 256>>>(qkv, 2048, ksh, ksl, KH_, 4, 1.0f);
    vtsplit<<<dim3(T_ / 32, 4, 16), dim3(32, 8)>>>(qkv, vth, vtl);

    // attention (tcgen05, TMEM-resident)
    dim3 gAttn(T_ / 128, NHEADS, B_);
    attn_tc<<<gAttn, 256, ATTN_TC_SMEM>>>(qsh, qsl, ksh, ksl, vth, vtl, eh, el);

    // output projection (tcgen05)
    gemm_dual<<<dim3(C_ / GBN, M_ / GBM), 256, GEMM_SMEM>>>(
        eh, el, woh, wol, out, M_, C_, NH_);
}

// round 9
// speedup vs baseline: 10.3095x; 1.0233x over previous
#include <cuda_runtime.h>
#include <cuda_bf16.h>
#include <cstdint>
#include <math.h>

#define B_ 4
#define T_ 2048
#define C_ 2048
#define NH_ 2048
#define KH_ 512
#define QKV_ 3072      // NH_ + KH_ + KH_
#define NHEADS 16
#define H_ 128
#define M_ (B_*T_)

typedef __nv_bfloat16 bf16;

#if defined(__CUDA_ARCH_FEAT_SM103_ALL) || defined(__CUDA_ARCH_FEAT_SM100_ALL)
#define HAS_TCGEN05 1
#else
#define HAS_TCGEN05 0
#endif

// ---------------------------------------------------------------------------
// Device-global scratch
// ---------------------------------------------------------------------------
__device__ float g_qkv[(size_t)M_ * QKV_];

__device__ bf16 g_x_hi[(size_t)M_ * C_],  g_x_lo[(size_t)M_ * C_];
__device__ bf16 g_e_hi[(size_t)M_ * NH_], g_e_lo[(size_t)M_ * NH_];
__device__ bf16 g_qh[(size_t)M_ * NH_],   g_ql[(size_t)M_ * NH_];
__device__ bf16 g_kh[(size_t)M_ * KH_],   g_kl[(size_t)M_ * KH_];
__device__ bf16 g_vth[(size_t)16 * 128 * T_], g_vtl[(size_t)16 * 128 * T_];
__device__ bf16 g_Wc_hi[(size_t)QKV_ * C_], g_Wc_lo[(size_t)QKV_ * C_];
__device__ bf16 g_Wo_hi[(size_t)C_ * NH_],  g_Wo_lo[(size_t)C_ * NH_];

// ---------------------------------------------------------------------------
// PTX helpers
// ---------------------------------------------------------------------------
__device__ __forceinline__ void cp16(void* dst, const void* src) {
    uint32_t d = (uint32_t)__cvta_generic_to_shared(dst);
    asm volatile("cp.async.cg.shared.global [%0], [%1], 16;\n" :: "r"(d), "l"(src));
}
__device__ __forceinline__ void mma16816(float* d, const uint32_t* a, const uint32_t* b) {
    asm volatile(
        "mma.sync.aligned.m16n8k16.row.col.f32.bf16.bf16.f32 "
        "{%0,%1,%2,%3},{%4,%5,%6,%7},{%8,%9},{%0,%1,%2,%3};\n"
        : "+f"(d[0]), "+f"(d[1]), "+f"(d[2]), "+f"(d[3])
        : "r"(a[0]), "r"(a[1]), "r"(a[2]), "r"(a[3]), "r"(b[0]), "r"(b[1]));
}

#if HAS_TCGEN05
#define MBAR_INIT(addr, cnt) \
    asm volatile("mbarrier.init.shared.b64 [%0], %1;" :: "r"(addr), "r"(cnt) : "memory")
#define MBAR_WAIT(addr, parity) do {                                        \
    asm volatile(                                                            \
        "{\n\t.reg .pred P1;\n\t"                                            \
        "WAIT_LOOP_%=:\n\t"                                                  \
        "mbarrier.try_wait.parity.acquire.cta.shared::cta.b64 P1, [%0], %1, 0x989680;\n\t" \
        "@P1 bra.uni WAIT_DONE_%=;\n\t"                                      \
        "bra.uni WAIT_LOOP_%=;\n\t"                                          \
        "WAIT_DONE_%=:\n\t}"                                                 \
        :: "r"(addr), "r"(parity) : "memory");                               \
} while (0)
#define TC_ALLOC(smem_addr, n) \
    asm volatile("tcgen05.alloc.cta_group::1.sync.aligned.shared::cta.b32 [%0], %1;" \
                 :: "r"(smem_addr), "r"(n) : "memory")
#define TC_DEALLOC(tmem, n) \
    asm volatile("tcgen05.dealloc.cta_group::1.sync.aligned.b32 %0, %1;" :: "r"(tmem), "r"(n))
#define TC_RELINQ() \
    asm volatile("tcgen05.relinquish_alloc_permit.cta_group::1.sync.aligned;")
#define TC_COMMIT(mbar) \
    asm volatile("tcgen05.commit.cta_group::1.mbarrier::arrive::one.shared::cluster.b64 [%0];" \
                 :: "r"(mbar) : "memory")
#define TC_FENCE_AFTER()  asm volatile("tcgen05.fence::after_thread_sync;" ::: "memory")
#define TC_FENCE_BEFORE() asm volatile("tcgen05.fence::before_thread_sync;" ::: "memory")
#define TC_WAIT_LD() asm volatile("tcgen05.wait::ld.sync.aligned;" ::: "memory")
#define TC_WAIT_ST() asm volatile("tcgen05.wait::st.sync.aligned;" ::: "memory")

#define TC_LD_X32(r, addr) \
    asm volatile( \
        "tcgen05.ld.sync.aligned.32x32b.x32.b32 " \
        "{%0, %1, %2, %3, %4, %5, %6, %7, %8, %9, %10, %11, %12, %13, %14, %15, " \
        " %16, %17, %18, %19, %20, %21, %22, %23, %24, %25, %26, %27, %28, %29, %30, %31}, [%32];" \
        : "=r"((r)[0]),  "=r"((r)[1]),  "=r"((r)[2]),  "=r"((r)[3]), \
          "=r"((r)[4]),  "=r"((r)[5]),  "=r"((r)[6]),  "=r"((r)[7]), \
          "=r"((r)[8]),  "=r"((r)[9]),  "=r"((r)[10]), "=r"((r)[11]), \
          "=r"((r)[12]), "=r"((r)[13]), "=r"((r)[14]), "=r"((r)[15]), \
          "=r"((r)[16]), "=r"((r)[17]), "=r"((r)[18]), "=r"((r)[19]), \
          "=r"((r)[20]), "=r"((r)[21]), "=r"((r)[22]), "=r"((r)[23]), \
          "=r"((r)[24]), "=r"((r)[25]), "=r"((r)[26]), "=r"((r)[27]), \
          "=r"((r)[28]), "=r"((r)[29]), "=r"((r)[30]), "=r"((r)[31]) \
        : "r"(addr))

#define TC_ST_X32(addr, r) \
    asm volatile( \
        "tcgen05.st.sync.aligned.32x32b.x32.b32 [%0], " \
        "{%1, %2, %3, %4, %5, %6, %7, %8, %9, %10, %11, %12, %13, %14, %15, %16, " \
        " %17, %18, %19, %20, %21, %22, %23, %24, %25, %26, %27, %28, %29, %30, %31, %32};" \
        :: "r"(addr), \
           "r"((r)[0]),  "r"((r)[1]),  "r"((r)[2]),  "r"((r)[3]), \
           "r"((r)[4]),  "r"((r)[5]),  "r"((r)[6]),  "r"((r)[7]), \
           "r"((r)[8]),  "r"((r)[9]),  "r"((r)[10]), "r"((r)[11]), \
           "r"((r)[12]), "r"((r)[13]), "r"((r)[14]), "r"((r)[15]), \
           "r"((r)[16]), "r"((r)[17]), "r"((r)[18]), "r"((r)[19]), \
           "r"((r)[20]), "r"((r)[21]), "r"((r)[22]), "r"((r)[23]), \
           "r"((r)[24]), "r"((r)[25]), "r"((r)[26]), "r"((r)[27]), \
           "r"((r)[28]), "r"((r)[29]), "r"((r)[30]), "r"((r)[31]) \
        : "memory")

#define TC_ST_X16(addr, r) \
    asm volatile( \
        "tcgen05.st.sync.aligned.32x32b.x16.b32 [%0], " \
        "{%1, %2, %3, %4, %5, %6, %7, %8, %9, %10, %11, %12, %13, %14, %15, %16};" \
        :: "r"(addr), \
           "r"((r)[0]),  "r"((r)[1]),  "r"((r)[2]),  "r"((r)[3]), \
           "r"((r)[4]),  "r"((r)[5]),  "r"((r)[6]),  "r"((r)[7]), \
           "r"((r)[8]),  "r"((r)[9]),  "r"((r)[10]), "r"((r)[11]), \
           "r"((r)[12]), "r"((r)[13]), "r"((r)[14]), "r"((r)[15]) \
        : "memory")

__device__ __forceinline__ void tc_mma_ss_f16(
    uint32_t d_tmem, uint64_t a_desc, uint64_t b_desc, uint32_t idesc, uint32_t en)
{
    asm volatile(
        "{\n\t.reg .pred p;\n\t"
        "setp.ne.u32 p, %4, 0;\n\t"
        "tcgen05.mma.cta_group::1.kind::f16 [%0], %1, %2, %3, {%5, %5, %5, %5}, p;\n\t"
        "}"
        :: "r"(d_tmem), "l"(a_desc), "l"(b_desc), "r"(idesc), "r"(en), "r"(0u)
        : "memory");
}
__device__ __forceinline__ void tc_mma_ts_f16(
    uint32_t d_tmem, uint32_t a_tmem, uint64_t b_desc, uint32_t idesc, uint32_t en)
{
    asm volatile(
        "{\n\t.reg .pred p;\n\t"
        "setp.ne.u32 p, %4, 0;\n\t"
        "tcgen05.mma.cta_group::1.kind::f16 [%0], [%1], %2, %3, {%5, %5, %5, %5}, p;\n\t"
        "}"
        :: "r"(d_tmem), "r"(a_tmem), "l"(b_desc), "r"(idesc), "r"(en), "r"(0u)
        : "memory");
}
__device__ __forceinline__ uint64_t make_desc_sw128(uint32_t smem_addr) {
    return ((uint64_t)2 << 61) | ((uint64_t)1 << 46) | ((uint64_t)64 << 32)
         | ((uint64_t)1 << 16) | ((uint64_t)(smem_addr >> 4) & 0x3FFF);
}
#endif

// ---------------------------------------------------------------------------
// Dual-path GEMM: C[M,N](f32) = A[M,K] * Bt[N,K]^T, split bf16.
// tcgen05 path: 128x256x64 tile, TMEM 256 cols, 2-stage cp.async.
// ---------------------------------------------------------------------------
#define GBM 128
#define GBN 256
#define TBK 64
#define ST_A 16384                  // 128x64 bf16
#define ST_B 32768                  // 256x64 bf16
#define TSTAGE (2 * ST_A + 2 * ST_B)  // 98304
#define FBK 32
#define FLDA 40
#define FSSZ (128 * FLDA)
#define GEMM_SMEM (1024 + 2 * TSTAGE)   // 197632
#define GEMM_IDESC 0x8400490u       // f32 acc, bf16 a/b, M=128, N=256

__global__ __launch_bounds__(256) void gemm_dual(
    const bf16* __restrict__ Ah, const bf16* __restrict__ Al,
    const bf16* __restrict__ Bh, const bf16* __restrict__ Bl,
    float* __restrict__ Cc, int M, int N, int K)
{
#if HAS_TCGEN05
    extern __shared__ __align__(1024) char smem[];
    uint32_t sbase = (uint32_t)__cvta_generic_to_shared(smem);
    int tid = threadIdx.x, warp = tid >> 5, lane = tid & 31;
    int bx = blockIdx.x, by = blockIdx.y;
    const int ktiles = K / TBK;

    if (tid == 0) {
        MBAR_INIT(sbase + 16, 1);
        MBAR_INIT(sbase + 24, 1);
    }
    if (warp == 0) TC_ALLOC(sbase, 256);
    __syncthreads();
    uint32_t tmem;
    asm volatile("ld.shared.b32 %0, [%1];" : "=r"(tmem) : "r"(sbase));

    char* stage0 = smem + 1024;

    auto issue = [&](int kt) {
        if (kt < ktiles) {
            char* st = stage0 + (kt & 1) * TSTAGE;
            size_t k0 = (size_t)kt * TBK;
            // A hi/lo: 128 rows
            #pragma unroll
            for (int a = 0; a < 2; a++) {
                const bf16* g = (a ? Al : Ah) + (size_t)(by * GBM) * K + k0;
                char* base = st + a * ST_A;
                #pragma unroll
                for (int it = 0; it < 4; it++) {
                    int idx = tid + it * 256;
                    int row = idx >> 3, ch = idx & 7;
                    uint32_t off = (uint32_t)((row >> 3) * 1024 + (row & 7) * 128 + ch * 16);
                    off ^= ((off >> 3) & 0x70);
                    cp16(base + off, g + (size_t)row * K + ch * 8);
                }
            }
            // B hi/lo: 256 rows
            #pragma unroll
            for (int a = 0; a < 2; a++) {
                const bf16* g = (a ? Bl : Bh) + (size_t)(bx * GBN) * K + k0;
                char* base = st + 2 * ST_A + a * ST_B;
                #pragma unroll
                for (int it = 0; it < 8; it++) {
                    int idx = tid + it * 256;
                    int row = idx >> 3, ch = idx & 7;
                    uint32_t off = (uint32_t)((row >> 3) * 1024 + (row & 7) * 128 + ch * 16);
                    off ^= ((off >> 3) & 0x70);
                    cp16(base + off, g + (size_t)row * K + ch * 8);
                }
            }
        }
        asm volatile("cp.async.commit_group;\n" ::);
    };

    issue(0);

    for (int kt = 0; kt < ktiles; kt++) {
        if (kt >= 1) {
            uint32_t mb = sbase + 16 + ((kt - 1) & 1) * 8;
            MBAR_WAIT(mb, ((kt - 1) >> 1) & 1);
        }
        issue(kt + 1);
        asm volatile("cp.async.wait_group 1;\n" ::);
        __syncthreads();

        if (tid == 0) {
            asm volatile("fence.proxy.async.shared::cta;" ::: "memory");
            char* st = stage0 + (kt & 1) * TSTAGE;
            uint32_t a0 = (uint32_t)__cvta_generic_to_shared(st);
            uint64_t dAh = make_desc_sw128(a0);
            uint64_t dAl = make_desc_sw128(a0 + ST_A);
            uint64_t dBh = make_desc_sw128(a0 + 2 * ST_A);
            uint64_t dBl = make_desc_sw128(a0 + 2 * ST_A + ST_B);
            #pragma unroll
            for (int ks = 0; ks < 4; ks++) {
                tc_mma_ss_f16(tmem, dAh + ks * 2, dBh + ks * 2, GEMM_IDESC,
                              (kt > 0 || ks > 0) ? 1u : 0u);
                tc_mma_ss_f16(tmem, dAh + ks * 2, dBl + ks * 2, GEMM_IDESC, 1u);
                tc_mma_ss_f16(tmem, dAl + ks * 2, dBh + ks * 2, GEMM_IDESC, 1u);
            }
            TC_COMMIT(sbase + 16 + (kt & 1) * 8);
        }
    }

    {
        uint32_t mb = sbase + 16 + ((ktiles - 1) & 1) * 8;
        MBAR_WAIT(mb, ((ktiles - 1) >> 1) & 1);
    }
    TC_FENCE_AFTER();

    // epilogue: warp -> rows (warp&3)*32+lane, cols (warp>>2)*128 .. +127
    int sp = warp & 3, chf = warp >> 2;
    #pragma unroll
    for (int cc = 0; cc < 4; cc++) {
        uint32_t dr[32];
        TC_LD_X32(dr, tmem + chf * 128 + cc * 32);
        TC_WAIT_LD();
        int row = by * GBM + sp * 32 + lane;
        int col = bx * GBN + chf * 128 + cc * 32;
        float* o = Cc + (size_t)row * N + col;
        #pragma unroll
        for (int q = 0; q < 8; q++)
            *(float4*)(o + q * 4) = make_float4(
                __uint_as_float(dr[4 * q]),     __uint_as_float(dr[4 * q + 1]),
                __uint_as_float(dr[4 * q + 2]), __uint_as_float(dr[4 * q + 3]));
    }
    __syncthreads();
    if (warp == 0) {
        TC_RELINQ();
        TC_DEALLOC(tmem, 256);
    }
#else
    // mma.sync fallback (PTX-only pass; runtime uses sm_103a cubin).
    // Processes the 256-wide tile as two 128-wide halves.
    extern __shared__ bf16 sm[];
    int tid = threadIdx.x;
    int by = blockIdx.y;
    int warp = tid >> 5, lane = tid & 31;
    int wm = (warp >> 2) * 64, wn = (warp & 3) * 32;
    int r = lane >> 2, c = lane & 3;

    for (int half = 0; half < 2; half++) {
        int bxe = blockIdx.x * 2 + half;
        const bf16* gAh = Ah + (size_t)(by * GBM) * K;
        const bf16* gAl = Al + (size_t)(by * GBM) * K;
        const bf16* gBh = Bh + (size_t)(bxe * 128) * K;
        const bf16* gBl = Bl + (size_t)(bxe * 128) * K;

        float acc[4][4][4];
        #pragma unroll
        for (int i = 0; i < 4; i++)
            #pragma unroll
            for (int j = 0; j < 4; j++)
                #pragma unroll
                for (int e = 0; e < 4; e++) acc[i][j][e] = 0.f;

        const int k_tiles = K / FBK;

        auto issue = [&](int stage, int kt) {
            if (kt < k_tiles) {
                size_t k0 = (size_t)kt * FBK;
                bf16* base = sm + stage * 4 * FSSZ;
                #pragma unroll
                for (int p = 0; p < 2; p++) {
                    int ci = tid + p * 256;
                    int row = ci >> 2, c16 = ci & 3;
                    int so = row * FLDA + c16 * 8;
                    size_t go = (size_t)row * K + k0 + c16 * 8;
                    cp16(base + so,            gAh + go);
                    cp16(base + FSSZ + so,     gAl + go);
                    cp16(base + 2 * FSSZ + so, gBh + go);
                    cp16(base + 3 * FSSZ + so, gBl + go);
                }
            }
            asm volatile("cp.async.commit_group;\n" ::);
        };

        #pragma unroll
        for (int s = 0; s < 2; s++) issue(s, s);

        for (int kt = 0; kt < k_tiles; kt++) {
            asm volatile("cp.async.wait_group 1;\n" ::);
            __syncthreads();
            issue((kt + 2) % 3, kt + 2);

            const uint32_t* wAh = (const uint32_t*)(sm + (kt % 3) * 4 * FSSZ);
            const uint32_t* wAl = wAh + FSSZ / 2;
            const uint32_t* wBh = wAh + FSSZ;
            const uint32_t* wBl = wAh + 3 * (FSSZ / 2);

            #pragma unroll
            for (int ks = 0; ks < 2; ks++) {
                int kw = ks * 8;
                uint32_t a_h[4][4], a_l[4][4], b_h[4][2], b_l[4][2];
                #pragma unroll
                for (int i = 0; i < 4; i++) {
                    int r0 = (wm + i * 16 + r) * 20 + kw + c;
                    int r1 = r0 + 8 * 20;
                    a_h[i][0] = wAh[r0];     a_h[i][1] = wAh[r1];
                    a_h[i][2] = wAh[r0 + 4]; a_h[i][3] = wAh[r1 + 4];
                    a_l[i][0] = wAl[r0];     a_l[i][1] = wAl[r1];
                    a_l[i][2] = wAl[r0 + 4]; a_l[i][3] = wAl[r1 + 4];
                }
                #pragma unroll
                for (int j = 0; j < 4; j++) {
                    int n0 = (wn + j * 8 + r) * 20 + kw + c;
                    b_h[j][0] = wBh[n0]; b_h[j][1] = wBh[n0 + 4];
                    b_l[j][0] = wBl[n0]; b_l[j][1] = wBl[n0 + 4];
                }
                #pragma unroll
                for (int i = 0; i < 4; i++)
                    #pragma unroll
                    for (int j = 0; j < 4; j++) {
                        mma16816(acc[i][j], a_h[i], b_h[j]);
                        mma16816(acc[i][j], a_h[i], b_l[j]);
                        mma16816(acc[i][j], a_l[i], b_h[j]);
                    }
            }
            __syncthreads();
        }

        #pragma unroll
        for (int i = 0; i < 4; i++)
            #pragma unroll
            for (int j = 0; j < 4; j++) {
                int row = by * GBM + wm + i * 16 + r;
                int col = bxe * 128 + wn + j * 8 + 2 * c;
                *(float2*)(Cc + (size_t)row * N + col) =
                    make_float2(acc[i][j][0], acc[i][j][1]);
                *(float2*)(Cc + (size_t)(row + 8) * N + col) =
                    make_float2(acc[i][j][2], acc[i][j][3]);
            }
        __syncthreads();
    }
#endif
}

// ---------------------------------------------------------------------------
// tcgen05 flash attention, fixed-max softmax, O resident in TMEM.
// Pipelined: S(t+1) issued before softmax(t); PV on separate mbar; 3-stage KV.
// TMEM: O@0(128), Qh@128(64), Ql@192(64), S0@256, S1@320, Ph@384(32), Pl@416(32)
// smem: [0:8) tmem ptr, [8:24) mbarS0/S1, [24:32) mbarP; 3 KV stages @1024.
// ---------------------------------------------------------------------------
#define AK_B 16384
#define ASTAGE (4 * AK_B)                 // 65536
#define ATTN_TC_SMEM (1024 + 3 * ASTAGE)  // 197632
#define IDESC_S  0x8100490u    // M=128, N=64
#define IDESC_PV 0x8200490u    // M=128, N=128

__global__ __launch_bounds__(256) void attn_tc(
    const bf16* __restrict__ qh, const bf16* __restrict__ ql,
    const bf16* __restrict__ kh_, const bf16* __restrict__ kl_,
    const bf16* __restrict__ vth, const bf16* __restrict__ vtl,
    bf16* __restrict__ eh, bf16* __restrict__ el)
{
#if HAS_TCGEN05
    extern __shared__ __align__(1024) char smem[];
    __shared__ float sL[2][128];
    uint32_t sbase = (uint32_t)__cvta_generic_to_shared(smem);
    int tid = threadIdx.x, warp = tid >> 5, lane = tid & 31;
    int b = blockIdx.z, n = blockIdx.y, khd = n >> 2;
    int q0 = blockIdx.x * 128, bT = b * T_;
    const int NT = T_ / 64;   // 32

    if (tid == 0) {
        MBAR_INIT(sbase + 8, 1);    // mbarS0 (even S tiles)
        MBAR_INIT(sbase + 16, 1);   // mbarS1 (odd S tiles)
        MBAR_INIT(sbase + 24, 1);   // mbarP
    }
    if (warp == 0) TC_ALLOC(sbase, 512);
    __syncthreads();
    uint32_t tmem;
    asm volatile("ld.shared.b32 %0, [%1];" : "=r"(tmem) : "r"(sbase));

    auto issue_kv = [&](int tile) {
        if (tile < NT) {
            int s0 = tile * 64;
            char* st = smem + 1024 + (tile % 3) * ASTAGE;
            #pragma unroll
            for (int a = 0; a < 2; a++) {
                const bf16* g = (a ? kl_ : kh_);
                char* base = st + a * AK_B;
                #pragma unroll
                for (int it = 0; it < 4; it++) {
                    int idx = tid + it * 256;
                    int s = idx >> 4, ch = idx & 15;
                    uint32_t off = (uint32_t)((s >> 3) * 1024 + (ch >> 3) * 8192
                                            + (s & 7) * 128 + (ch & 7) * 16);
                    off ^= ((off >> 3) & 0x70);
                    cp16(base + off, g + (size_t)(bT + s0 + s) * KH_ + khd * 128 + ch * 8);
                }
            }
            #pragma unroll
            for (int a = 0; a < 2; a++) {
                const bf16* g = (a ? vtl : vth);
                char* base = st + 2 * AK_B + a * AK_B;
                #pragma unroll
                for (int it = 0; it < 4; it++) {
                    int idx = tid + it * 256;
                    int h = idx >> 3, tch = idx & 7;
                    uint32_t off = (uint32_t)((h >> 3) * 1024 + (h & 7) * 128 + tch * 16);
                    off ^= ((off >> 3) & 0x70);
                    cp16(base + off,
                         g + ((size_t)(b * 4 + khd) * 128 + h) * T_ + s0 + tch * 8);
                }
            }
        }
        asm volatile("cp.async.commit_group;\n" ::);
    };

    // helper: issue S(tile) MMAs (K stage tile%3 -> S buffer tile&1)
    auto issue_S = [&](int tile) {
        uint32_t kb = sbase + 1024 + (uint32_t)(tile % 3) * ASTAGE;
        uint64_t dKh = make_desc_sw128(kb);
        uint64_t dKl = make_desc_sw128(kb + AK_B);
        uint32_t sdst = tmem + 256 + (uint32_t)(tile & 1) * 64;
        #pragma unroll
        for (int ks = 0; ks < 8; ks++) {
            uint64_t koff = (ks < 4) ? (uint64_t)(ks * 2)
                                     : (uint64_t)(512 + (ks - 4) * 2);
            uint32_t aH = tmem + 128 + ks * 8, aL = tmem + 192 + ks * 8;
            tc_mma_ts_f16(sdst, aH, dKh + koff, IDESC_S, ks > 0 ? 1u : 0u);
            tc_mma_ts_f16(sdst, aH, dKl + koff, IDESC_S, 1u);
            tc_mma_ts_f16(sdst, aL, dKh + koff, IDESC_S, 1u);
        }
        TC_COMMIT(sbase + 8 + (uint32_t)(tile & 1) * 8);
    };

    issue_kv(0);
    issue_kv(1);

    // Q -> TMEM (warps 0-3, row = tid)
    if (tid < 128) {
        uint32_t woff = (uint32_t)(tid >> 5) << 21;
        uint32_t qr[32];
        const uint4* srcA = (const uint4*)(qh + (size_t)(bT + q0 + tid) * NH_ + n * 128);
        const uint4* srcB = (const uint4*)(ql + (size_t)(bT + q0 + tid) * NH_ + n * 128);
        #pragma unroll
        for (int i = 0; i < 8; i++) {
            uint4 v = srcA[i];
            qr[4*i] = v.x; qr[4*i+1] = v.y; qr[4*i+2] = v.z; qr[4*i+3] = v.w;
        }
        TC_ST_X32(tmem + 128 + woff, qr);
        #pragma unroll
        for (int i = 0; i < 8; i++) {
            uint4 v = srcA[i + 8];
            qr[4*i] = v.x; qr[4*i+1] = v.y; qr[4*i+2] = v.z; qr[4*i+3] = v.w;
        }
        TC_ST_X32(tmem + 160 + woff, qr);
        #pragma unroll
        for (int i = 0; i < 8; i++) {
            uint4 v = srcB[i];
            qr[4*i] = v.x; qr[4*i+1] = v.y; qr[4*i+2] = v.z; qr[4*i+3] = v.w;
        }
        TC_ST_X32(tmem + 192 + woff, qr);
        #pragma unroll
        for (int i = 0; i < 8; i++) {
            uint4 v = srcB[i + 8];
            qr[4*i] = v.x; qr[4*i+1] = v.y; qr[4*i+2] = v.z; qr[4*i+3] = v.w;
        }
        TC_ST_X32(tmem + 224 + woff, qr);
        TC_WAIT_ST();
    }
    TC_FENCE_BEFORE();
    asm volatile("cp.async.wait_group 1;\n" ::);   // kv(0) done
    __syncthreads();

    if (tid == 0) {
        TC_FENCE_AFTER();
        asm volatile("fence.proxy.async.shared::cta;" ::: "memory");
        issue_S(0);
    }

    int chalf = warp >> 2;            // 0: s-cols 0-31, 1: s-cols 32-63
    int row = (warp & 3) * 32 + lane;
    uint32_t woff = (uint32_t)(warp & 3) << 21;
    float li = 0.f;

    for (int t = 0; t < NT; t++) {
        // 1. wait S(t)
        MBAR_WAIT(sbase + 8 + (uint32_t)(t & 1) * 8, (uint32_t)((t >> 1) & 1));
        TC_FENCE_AFTER();

        // 2. kv(t+1) landed; issue S(t+1) (overlaps softmax below)
        asm volatile("cp.async.wait_group 0;\n" ::);
        __syncthreads();
        if (tid == 0 && t + 1 < NT) {
            asm volatile("fence.proxy.async.shared::cta;" ::: "memory");
            issue_S(t + 1);
        }

        // 3. softmax on S(t)
        uint32_t sr[32];
        TC_LD_X32(sr, tmem + 256 + (uint32_t)(t & 1) * 64 + chalf * 32);
        TC_WAIT_LD();
        float pv[32];
        float lsum = 0.f;
        #pragma unroll
        for (int i = 0; i < 32; i++) {
            pv[i] = __expf(__uint_as_float(sr[i]));
            lsum += pv[i];
        }
        li += lsum;
        uint32_t ph[16], pl[16];
        #pragma unroll
        for (int j = 0; j < 16; j++) {
            float p0 = pv[2*j], p1 = pv[2*j+1];
            bf16 h0 = __float2bfloat16(p0), h1 = __float2bfloat16(p1);
            __nv_bfloat162 hp = {h0, h1};
            __nv_bfloat162 lp = {__float2bfloat16(p0 - __bfloat162float(h0)),
                                 __float2bfloat16(p1 - __bfloat162float(h1))};
            ph[j] = *(uint32_t*)&hp;
            pl[j] = *(uint32_t*)&lp;
        }

        // 4. wait PV(t-1) (frees P and V stage (t-1)%3)
        if (t >= 1) MBAR_WAIT(sbase + 24, (uint32_t)((t - 1) & 1));
        TC_FENCE_AFTER();

        // 5. prefetch kv(t+2) into stage (t+2)%3 == (t-1)%3
        issue_kv(t + 2);

        // 6. store P
        TC_ST_X16(tmem + 384 + chalf * 16 + woff, ph);
        TC_ST_X16(tmem + 416 + chalf * 16 + woff, pl);
        TC_WAIT_ST();
        TC_FENCE_BEFORE();
        __syncthreads();

        // 7. issue PV(t)
        if (tid == 0) {
            TC_FENCE_AFTER();
            asm volatile("fence.proxy.async.shared::cta;" ::: "memory");
            uint32_t vb = sbase + 1024 + (uint32_t)(t % 3) * ASTAGE + 2 * AK_B;
            uint64_t dVh = make_desc_sw128(vb);
            uint64_t dVl = make_desc_sw128(vb + AK_B);
            #pragma unroll
            for (int ks = 0; ks < 4; ks++) {
                uint32_t aH = tmem + 384 + ks * 8, aL = tmem + 416 + ks * 8;
                tc_mma_ts_f16(tmem, aH, dVh + ks * 2, IDESC_PV,
                              (t > 0 || ks > 0) ? 1u : 0u);
                tc_mma_ts_f16(tmem, aH, dVl + ks * 2, IDESC_PV, 1u);
                tc_mma_ts_f16(tmem, aL, dVh + ks * 2, IDESC_PV, 1u);
            }
            TC_COMMIT(sbase + 24);
        }
    }

    // combine li halves
    sL[chalf][row] = li;
    __syncthreads();
    float inv = 1.f / (sL[0][row] + sL[1][row]);

    // wait PV(NT-1)
    MBAR_WAIT(sbase + 24, (uint32_t)((NT - 1) & 1));
    TC_FENCE_AFTER();

    uint32_t o0[32], o1[32];
    TC_LD_X32(o0, tmem + chalf * 64);
    TC_LD_X32(o1, tmem + chalf * 64 + 32);
    TC_WAIT_LD();

    size_t obase = (size_t)(bT + q0 + row) * NH_ + n * 128 + chalf * 64;
    #pragma unroll
    for (int j = 0; j < 16; j++) {
        float v0 = __uint_as_float(j < 8 ? o0[4*(j&7)]   : o1[4*(j&7)])   * inv;
        float v1 = __uint_as_float(j < 8 ? o0[4*(j&7)+1] : o1[4*(j&7)+1]) * inv;
        float v2 = __uint_as_float(j < 8 ? o0[4*(j&7)+2] : o1[4*(j&7)+2]) * inv;
        float v3 = __uint_as_float(j < 8 ? o0[4*(j&7)+3] : o1[4*(j&7)+3]) * inv;
        bf16 h0 = __float2bfloat16(v0), h1 = __float2bfloat16(v1);
        bf16 h2 = __float2bfloat16(v2), h3 = __float2bfloat16(v3);
        __nv_bfloat162 hp0 = {h0, h1}, hp1 = {h2, h3};
        __nv_bfloat162 lp0 = {__float2bfloat16(v0 - __bfloat162float(h0)),
                              __float2bfloat16(v1 - __bfloat162float(h1))};
        __nv_bfloat162 lp1 = {__float2bfloat16(v2 - __bfloat162float(h2)),
                              __float2bfloat16(v3 - __bfloat162float(h3))};
        int colo = (j & 7) * 4 + (j < 8 ? 0 : 32);
        *(uint2*)(eh + obase + colo) = make_uint2(*(uint32_t*)&hp0, *(uint32_t*)&hp1);
        *(uint2*)(el + obase + colo) = make_uint2(*(uint32_t*)&lp0, *(uint32_t*)&lp1);
    }

    __syncthreads();
    if (warp == 0) {
        TC_RELINQ();
        TC_DEALLOC(tmem, 512);
    }
#endif
}

// ---------------------------------------------------------------------------
// Prep kernels (unchanged)
// ---------------------------------------------------------------------------
__global__ __launch_bounds__(256) void split_f32(
    const float* __restrict__ src, bf16* __restrict__ hi, bf16* __restrict__ lo,
    size_t n4)
{
    size_t i = (size_t)blockIdx.x * blockDim.x + threadIdx.x;
    if (i >= n4) return;
    float4 v = *(const float4*)(src + i * 4);
    bf16 h0 = __float2bfloat16(v.x), h1 = __float2bfloat16(v.y);
    bf16 h2 = __float2bfloat16(v.z), h3 = __float2bfloat16(v.w);
    bf16 l0 = __float2bfloat16(v.x - __bfloat162float(h0));
    bf16 l1 = __float2bfloat16(v.y - __bfloat162float(h1));
    bf16 l2 = __float2bfloat16(v.z - __bfloat162float(h2));
    bf16 l3 = __float2bfloat16(v.w - __bfloat162float(h3));
    __nv_bfloat162 hp0 = {h0, h1}, hp1 = {h2, h3};
    __nv_bfloat162 lp0 = {l0, l1}, lp1 = {l2, l3};
    *(uint2*)(hi + i * 4) = make_uint2(*(unsigned int*)&hp0, *(unsigned int*)&hp1);
    *(uint2*)(lo + i * 4) = make_uint2(*(unsigned int*)&lp0, *(unsigned int*)&lp1);
}

__global__ __launch_bounds__(256) void tsplit(
    const float* __restrict__ W, bf16* __restrict__ hi, bf16* __restrict__ lo,
    int K, int N)
{
    __shared__ float t[32][33];
    int kb = blockIdx.y * 32, nb = blockIdx.x * 32;
    #pragma unroll
    for (int i = 0; i < 4; i++)
        t[threadIdx.y + 8 * i][threadIdx.x] =
            W[(size_t)(kb + threadIdx.y + 8 * i) * N + nb + threadIdx.x];
    __syncthreads();
    #pragma unroll
    for (int i = 0; i < 4; i++) {
        float f = t[threadIdx.x][threadIdx.y + 8 * i];
        bf16 h = __float2bfloat16(f);
        size_t idx = (size_t)(nb + threadIdx.y + 8 * i) * K + kb + threadIdx.x;
        hi[idx] = h;
        lo[idx] = __float2bfloat16(f - __bfloat162float(h));
    }
}

__global__ __launch_bounds__(256) void vtsplit(
    const float* __restrict__ qkv, bf16* __restrict__ hi, bf16* __restrict__ lo)
{
    __shared__ float t[32][33];
    int t0 = blockIdx.x * 32, h0 = blockIdx.y * 32;
    int bz = blockIdx.z;
    int b = bz >> 2, kh = bz & 3;
    #pragma unroll
    for (int i = 0; i < 4; i++)
        t[threadIdx.y + 8 * i][threadIdx.x] =
            qkv[(size_t)(b * T_ + t0 + threadIdx.y + 8 * i) * QKV_ + 2560 + kh * 128 + h0 + threadIdx.x];
    __syncthreads();
    #pragma unroll
    for (int i = 0; i < 4; i++) {
        float f = t[threadIdx.x][threadIdx.y + 8 * i];
        bf16 h = __float2bfloat16(f);
        size_t idx = ((size_t)bz * 128 + h0 + threadIdx.y + 8 * i) * T_ + t0 + threadIdx.x;
        hi[idx] = h;
        lo[idx] = __float2bfloat16(f - __bfloat162float(h));
    }
}

__global__ __launch_bounds__(256) void rms_rope_split(
    const float* __restrict__ in, int inoff,
    bf16* __restrict__ outh, bf16* __restrict__ outl,
    int width, int nheads, float outscale)
{
    int row = blockIdx.x;
    int t = row % T_;
    const float* ptr = in + (size_t)row * QKV_ + inoff;

    float ss = 0.f;
    for (int i = threadIdx.x; i < width; i += 256) {
        float v = ptr[i];
        ss += v * v;
    }
    #pragma unroll
    for (int o = 16; o; o >>= 1) ss += __shfl_xor_sync(0xffffffffu, ss, o);
    __shared__ float red[8];
    if ((threadIdx.x & 31) == 0) red[threadIdx.x >> 5] = ss;
    __syncthreads();
    float tot = red[0] + red[1] + red[2] + red[3] + red[4] + red[5] + red[6] + red[7];
    float rs = rsqrtf(tot / (float)width + 1e-6f) * outscale;

    int npairs = nheads * 64;
    const double TWO_PI = 6.283185307179586476925286766559;
    bf16* oh = outh + (size_t)row * width;
    bf16* ol = outl + (size_t)row * width;
    for (int p = threadIdx.x; p < npairs; p += 256) {
        int head = p >> 6;
        int hp = p & 63;
        float inv = __expf(-(float)hp * (9.210340371976184f / 64.f));
        float theta = (float)t * inv;
        double td = (double)theta * (1.0 / TWO_PI);
        double frac = td - floor(td);
        if (frac > 0.5) frac -= 1.0;
        float redang = (float)(frac * TWO_PI);
        float s, cc;
        sincosf(redang, &s, &cc);

        int base = head * H_;
        float x1 = ptr[base + hp] * rs;
        float x2 = ptr[base + hp + 64] * rs;
        float y1 = x1 * cc - x2 * s;
        float y2 = x2 * cc + x1 * s;
        bf16 h1 = __float2bfloat16(y1), h2 = __float2bfloat16(y2);
        oh[base + hp]      = h1;
        oh[base + hp + 64] = h2;
        ol[base + hp]      = __float2bfloat16(y1 - __bfloat162float(h1));
        ol[base + hp + 64] = __float2bfloat16(y2 - __bfloat162float(h2));
    }
}

// ---------------------------------------------------------------------------
extern "C" void kernel_launch(void* const* d_in, const int* in_sizes, int n_in,
                              void* d_out, int out_size)
{
    const float* x    = (const float*)d_in[0];
    const float* Wq   = (const float*)d_in[1];
    const float* Wk   = (const float*)d_in[2];
    const float* Wv   = (const float*)d_in[3];
    const float* Wout = (const float*)d_in[4];
    float* out = (float*)d_out;

    float* qkv;
    cudaGetSymbolAddress((void**)&qkv, g_qkv);
    bf16 *xh, *xl, *eh, *el, *qsh, *qsl, *ksh, *ksl, *vth, *vtl;
    bf16 *wch, *wcl, *woh, *wol;
    cudaGetSymbolAddress((void**)&xh, g_x_hi);   cudaGetSymbolAddress((void**)&xl, g_x_lo);
    cudaGetSymbolAddress((void**)&eh, g_e_hi);   cudaGetSymbolAddress((void**)&el, g_e_lo);
    cudaGetSymbolAddress((void**)&qsh, g_qh);    cudaGetSymbolAddress((void**)&qsl, g_ql);
    cudaGetSymbolAddress((void**)&ksh, g_kh);    cudaGetSymbolAddress((void**)&ksl, g_kl);
    cudaGetSymbolAddress((void**)&vth, g_vth);   cudaGetSymbolAddress((void**)&vtl, g_vtl);
    cudaGetSymbolAddress((void**)&wch, g_Wc_hi); cudaGetSymbolAddress((void**)&wcl, g_Wc_lo);
    cudaGetSymbolAddress((void**)&woh, g_Wo_hi); cudaGetSymbolAddress((void**)&wol, g_Wo_lo);

    cudaFuncSetAttribute(gemm_dual, cudaFuncAttributeMaxDynamicSharedMemorySize,
                         GEMM_SMEM);
    cudaFuncSetAttribute(attn_tc, cudaFuncAttributeMaxDynamicSharedMemorySize,
                         ATTN_TC_SMEM);

    // operand prep
    split_f32<<<(int)((M_ * (size_t)C_ / 4 + 255) / 256), 256>>>(x, xh, xl, (size_t)M_ * C_ / 4);
    tsplit<<<dim3(NH_ / 32, C_ / 32), dim3(32, 8)>>>(Wq, wch, wcl, C_, NH_);
    tsplit<<<dim3(KH_ / 32, C_ / 32), dim3(32, 8)>>>(
        Wk, wch + (size_t)NH_ * C_, wcl + (size_t)NH_ * C_, C_, KH_);
    tsplit<<<dim3(KH_ / 32, C_ / 32), dim3(32, 8)>>>(
        Wv, wch + (size_t)(NH_ + KH_) * C_, wcl + (size_t)(NH_ + KH_) * C_, C_, KH_);
    tsplit<<<dim3(C_ / 32, NH_ / 32), dim3(32, 8)>>>(Wout, woh, wol, NH_, C_);

    // fused QKV projection (tcgen05, 128x256 tiles)
    gemm_dual<<<dim3(QKV_ / GBN, M_ / GBM), 256, GEMM_SMEM>>>(
        xh, xl, wch, wcl, qkv, M_, QKV_, C_);

    // norm + rope -> split bf16 ; V transpose+split
    rms_rope_split<<<M_, 256>>>(qkv, 0,    qsh, qsl, NH_, NHEADS, 0.08838834764831845f);
    rms_rope_split<<<M_, 256>>>(qkv, 2048, ksh, ksl, KH_, 4, 1.0f);
    vtsplit<<<dim3(T_ / 32, 4, 16), dim3(32, 8)>>>(qkv, vth, vtl);

    // attention (tcgen05, pipelined)
    dim3 gAttn(T_ / 128, NHEADS, B_);
    attn_tc<<<gAttn, 256, ATTN_TC_SMEM>>>(qsh, qsl, ksh, ksl, vth, vtl, eh, el);

    // output projection (tcgen05, 128x256 tiles)
    gemm_dual<<<dim3(C_ / GBN, M_ / GBM), 256, GEMM_SMEM>>>(
        eh, el, woh, wol, out, M_, C_, NH_);
}